// round 6
// baseline (speedup 1.0000x reference)
#include <cuda_runtime.h>
#include <cuda_bf16.h>

#define NN 50000
#define NE 600000
#define HID 128
#define NT 256

typedef unsigned long long u64;
typedef unsigned int u32;
typedef unsigned short u16;

// ---------------- scratch ----------------
__device__ float g_h[NN * HID];
__device__ float g_agg[NN * HID];
__device__ float g_sumexp[3 * NN];
__device__ float g_scores[NE];
__device__ float g_es[NE];
__device__ int   g_src[NE];
__device__ int   g_dst[NE];
__device__ unsigned g_maxenc[3];
__device__ int   g_is64;
// counting sort by dst
__device__ int g_cnt[NN];
__device__ int g_cur[NN];
__device__ int g_eord[NE];
// bf16 hi/lo splits
__device__ __align__(16) u16 g_hh[NN * HID];
__device__ __align__(16) u16 g_hl[NN * HID];
__device__ __align__(16) u16 g_eah[NE * 16];
__device__ __align__(16) u16 g_eal[NE * 16];
__device__ __align__(16) u16 g_W1h[3 * 128 * 144];
__device__ __align__(16) u16 g_W1l[3 * 128 * 144];
__device__ __align__(16) u16 g_W2h[3 * 128 * 128];
__device__ __align__(16) u16 g_W2l[3 * 128 * 128];
__device__ __align__(16) u16 g_A1h[3 * 64 * 272];
__device__ __align__(16) u16 g_A1l[3 * 64 * 272];

__device__ __forceinline__ unsigned fenc(float f) {
    unsigned u = __float_as_uint(f);
    return (u & 0x80000000u) ? ~u : (u | 0x80000000u);
}
__device__ __forceinline__ float fdec(unsigned u) {
    return (u & 0x80000000u) ? __uint_as_float(u & 0x7fffffffu)
                             : __uint_as_float(~u);
}

// ---------------- packed f32x2 (k_update) ----------------
__device__ __forceinline__ u64 pack2(float lo, float hi) {
    u64 r;
    asm("mov.b64 %0, {%1, %2};" : "=l"(r)
        : "r"(__float_as_uint(lo)), "r"(__float_as_uint(hi)));
    return r;
}
__device__ __forceinline__ u64 pack2s(float v) { return pack2(v, v); }
__device__ __forceinline__ void ffma2(u64 &d, u64 a, u64 b) {
    asm("fma.rn.f32x2 %0, %1, %2, %0;" : "+l"(d) : "l"(a), "l"(b));
}
__device__ __forceinline__ void unpack2(u64 v, float &lo, float &hi) {
    unsigned a, b;
    asm("mov.b64 {%0, %1}, %2;" : "=r"(a), "=r"(b) : "l"(v));
    lo = __uint_as_float(a);
    hi = __uint_as_float(b);
}

// ---------------- bf16 split helpers ----------------
__device__ __forceinline__ void split_bf16(float v, u16 &h, u16 &l) {
    __nv_bfloat16 bh = __float2bfloat16(v);
    __nv_bfloat16 bl = __float2bfloat16(v - __bfloat162float(bh));
    h = __bfloat16_as_ushort(bh);
    l = __bfloat16_as_ushort(bl);
}
__device__ __forceinline__ void split2(float a, float b, u32 &h, u32 &l) {
    u16 h0, l0, h1, l1;
    split_bf16(a, h0, l0);
    split_bf16(b, h1, l1);
    h = (u32)h0 | ((u32)h1 << 16);
    l = (u32)l0 | ((u32)l1 << 16);
}

// ---------------- HMMA helpers ----------------
__device__ __forceinline__ u32 smem_u32(const void* p) {
    u32 a;
    asm("{ .reg .u64 t; cvta.to.shared.u64 t, %1; cvt.u32.u64 %0, t; }"
        : "=r"(a) : "l"(p));
    return a;
}
__device__ __forceinline__ void ldsm4(u32* r, u32 addr) {
    asm volatile("ldmatrix.sync.aligned.m8n8.x4.shared.b16 {%0,%1,%2,%3}, [%4];"
        : "=r"(r[0]), "=r"(r[1]), "=r"(r[2]), "=r"(r[3]) : "r"(addr));
}
__device__ __forceinline__ void ldsm2(u32* r, u32 addr) {
    asm volatile("ldmatrix.sync.aligned.m8n8.x2.shared.b16 {%0,%1}, [%2];"
        : "=r"(r[0]), "=r"(r[1]) : "r"(addr));
}
__device__ __forceinline__ void mma16816(float* d, const u32* a, const u32* b) {
    asm volatile("mma.sync.aligned.m16n8k16.row.col.f32.bf16.bf16.f32 "
        "{%0,%1,%2,%3}, {%4,%5,%6,%7}, {%8,%9}, {%0,%1,%2,%3};"
        : "+f"(d[0]), "+f"(d[1]), "+f"(d[2]), "+f"(d[3])
        : "r"(a[0]), "r"(a[1]), "r"(a[2]), "r"(a[3]), "r"(b[0]), "r"(b[1]));
}

// ---------------- weight preconversion ----------------
__global__ void k_prep(const float* __restrict__ mw1, const float* __restrict__ mw2,
                       const float* __restrict__ aw1) {
    int idx = blockIdx.x * blockDim.x + threadIdx.x;
    const int N1 = 3 * 128 * 144, N2 = 3 * 128 * 128, N3 = 3 * 64 * 272;
    u16 h, l;
    if (idx < N1) {
        split_bf16(mw1[idx], h, l);
        g_W1h[idx] = h; g_W1l[idx] = l;
    } else if (idx < N1 + N2) {
        int i = idx - N1;
        split_bf16(mw2[i], h, l);
        g_W2h[i] = h; g_W2l[i] = l;
    } else if (idx < N1 + N2 + N3) {
        int i = idx - N1 - N2;
        split_bf16(aw1[i], h, l);
        g_A1h[i] = h; g_A1l[i] = l;
    }
}

// ---------------- detect + convert + ea split + zero ----------------
__global__ void k_detect(const unsigned* __restrict__ raw) {
    __shared__ int nz;
    if (threadIdx.x == 0) nz = 0;
    __syncthreads();
    for (int i = threadIdx.x; i < 2048; i += NT)
        if (raw[2 * i + 1] != 0u) atomicOr(&nz, 1);
    __syncthreads();
    if (threadIdx.x == 0) g_is64 = (nz == 0) ? 1 : 0;
}

__global__ void k_convert(const void* __restrict__ eidx, const float* __restrict__ ea) {
    int i = blockIdx.x * blockDim.x + threadIdx.x;
    long long stride = (long long)gridDim.x * blockDim.x;
    if (i < NE) {
        if (g_is64) {
            const long long* p = (const long long*)eidx;
            g_src[i] = (int)p[i];
            g_dst[i] = (int)p[NE + i];
        } else {
            const int* p = (const int*)eidx;
            g_src[i] = p[i];
            g_dst[i] = p[NE + i];
        }
    }
    for (long long j = i; j < (long long)NE * 16; j += stride) {
        u16 h, l;
        split_bf16(ea[j], h, l);
        g_eah[j] = h; g_eal[j] = l;
    }
    for (long long j = i; j < (long long)NN * HID; j += stride) g_agg[j] = 0.f;
    for (long long j = i; j < 3 * NN; j += stride) g_sumexp[j] = 0.f;
    for (long long j = i; j < NN; j += stride) g_cnt[j] = 0;
    if (i == 0) {
        g_maxenc[0] = 0x007FFFFFu;
        g_maxenc[1] = 0x007FFFFFu;
        g_maxenc[2] = 0x007FFFFFu;
    }
}

// ---------------- counting sort by dst ----------------
__global__ void k_hist() {
    int i = blockIdx.x * blockDim.x + threadIdx.x;
    if (i < NE) atomicAdd(&g_cnt[g_dst[i]], 1);
}

__global__ void k_scan() {
    __shared__ int warpsum[32];
    __shared__ int scarry;
    int tid = threadIdx.x, lane = tid & 31, wid = tid >> 5;
    if (tid == 0) scarry = 0;
    __syncthreads();
    for (int base = 0; base < NN; base += 1024) {
        int i = base + tid;
        int v = (i < NN) ? g_cnt[i] : 0;
        int s = v;
#pragma unroll
        for (int off = 1; off < 32; off <<= 1) {
            int t = __shfl_up_sync(0xffffffffu, s, off);
            if (lane >= off) s += t;
        }
        if (lane == 31) warpsum[wid] = s;
        __syncthreads();
        if (wid == 0) {
            int ws = warpsum[lane];
#pragma unroll
            for (int off = 1; off < 32; off <<= 1) {
                int t = __shfl_up_sync(0xffffffffu, ws, off);
                if (lane >= off) ws += t;
            }
            warpsum[lane] = ws;
        }
        __syncthreads();
        int incl = s + (wid > 0 ? warpsum[wid - 1] : 0) + scarry;
        if (i < NN) g_cur[i] = incl - v;
        __syncthreads();
        if (tid == 1023) scarry = incl;
        __syncthreads();
    }
}

__global__ void k_scatter() {
    int i = blockIdx.x * blockDim.x + threadIdx.x;
    if (i < NE) {
        int pos = atomicAdd(&g_cur[g_dst[i]], 1);
        g_eord[pos] = i;
    }
}

// ---------------- node projection (+ split store) ----------------
__global__ void k_nodeproj(const float* __restrict__ x,
                           const float* __restrict__ W,
                           const float* __restrict__ b) {
    __shared__ float sA[32 * 33];
    __shared__ float sW[128 * 33];
    int tid = threadIdx.x;
    int n0 = blockIdx.x * 32;
    for (int idx = tid; idx < 32 * 32; idx += NT) {
        int r = idx >> 5, k = idx & 31;
        int n = n0 + r;
        sA[r * 33 + k] = (n < NN) ? x[n * 32 + k] : 0.f;
    }
    for (int idx = tid; idx < 128 * 32; idx += NT) {
        int o = idx >> 5, k = idx & 31;
        sW[o * 33 + k] = W[o * 32 + k];
    }
    __syncthreads();
    int tc = tid & 31, trg = tid >> 5;
    float acc[4][4] = {};
#pragma unroll 8
    for (int k = 0; k < 32; k++) {
        float a[4], w[4];
#pragma unroll
        for (int i = 0; i < 4; i++) a[i] = sA[(trg * 4 + i) * 33 + k];
#pragma unroll
        for (int j = 0; j < 4; j++) w[j] = sW[(tc + 32 * j) * 33 + k];
#pragma unroll
        for (int i = 0; i < 4; i++)
#pragma unroll
            for (int j = 0; j < 4; j++) acc[i][j] += a[i] * w[j];
    }
#pragma unroll
    for (int i = 0; i < 4; i++) {
        int n = n0 + trg * 4 + i;
        if (n < NN)
#pragma unroll
            for (int j = 0; j < 4; j++) {
                int c = tc + 32 * j;
                float v = fmaxf(acc[i][j] + b[c], 0.f);
                g_h[n * HID + c] = v;
                u16 h, l;
                split_bf16(v, h, l);
                g_hh[n * HID + c] = h;
                g_hl[n * HID + c] = l;
            }
    }
}

// ---------------- attention scores (HMMA bf16 split) ----------------
#define APA 280
#define ATT_AH 0
#define ATT_AL 71680
#define ATT_WH 143360
#define ATT_WL 179200
#define ATT_META 215040
#define SMEM_ATT (215040 + 2368)

__global__ void __launch_bounds__(512, 1)
k_attn(const float* __restrict__ ab1,
       const float* __restrict__ aw2,
       const float* __restrict__ ab2p, int layer) {
    extern __shared__ char sm[];
    u16* sAh = (u16*)(sm + ATT_AH);
    u16* sAl = (u16*)(sm + ATT_AL);
    u16* sWh = (u16*)(sm + ATT_WH);
    u16* sWl = (u16*)(sm + ATT_WL);
    int*   ssrc  = (int*)(sm + ATT_META);
    int*   sdst  = (int*)(sm + ATT_META + 512);
    float* sscore = (float*)(sm + ATT_META + 1024);
    float* sb1   = (float*)(sm + ATT_META + 1536);
    float* sv    = (float*)(sm + ATT_META + 1792);
    unsigned* smax = (unsigned*)(sm + ATT_META + 2048);
    u32 sb = smem_u32(sm);

    int tid = threadIdx.x, lane = tid & 31, w = tid >> 5;
    int e0 = blockIdx.x * 128;
    if (tid < 128) {
        int e = e0 + tid;
        if (e < NE) { ssrc[tid] = g_src[e]; sdst[tid] = g_dst[e]; }
        else        { ssrc[tid] = 0;        sdst[tid] = 0; }
        sscore[tid] = ab2p[0];
    }
    if (tid < 64) { sb1[tid] = ab1[tid]; sv[tid] = aw2[tid]; }
    if (tid == 0) *smax = 0x007FFFFFu;
    __syncthreads();

    for (int idx = tid; idx < 128 * 34; idx += 512) {
        int r = idx / 34, c4 = idx - r * 34;
        int c = c4 * 8;
        const uint4 *ph, *pl;
        if (c < 128) {
            int s = ssrc[r] * HID + c;
            ph = (const uint4*)&g_hh[s]; pl = (const uint4*)&g_hl[s];
        } else if (c < 256) {
            int s = sdst[r] * HID + (c - 128);
            ph = (const uint4*)&g_hh[s]; pl = (const uint4*)&g_hl[s];
        } else {
            int e = min(e0 + r, NE - 1);
            int s = e * 16 + (c - 256);
            ph = (const uint4*)&g_eah[s]; pl = (const uint4*)&g_eal[s];
        }
        *(uint4*)&sAh[r * APA + c] = *ph;
        *(uint4*)&sAl[r * APA + c] = *pl;
    }
    {
        const u16* wh = g_A1h + layer * 64 * 272;
        const u16* wl = g_A1l + layer * 64 * 272;
        for (int idx = tid; idx < 64 * 34; idx += 512) {
            int r = idx / 34, c4 = idx - r * 34;
            int c = c4 * 8;
            *(uint4*)&sWh[r * APA + c] = *(const uint4*)&wh[r * 272 + c];
            *(uint4*)&sWl[r * APA + c] = *(const uint4*)&wl[r * 272 + c];
        }
    }
    __syncthreads();

    int m0 = (w & 7) * 16, n0 = (w >> 3) * 32;
    float acc[4][4];
#pragma unroll
    for (int i = 0; i < 4; i++)
#pragma unroll
        for (int j = 0; j < 4; j++) acc[i][j] = 0.f;

    for (int ks = 0; ks < 17; ks++) {
        int kb = ks * 16;
        u32 ah[4], al[4];
        {
            int r = m0 + (lane & 15);
            int c = kb + ((lane >> 4) << 3);
            u32 off = (u32)(r * APA + c) * 2;
            ldsm4(ah, sb + ATT_AH + off);
            ldsm4(al, sb + ATT_AL + off);
        }
#pragma unroll
        for (int nt = 0; nt < 4; nt++) {
            int rn = n0 + nt * 8 + (lane & 7);
            int cn = kb + (((lane >> 3) & 1) << 3);
            u32 offb = (u32)(rn * APA + cn) * 2;
            u32 bh[2], bl[2];
            ldsm2(bh, sb + ATT_WH + offb);
            ldsm2(bl, sb + ATT_WL + offb);
            mma16816(acc[nt], ah, bh);
            mma16816(acc[nt], ah, bl);
            mma16816(acc[nt], al, bh);
        }
    }

    float p0 = 0.f, p1 = 0.f;
#pragma unroll
    for (int nt = 0; nt < 4; nt++) {
        int c = n0 + nt * 8 + 2 * (lane & 3);
        float b0 = sb1[c], b1 = sb1[c + 1];
        float v0 = sv[c], v1 = sv[c + 1];
        float x;
        x = acc[nt][0] + b0; x = (x > 0.f) ? x : 0.2f * x; p0 += x * v0;
        x = acc[nt][1] + b1; x = (x > 0.f) ? x : 0.2f * x; p0 += x * v1;
        x = acc[nt][2] + b0; x = (x > 0.f) ? x : 0.2f * x; p1 += x * v0;
        x = acc[nt][3] + b1; x = (x > 0.f) ? x : 0.2f * x; p1 += x * v1;
    }
    p0 += __shfl_xor_sync(0xffffffffu, p0, 1);
    p0 += __shfl_xor_sync(0xffffffffu, p0, 2);
    p1 += __shfl_xor_sync(0xffffffffu, p1, 1);
    p1 += __shfl_xor_sync(0xffffffffu, p1, 2);
    if ((lane & 3) == 0) {
        atomicAdd(&sscore[m0 + (lane >> 2)], p0);
        atomicAdd(&sscore[m0 + 8 + (lane >> 2)], p1);
    }
    __syncthreads();
    if (tid < 128) {
        int e = e0 + tid;
        float s = sscore[tid];
        float m = (e < NE) ? s : -3.4e38f;
        if (e < NE) g_scores[e] = s;
#pragma unroll
        for (int off = 16; off > 0; off >>= 1)
            m = fmaxf(m, __shfl_xor_sync(0xffffffffu, m, off));
        if (lane == 0) atomicMax(smax, fenc(m));
    }
    __syncthreads();
    if (tid == 0) atomicMax(&g_maxenc[layer], *smax);
}

// ---------------- exp + scatter sum ----------------
__global__ void k_exp(int layer) {
    int i = blockIdx.x * blockDim.x + threadIdx.x;
    if (i >= NE) return;
    float m = fdec(g_maxenc[layer]);
    float es = expf(g_scores[i] - m);
    g_es[i] = es;
    atomicAdd(&g_sumexp[layer * NN + g_dst[i]], es);
}

// ---------------- message MLP (HMMA, dst-sorted, segmented reduce) ----------------
#define APM 152
#define MSG_AH 0
#define MSG_AL 38912
#define MSG_WH 77824
#define MSG_WL 116736
#define MSG_META 155648
#define SMEM_MSG (155648 + 3072)

__global__ void __launch_bounds__(512, 1)
k_msg(const float* __restrict__ mb1,
      const float* __restrict__ mb2, int layer) {
    extern __shared__ char sm[];
    u16* sAh = (u16*)(sm + MSG_AH);
    u16* sAl = (u16*)(sm + MSG_AL);
    u16* sWh = (u16*)(sm + MSG_WH);
    u16* sWl = (u16*)(sm + MSG_WL);
    int*   ssrc = (int*)(sm + MSG_META);
    int*   sdst = (int*)(sm + MSG_META + 512);
    float* swt  = (float*)(sm + MSG_META + 1024);
    float* smb1 = (float*)(sm + MSG_META + 1536);
    float* smb2 = (float*)(sm + MSG_META + 2048);
    int*   seid = (int*)(sm + MSG_META + 2560);
    u32 sb = smem_u32(sm);

    int tid = threadIdx.x, lane = tid & 31, w = tid >> 5;
    int e0 = blockIdx.x * 128;
    if (tid < 128) {
        int s = e0 + tid;
        if (s < NE) {
            int e = g_eord[s];
            seid[tid] = e;
            ssrc[tid] = g_src[e];
            int d = g_dst[e];
            sdst[tid] = d;
            swt[tid] = g_es[e] / (g_sumexp[layer * NN + d] + 1e-6f);
        } else {
            seid[tid] = 0; ssrc[tid] = 0; sdst[tid] = 0; swt[tid] = 0.f;
        }
        smb1[tid] = mb1[tid];
        smb2[tid] = mb2[tid];
    }
    __syncthreads();

    // gather A [128 x 144]
    for (int idx = tid; idx < 128 * 18; idx += 512) {
        int r = idx / 18, c4 = idx - r * 18;
        int c = c4 * 8;
        const uint4 *ph, *pl;
        if (c < 128) {
            int s = ssrc[r] * HID + c;
            ph = (const uint4*)&g_hh[s]; pl = (const uint4*)&g_hl[s];
        } else {
            int s = seid[r] * 16 + (c - 128);
            ph = (const uint4*)&g_eah[s]; pl = (const uint4*)&g_eal[s];
        }
        *(uint4*)&sAh[r * APM + c] = *ph;
        *(uint4*)&sAl[r * APM + c] = *pl;
    }
    // W1 [128 x 144]
    {
        const u16* wh = g_W1h + layer * 128 * 144;
        const u16* wl = g_W1l + layer * 128 * 144;
        for (int idx = tid; idx < 128 * 18; idx += 512) {
            int r = idx / 18, c4 = idx - r * 18;
            int c = c4 * 8;
            *(uint4*)&sWh[r * APM + c] = *(const uint4*)&wh[r * 144 + c];
            *(uint4*)&sWl[r * APM + c] = *(const uint4*)&wl[r * 144 + c];
        }
    }
    __syncthreads();

    int m0 = (w & 3) * 32, n0 = (w >> 2) * 32;
    float acc[2][4][4];
#pragma unroll
    for (int i = 0; i < 2; i++)
#pragma unroll
        for (int j = 0; j < 4; j++)
#pragma unroll
            for (int k = 0; k < 4; k++) acc[i][j][k] = 0.f;

    for (int ks = 0; ks < 9; ks++) {
        int kb = ks * 16;
        u32 ah[2][4], al[2][4];
#pragma unroll
        for (int mt = 0; mt < 2; mt++) {
            int r = m0 + mt * 16 + (lane & 15);
            int c = kb + ((lane >> 4) << 3);
            u32 off = (u32)(r * APM + c) * 2;
            ldsm4(ah[mt], sb + MSG_AH + off);
            ldsm4(al[mt], sb + MSG_AL + off);
        }
#pragma unroll
        for (int nt = 0; nt < 4; nt++) {
            int rn = n0 + nt * 8 + (lane & 7);
            int cn = kb + (((lane >> 3) & 1) << 3);
            u32 offb = (u32)(rn * APM + cn) * 2;
            u32 bh[2], bl[2];
            ldsm2(bh, sb + MSG_WH + offb);
            ldsm2(bl, sb + MSG_WL + offb);
#pragma unroll
            for (int mt = 0; mt < 2; mt++) {
                mma16816(acc[mt][nt], ah[mt], bh);
                mma16816(acc[mt][nt], ah[mt], bl);
                mma16816(acc[mt][nt], al[mt], bh);
            }
        }
    }
    __syncthreads();

    // epilogue1: relu(D+b1) -> re-split into A tiles
#pragma unroll
    for (int mt = 0; mt < 2; mt++)
#pragma unroll
        for (int nt = 0; nt < 4; nt++) {
            int rA = m0 + mt * 16 + (lane >> 2);
            int rB = rA + 8;
            int c = n0 + nt * 8 + 2 * (lane & 3);
            float b0 = smb1[c], b1 = smb1[c + 1];
            u32 h, l;
            split2(fmaxf(acc[mt][nt][0] + b0, 0.f),
                   fmaxf(acc[mt][nt][1] + b1, 0.f), h, l);
            *(u32*)&sAh[rA * APM + c] = h;
            *(u32*)&sAl[rA * APM + c] = l;
            split2(fmaxf(acc[mt][nt][2] + b0, 0.f),
                   fmaxf(acc[mt][nt][3] + b1, 0.f), h, l);
            *(u32*)&sAh[rB * APM + c] = h;
            *(u32*)&sAl[rB * APM + c] = l;
        }
    // W2 [128 x 128]
    {
        const u16* wh = g_W2h + layer * 128 * 128;
        const u16* wl = g_W2l + layer * 128 * 128;
        for (int idx = tid; idx < 128 * 16; idx += 512) {
            int r = idx >> 4, c4 = idx & 15;
            int c = c4 * 8;
            *(uint4*)&sWh[r * APM + c] = *(const uint4*)&wh[r * 128 + c];
            *(uint4*)&sWl[r * APM + c] = *(const uint4*)&wl[r * 128 + c];
        }
    }
    __syncthreads();

    // GEMM2 K=128
    float acc2[2][4][4];
#pragma unroll
    for (int i = 0; i < 2; i++)
#pragma unroll
        for (int j = 0; j < 4; j++)
#pragma unroll
            for (int k = 0; k < 4; k++) acc2[i][j][k] = 0.f;

    for (int ks = 0; ks < 8; ks++) {
        int kb = ks * 16;
        u32 ah[2][4], al[2][4];
#pragma unroll
        for (int mt = 0; mt < 2; mt++) {
            int r = m0 + mt * 16 + (lane & 15);
            int c = kb + ((lane >> 4) << 3);
            u32 off = (u32)(r * APM + c) * 2;
            ldsm4(ah[mt], sb + MSG_AH + off);
            ldsm4(al[mt], sb + MSG_AL + off);
        }
#pragma unroll
        for (int nt = 0; nt < 4; nt++) {
            int rn = n0 + nt * 8 + (lane & 7);
            int cn = kb + (((lane >> 3) & 1) << 3);
            u32 offb = (u32)(rn * APM + cn) * 2;
            u32 bh[2], bl[2];
            ldsm2(bh, sb + MSG_WH + offb);
            ldsm2(bl, sb + MSG_WL + offb);
#pragma unroll
            for (int mt = 0; mt < 2; mt++) {
                mma16816(acc2[mt][nt], ah[mt], bh);
                mma16816(acc2[mt][nt], ah[mt], bl);
                mma16816(acc2[mt][nt], al[mt], bh);
            }
        }
    }
    __syncthreads();  // all W reads done; stage reuses W area

    // epilogue2: stage weighted messages, then segmented reduce + atomics
    float* stage = (float*)(sm + MSG_WH);  // 128 x 132 floats
#pragma unroll
    for (int mt = 0; mt < 2; mt++)
#pragma unroll
        for (int nt = 0; nt < 4; nt++) {
            int rA = m0 + mt * 16 + (lane >> 2);
            int rB = rA + 8;
            int c = n0 + nt * 8 + 2 * (lane & 3);
            float b0 = smb2[c], b1 = smb2[c + 1];
            float wA = swt[rA], wB = swt[rB];
            stage[rA * 132 + c]     = (acc2[mt][nt][0] + b0) * wA;
            stage[rA * 132 + c + 1] = (acc2[mt][nt][1] + b1) * wA;
            stage[rB * 132 + c]     = (acc2[mt][nt][2] + b0) * wB;
            stage[rB * 132 + c + 1] = (acc2[mt][nt][3] + b1) * wB;
        }
    __syncthreads();
    {
        int col = tid & 127, grp = tid >> 7;
        int r0s = grp * 32;
        float a = 0.f;
        int prev = sdst[r0s];
        for (int r = r0s; r < r0s + 32; r++) {
            int d = sdst[r];
            if (d != prev) {
                atomicAdd(&g_agg[(u64)prev * HID + col], a);
                a = 0.f; prev = d;
            }
            a += stage[r * 132 + col];
        }
        atomicAdd(&g_agg[(u64)prev * HID + col], a);
    }
}

// ---------------- node update + residual + layernorm (FFMA2, + split store) ----------------
__global__ void __launch_bounds__(256, 2)
k_update(const float* __restrict__ uw1,
         const float* __restrict__ ub1,
         const float* __restrict__ uw2,
         const float* __restrict__ ub2,
         const float* __restrict__ lng,
         const float* __restrict__ lnb) {
    extern __shared__ float smu[];
    float* sAT = smu;
    float* sW  = sAT + 16 * 132;
    float* sM  = sW + 16 * 128;

    int tid = threadIdx.x;
    int n0 = blockIdx.x * 128;
    int tcol = tid & 15, trow = tid >> 4;
    int r0 = trow * 8, c0 = tcol * 8;
    int lrow = tid & 127;
    int lkq0 = (tid >> 7) * 2;

    u64 acc[8][4];
#pragma unroll
    for (int i = 0; i < 8; i++)
#pragma unroll
        for (int j = 0; j < 4; j++) acc[i][j] = 0ull;

    for (int kb = 0; kb < 256; kb += 16) {
#pragma unroll
        for (int q = 0; q < 2; q++) {
            int kq = lkq0 + q;
            int kg = kb + kq * 4;
            int n = n0 + lrow;
            float4 v = make_float4(0.f, 0.f, 0.f, 0.f);
            if (n < NN) {
                if (kg < 128) v = *(const float4*)&g_h[n * HID + kg];
                else {
                    v = *(const float4*)&g_agg[n * HID + (kg - 128)];
                    *(float4*)&g_agg[n * HID + (kg - 128)] =
                        make_float4(0.f, 0.f, 0.f, 0.f);
                }
            }
            sAT[(kq * 4 + 0) * 132 + lrow] = v.x;
            sAT[(kq * 4 + 1) * 132 + lrow] = v.y;
            sAT[(kq * 4 + 2) * 132 + lrow] = v.z;
            sAT[(kq * 4 + 3) * 132 + lrow] = v.w;
        }
#pragma unroll
        for (int q = 0; q < 2; q++) {
            int kq = lkq0 + q;
            float4 w = *(const float4*)&uw1[lrow * 256 + kb + kq * 4];
            sW[(kq * 4 + 0) * 128 + lrow] = w.x;
            sW[(kq * 4 + 1) * 128 + lrow] = w.y;
            sW[(kq * 4 + 2) * 128 + lrow] = w.z;
            sW[(kq * 4 + 3) * 128 + lrow] = w.w;
        }
        __syncthreads();
#pragma unroll
        for (int k = 0; k < 16; k++) {
            float4 a0 = *(const float4*)&sAT[k * 132 + r0];
            float4 a1 = *(const float4*)&sAT[k * 132 + r0 + 4];
            float4 w0 = *(const float4*)&sW[k * 128 + c0];
            float4 w1 = *(const float4*)&sW[k * 128 + c0 + 4];
            u64 ww0 = pack2(w0.x, w0.y), ww1 = pack2(w0.z, w0.w);
            u64 ww2 = pack2(w1.x, w1.y), ww3 = pack2(w1.z, w1.w);
            float av[8] = {a0.x, a0.y, a0.z, a0.w, a1.x, a1.y, a1.z, a1.w};
#pragma unroll
            for (int i = 0; i < 8; i++) {
                u64 ap = pack2s(av[i]);
                ffma2(acc[i][0], ap, ww0);
                ffma2(acc[i][1], ap, ww1);
                ffma2(acc[i][2], ap, ww2);
                ffma2(acc[i][3], ap, ww3);
            }
        }
        __syncthreads();
    }

    {
        float4 b0 = *(const float4*)&ub1[c0];
        float4 b1 = *(const float4*)&ub1[c0 + 4];
        float bb[8] = {b0.x, b0.y, b0.z, b0.w, b1.x, b1.y, b1.z, b1.w};
#pragma unroll
        for (int i = 0; i < 8; i++) {
            float* row = &sM[(r0 + i) * 132 + c0];
#pragma unroll
            for (int jp = 0; jp < 4; jp++) {
                float lo, hi;
                unpack2(acc[i][jp], lo, hi);
                row[2 * jp]     = fmaxf(lo + bb[2 * jp], 0.f);
                row[2 * jp + 1] = fmaxf(hi + bb[2 * jp + 1], 0.f);
            }
        }
    }
    __syncthreads();

    u64 acc2[8][4];
#pragma unroll
    for (int i = 0; i < 8; i++)
#pragma unroll
        for (int j = 0; j < 4; j++) acc2[i][j] = 0ull;

    for (int kb = 0; kb < 128; kb += 16) {
#pragma unroll
        for (int q = 0; q < 2; q++) {
            int kq = lkq0 + q;
            float4 w = *(const float4*)&uw2[lrow * 128 + kb + kq * 4];
            sW[(kq * 4 + 0) * 128 + lrow] = w.x;
            sW[(kq * 4 + 1) * 128 + lrow] = w.y;
            sW[(kq * 4 + 2) * 128 + lrow] = w.z;
            sW[(kq * 4 + 3) * 128 + lrow] = w.w;
        }
        __syncthreads();
#pragma unroll
        for (int k = 0; k < 16; k++) {
            int kg = kb + k;
            float4 w0 = *(const float4*)&sW[k * 128 + c0];
            float4 w1 = *(const float4*)&sW[k * 128 + c0 + 4];
            u64 ww0 = pack2(w0.x, w0.y), ww1 = pack2(w0.z, w0.w);
            u64 ww2 = pack2(w1.x, w1.y), ww3 = pack2(w1.z, w1.w);
#pragma unroll
            for (int i = 0; i < 8; i++) {
                u64 ap = pack2s(sM[(r0 + i) * 132 + kg]);
                ffma2(acc2[i][0], ap, ww0);
                ffma2(acc2[i][1], ap, ww1);
                ffma2(acc2[i][2], ap, ww2);
                ffma2(acc2[i][3], ap, ww3);
            }
        }
        __syncthreads();
    }

    {
        float4 b0 = *(const float4*)&ub2[c0];
        float4 b1 = *(const float4*)&ub2[c0 + 4];
        float bb[8] = {b0.x, b0.y, b0.z, b0.w, b1.x, b1.y, b1.z, b1.w};
        float4 g0 = *(const float4*)&lng[c0];
        float4 g1 = *(const float4*)&lng[c0 + 4];
        float gg[8] = {g0.x, g0.y, g0.z, g0.w, g1.x, g1.y, g1.z, g1.w};
        float4 q0 = *(const float4*)&lnb[c0];
        float4 q1 = *(const float4*)&lnb[c0 + 4];
        float qq[8] = {q0.x, q0.y, q0.z, q0.w, q1.x, q1.y, q1.z, q1.w};

#pragma unroll
        for (int i = 0; i < 8; i++) {
            int n = n0 + r0 + i;
            float v[8];
            if (n < NN) {
                float4 h0 = *(const float4*)&g_h[n * HID + c0];
                float4 h1 = *(const float4*)&g_h[n * HID + c0 + 4];
                float hh[8] = {h0.x, h0.y, h0.z, h0.w, h1.x, h1.y, h1.z, h1.w};
#pragma unroll
                for (int jp = 0; jp < 4; jp++) {
                    float lo, hi;
                    unpack2(acc2[i][jp], lo, hi);
                    v[2 * jp]     = fmaxf(lo + bb[2 * jp] + hh[2 * jp], 0.f);
                    v[2 * jp + 1] = fmaxf(hi + bb[2 * jp + 1] + hh[2 * jp + 1], 0.f);
                }
            } else {
#pragma unroll
                for (int j = 0; j < 8; j++) v[j] = 0.f;
            }
            float s = 0.f, sq = 0.f;
#pragma unroll
            for (int j = 0; j < 8; j++) { s += v[j]; sq += v[j] * v[j]; }
#pragma unroll
            for (int off = 8; off > 0; off >>= 1) {
                s  += __shfl_xor_sync(0xffffffffu, s, off);
                sq += __shfl_xor_sync(0xffffffffu, sq, off);
            }
            float mu = s * (1.f / 128.f);
            float var = sq * (1.f / 128.f) - mu * mu;
            float rs = rsqrtf(var + 1e-5f);
            if (n < NN) {
                float o[8];
#pragma unroll
                for (int j = 0; j < 8; j++)
                    o[j] = (v[j] - mu) * rs * gg[j] + qq[j];
                *(float4*)&g_h[n * HID + c0]     = make_float4(o[0], o[1], o[2], o[3]);
                *(float4*)&g_h[n * HID + c0 + 4] = make_float4(o[4], o[5], o[6], o[7]);
#pragma unroll
                for (int j = 0; j < 8; j += 2) {
                    u32 h, l;
                    split2(o[j], o[j + 1], h, l);
                    *(u32*)&g_hh[n * HID + c0 + j] = h;
                    *(u32*)&g_hl[n * HID + c0 + j] = l;
                }
            }
        }
    }
}

// ---------------- final readout ----------------
__global__ void k_final(const float* __restrict__ gc,
                        const float* __restrict__ qw1,
                        const float* __restrict__ qb1,
                        const float* __restrict__ qw2,
                        const float* __restrict__ qb2p,
                        float* __restrict__ out) {
    __shared__ float sA[32 * 33];
    __shared__ float sW[128 * 33];
    __shared__ float sctx[64];
    __shared__ float sout[32];
    int tid = threadIdx.x;
    int n0 = blockIdx.x * 32;
    if (tid < 64) sctx[tid] = gc[tid];
    if (tid < 32) sout[tid] = qb2p[0];
    __syncthreads();
    int tc = tid & 31, trg = tid >> 5;
    float acc[4][4] = {};
    for (int kb = 0; kb < 192; kb += 32) {
        for (int idx = tid; idx < 32 * 32; idx += NT) {
            int r = idx >> 5, kk = idx & 31;
            int n = n0 + r;
            int kg = kb + kk;
            float v = 0.f;
            if (n < NN) v = (kg < 128) ? g_h[n * HID + kg] : sctx[kg - 128];
            sA[r * 33 + kk] = v;
        }
        for (int idx = tid; idx < 128 * 32; idx += NT) {
            int o = idx >> 5, kk = idx & 31;
            sW[o * 33 + kk] = qw1[o * 192 + kb + kk];
        }
        __syncthreads();
#pragma unroll 8
        for (int k = 0; k < 32; k++) {
            float a[4], w[4];
#pragma unroll
            for (int i = 0; i < 4; i++) a[i] = sA[(trg * 4 + i) * 33 + k];
#pragma unroll
            for (int j = 0; j < 4; j++) w[j] = sW[(tc + 32 * j) * 33 + k];
#pragma unroll
            for (int i = 0; i < 4; i++)
#pragma unroll
                for (int j = 0; j < 4; j++) acc[i][j] += a[i] * w[j];
        }
        __syncthreads();
    }
    float p[4] = {0.f, 0.f, 0.f, 0.f};
#pragma unroll
    for (int j = 0; j < 4; j++) {
        int c = tc + 32 * j;
        float b = qb1[c], w2 = qw2[c];
#pragma unroll
        for (int i = 0; i < 4; i++) {
            float v = fmaxf(acc[i][j] + b, 0.f);
            p[i] += v * w2;
        }
    }
#pragma unroll
    for (int i = 0; i < 4; i++) atomicAdd(&sout[trg * 4 + i], p[i]);
    __syncthreads();
    if (tid < 32) {
        int n = n0 + tid;
        if (n < NN) out[n] = sout[tid];
    }
}

// ---------------- launch ----------------
extern "C" void kernel_launch(void* const* d_in, const int* in_sizes, int n_in,
                              void* d_out, int out_size) {
    const float* x    = (const float*)d_in[0];
    const void*  eidx = d_in[1];
    const float* ea   = (const float*)d_in[2];
    const float* gc   = (const float*)d_in[3];
    const float* npw  = (const float*)d_in[4];
    const float* npb  = (const float*)d_in[5];
    const float* mw1  = (const float*)d_in[6];
    const float* mb1  = (const float*)d_in[7];
    const float* mw2  = (const float*)d_in[8];
    const float* mb2  = (const float*)d_in[9];
    const float* aw1  = (const float*)d_in[10];
    const float* ab1  = (const float*)d_in[11];
    const float* aw2  = (const float*)d_in[12];
    const float* ab2  = (const float*)d_in[13];
    const float* uw1  = (const float*)d_in[14];
    const float* ub1  = (const float*)d_in[15];
    const float* uw2  = (const float*)d_in[16];
    const float* ub2  = (const float*)d_in[17];
    const float* lng  = (const float*)d_in[18];
    const float* lnb  = (const float*)d_in[19];
    const float* qw1  = (const float*)d_in[20];
    const float* qb1  = (const float*)d_in[21];
    const float* qw2  = (const float*)d_in[22];
    const float* qb2  = (const float*)d_in[23];
    float* out = (float*)d_out;

    const int smem_upd = (16 * 132 + 16 * 128 + 128 * 132) * 4;
    cudaFuncSetAttribute(k_msg, cudaFuncAttributeMaxDynamicSharedMemorySize, SMEM_MSG);
    cudaFuncSetAttribute(k_attn, cudaFuncAttributeMaxDynamicSharedMemorySize, SMEM_ATT);
    cudaFuncSetAttribute(k_update, cudaFuncAttributeMaxDynamicSharedMemorySize, smem_upd);

    k_prep<<<(3 * (128 * 144 + 128 * 128 + 64 * 272) + 255) / 256, 256>>>(mw1, mw2, aw1);
    k_detect<<<1, NT>>>((const unsigned*)eidx);
    k_convert<<<(NE + NT - 1) / NT, NT>>>(eidx, ea);
    k_hist<<<(NE + 255) / 256, 256>>>();
    k_scan<<<1, 1024>>>();
    k_scatter<<<(NE + 255) / 256, 256>>>();
    k_nodeproj<<<(NN + 31) / 32, NT>>>(x, npw, npb);

    int egrid = (NE + 127) / 128;
    for (int l = 0; l < 3; l++) {
        k_attn<<<egrid, 512, SMEM_ATT>>>(ab1 + l * 64, aw2 + l * 64, ab2 + l, l);
        k_exp<<<(NE + NT - 1) / NT, NT>>>(l);
        k_msg<<<egrid, 512, SMEM_MSG>>>(mb1 + l * 128, mb2 + l * 128, l);
        k_update<<<(NN + 127) / 128, NT, smem_upd>>>(uw1 + l * 128 * 256, ub1 + l * 128,
                                                     uw2 + l * 128 * 128, ub2 + l * 128,
                                                     lng + l * 128, lnb + l * 128);
    }
    k_final<<<(NN + 31) / 32, NT>>>(gc, qw1, qb1, qw2, qb2, out);
}

// round 7
// speedup vs baseline: 1.0895x; 1.0895x over previous
#include <cuda_runtime.h>
#include <cuda_bf16.h>

#define NN 50000
#define NE 600000
#define HID 128
#define NT 256

typedef unsigned long long u64;
typedef unsigned int u32;
typedef unsigned short u16;

// ---------------- scratch ----------------
__device__ float g_h[NN * HID];
__device__ float g_agg[NN * HID];
__device__ float g_pre[NN * 256];      // [0:64)=u_s, [64:128)=u_d, [128:256)=vh
__device__ float g_sumexp[3 * NN];
__device__ float g_scores[NE];
__device__ float g_es[NE];
__device__ int   g_src[NE];
__device__ int   g_dst[NE];
__device__ unsigned g_maxenc[3];
__device__ int   g_is64;
// bf16 hi/lo splits
__device__ __align__(16) u16 g_hh[NN * HID];
__device__ __align__(16) u16 g_hl[NN * HID];
__device__ __align__(16) u16 g_eah[NE * 16];
__device__ __align__(16) u16 g_eal[NE * 16];
__device__ __align__(16) u16 g_NPh[3 * 256 * 128];  // node-pre weights (concat)
__device__ __align__(16) u16 g_NPl[3 * 256 * 128];
__device__ __align__(16) u16 g_EWh[3 * 192 * 16];   // ea-part weights: 64 att + 128 msg
__device__ __align__(16) u16 g_EWl[3 * 192 * 16];
__device__ __align__(16) u16 g_W2h[3 * 128 * 128];
__device__ __align__(16) u16 g_W2l[3 * 128 * 128];

__device__ __forceinline__ unsigned fenc(float f) {
    unsigned u = __float_as_uint(f);
    return (u & 0x80000000u) ? ~u : (u | 0x80000000u);
}
__device__ __forceinline__ float fdec(unsigned u) {
    return (u & 0x80000000u) ? __uint_as_float(u & 0x7fffffffu)
                             : __uint_as_float(~u);
}

// ---------------- packed f32x2 (k_update) ----------------
__device__ __forceinline__ u64 pack2(float lo, float hi) {
    u64 r;
    asm("mov.b64 %0, {%1, %2};" : "=l"(r)
        : "r"(__float_as_uint(lo)), "r"(__float_as_uint(hi)));
    return r;
}
__device__ __forceinline__ u64 pack2s(float v) { return pack2(v, v); }
__device__ __forceinline__ void ffma2(u64 &d, u64 a, u64 b) {
    asm("fma.rn.f32x2 %0, %1, %2, %0;" : "+l"(d) : "l"(a), "l"(b));
}
__device__ __forceinline__ void unpack2(u64 v, float &lo, float &hi) {
    unsigned a, b;
    asm("mov.b64 {%0, %1}, %2;" : "=r"(a), "=r"(b) : "l"(v));
    lo = __uint_as_float(a);
    hi = __uint_as_float(b);
}

// ---------------- bf16 split helpers ----------------
__device__ __forceinline__ void split_bf16(float v, u16 &h, u16 &l) {
    __nv_bfloat16 bh = __float2bfloat16(v);
    __nv_bfloat16 bl = __float2bfloat16(v - __bfloat162float(bh));
    h = __bfloat16_as_ushort(bh);
    l = __bfloat16_as_ushort(bl);
}
__device__ __forceinline__ void split2(float a, float b, u32 &h, u32 &l) {
    u16 h0, l0, h1, l1;
    split_bf16(a, h0, l0);
    split_bf16(b, h1, l1);
    h = (u32)h0 | ((u32)h1 << 16);
    l = (u32)l0 | ((u32)l1 << 16);
}

// ---------------- HMMA helpers ----------------
__device__ __forceinline__ u32 smem_u32(const void* p) {
    u32 a;
    asm("{ .reg .u64 t; cvta.to.shared.u64 t, %1; cvt.u32.u64 %0, t; }"
        : "=r"(a) : "l"(p));
    return a;
}
__device__ __forceinline__ void ldsm4(u32* r, u32 addr) {
    asm volatile("ldmatrix.sync.aligned.m8n8.x4.shared.b16 {%0,%1,%2,%3}, [%4];"
        : "=r"(r[0]), "=r"(r[1]), "=r"(r[2]), "=r"(r[3]) : "r"(addr));
}
__device__ __forceinline__ void ldsm2(u32* r, u32 addr) {
    asm volatile("ldmatrix.sync.aligned.m8n8.x2.shared.b16 {%0,%1}, [%2];"
        : "=r"(r[0]), "=r"(r[1]) : "r"(addr));
}
__device__ __forceinline__ void mma16816(float* d, const u32* a, const u32* b) {
    asm volatile("mma.sync.aligned.m16n8k16.row.col.f32.bf16.bf16.f32 "
        "{%0,%1,%2,%3}, {%4,%5,%6,%7}, {%8,%9}, {%0,%1,%2,%3};"
        : "+f"(d[0]), "+f"(d[1]), "+f"(d[2]), "+f"(d[3])
        : "r"(a[0]), "r"(a[1]), "r"(a[2]), "r"(a[3]), "r"(b[0]), "r"(b[1]));
}

// ---------------- weight preconversion ----------------
__global__ void k_prep(const float* __restrict__ mw1, const float* __restrict__ mw2,
                       const float* __restrict__ aw1) {
    int idx = blockIdx.x * blockDim.x + threadIdx.x;
    const int NP = 3 * 256 * 128, EW = 3 * 192 * 16, W2 = 3 * 128 * 128;
    u16 h, l;
    if (idx < NP) {
        int lyr = idx / (256 * 128);
        int rem = idx % (256 * 128);
        int n = rem / 128, k = rem % 128;
        float v;
        if (n < 64)        v = aw1[lyr * 64 * 272 + n * 272 + k];
        else if (n < 128)  v = aw1[lyr * 64 * 272 + (n - 64) * 272 + 128 + k];
        else               v = mw1[lyr * 128 * 144 + (n - 128) * 144 + k];
        split_bf16(v, h, l);
        g_NPh[idx] = h; g_NPl[idx] = l;
    } else if (idx < NP + EW) {
        int i = idx - NP;
        int lyr = i / (192 * 16);
        int rem = i % (192 * 16);
        int n = rem / 16, k = rem % 16;
        float v = (n < 64) ? aw1[lyr * 64 * 272 + n * 272 + 256 + k]
                           : mw1[lyr * 128 * 144 + (n - 64) * 144 + 128 + k];
        split_bf16(v, h, l);
        g_EWh[i] = h; g_EWl[i] = l;
    } else if (idx < NP + EW + W2) {
        int i = idx - NP - EW;
        split_bf16(mw2[i], h, l);
        g_W2h[i] = h; g_W2l[i] = l;
    }
}

// ---------------- detect + convert + ea split + zero ----------------
__global__ void k_detect(const unsigned* __restrict__ raw) {
    __shared__ int nz;
    if (threadIdx.x == 0) nz = 0;
    __syncthreads();
    for (int i = threadIdx.x; i < 2048; i += NT)
        if (raw[2 * i + 1] != 0u) atomicOr(&nz, 1);
    __syncthreads();
    if (threadIdx.x == 0) g_is64 = (nz == 0) ? 1 : 0;
}

__global__ void k_convert(const void* __restrict__ eidx, const float* __restrict__ ea) {
    int i = blockIdx.x * blockDim.x + threadIdx.x;
    long long stride = (long long)gridDim.x * blockDim.x;
    if (i < NE) {
        if (g_is64) {
            const long long* p = (const long long*)eidx;
            g_src[i] = (int)p[i];
            g_dst[i] = (int)p[NE + i];
        } else {
            const int* p = (const int*)eidx;
            g_src[i] = p[i];
            g_dst[i] = p[NE + i];
        }
    }
    for (long long j = i; j < (long long)NE * 16; j += stride) {
        u16 h, l;
        split_bf16(ea[j], h, l);
        g_eah[j] = h; g_eal[j] = l;
    }
    for (long long j = i; j < (long long)NN * HID; j += stride) g_agg[j] = 0.f;
    for (long long j = i; j < 3 * NN; j += stride) g_sumexp[j] = 0.f;
    if (i == 0) {
        g_maxenc[0] = 0x007FFFFFu;
        g_maxenc[1] = 0x007FFFFFu;
        g_maxenc[2] = 0x007FFFFFu;
    }
}

// ---------------- node projection (+ split store) ----------------
__global__ void k_nodeproj(const float* __restrict__ x,
                           const float* __restrict__ W,
                           const float* __restrict__ b) {
    __shared__ float sA[32 * 33];
    __shared__ float sW[128 * 33];
    int tid = threadIdx.x;
    int n0 = blockIdx.x * 32;
    for (int idx = tid; idx < 32 * 32; idx += NT) {
        int r = idx >> 5, k = idx & 31;
        int n = n0 + r;
        sA[r * 33 + k] = (n < NN) ? x[n * 32 + k] : 0.f;
    }
    for (int idx = tid; idx < 128 * 32; idx += NT) {
        int o = idx >> 5, k = idx & 31;
        sW[o * 33 + k] = W[o * 32 + k];
    }
    __syncthreads();
    int tc = tid & 31, trg = tid >> 5;
    float acc[4][4] = {};
#pragma unroll 8
    for (int k = 0; k < 32; k++) {
        float a[4], w[4];
#pragma unroll
        for (int i = 0; i < 4; i++) a[i] = sA[(trg * 4 + i) * 33 + k];
#pragma unroll
        for (int j = 0; j < 4; j++) w[j] = sW[(tc + 32 * j) * 33 + k];
#pragma unroll
        for (int i = 0; i < 4; i++)
#pragma unroll
            for (int j = 0; j < 4; j++) acc[i][j] += a[i] * w[j];
    }
#pragma unroll
    for (int i = 0; i < 4; i++) {
        int n = n0 + trg * 4 + i;
        if (n < NN)
#pragma unroll
            for (int j = 0; j < 4; j++) {
                int c = tc + 32 * j;
                float v = fmaxf(acc[i][j] + b[c], 0.f);
                g_h[n * HID + c] = v;
                u16 h, l;
                split_bf16(v, h, l);
                g_hh[n * HID + c] = h;
                g_hl[n * HID + c] = l;
            }
    }
}

// ---------------- node precompute GEMM: g_pre = h @ NPW^T (HMMA) ----------------
#define NPP 136
#define NP_AH 0
#define NP_AL 34816
#define NP_WH 69632
#define NP_WL 104448
#define SMEM_NP 139264

__global__ void __launch_bounds__(512, 1)
k_node_pre(int layer) {
    extern __shared__ char sm[];
    u16* sAh = (u16*)(sm + NP_AH);
    u16* sAl = (u16*)(sm + NP_AL);
    u16* sWh = (u16*)(sm + NP_WH);
    u16* sWl = (u16*)(sm + NP_WL);
    u32 sb = smem_u32(sm);
    int tid = threadIdx.x, lane = tid & 31, w = tid >> 5;
    int n0 = blockIdx.x * 128;

    // load A rows (contiguous nodes)
    for (int idx = tid; idx < 128 * 16; idx += 512) {
        int r = idx >> 4, c = (idx & 15) * 8;
        int n = n0 + r;
        if (n < NN) {
            *(uint4*)&sAh[r * NPP + c] = *(const uint4*)&g_hh[n * HID + c];
            *(uint4*)&sAl[r * NPP + c] = *(const uint4*)&g_hl[n * HID + c];
        } else {
            uint4 z = make_uint4(0, 0, 0, 0);
            *(uint4*)&sAh[r * NPP + c] = z;
            *(uint4*)&sAl[r * NPP + c] = z;
        }
    }

    int m0 = (w & 3) * 32, n0w = (w >> 2) * 32;
    for (int half = 0; half < 2; half++) {
        const u16* wh = g_NPh + layer * 256 * 128 + half * 128 * 128;
        const u16* wl = g_NPl + layer * 256 * 128 + half * 128 * 128;
        for (int idx = tid; idx < 128 * 16; idx += 512) {
            int r = idx >> 4, c = (idx & 15) * 8;
            *(uint4*)&sWh[r * NPP + c] = *(const uint4*)&wh[r * 128 + c];
            *(uint4*)&sWl[r * NPP + c] = *(const uint4*)&wl[r * 128 + c];
        }
        __syncthreads();
        float acc[2][4][4];
#pragma unroll
        for (int i = 0; i < 2; i++)
#pragma unroll
            for (int j = 0; j < 4; j++)
#pragma unroll
                for (int k = 0; k < 4; k++) acc[i][j][k] = 0.f;
        for (int ks = 0; ks < 8; ks++) {
            int kb = ks * 16;
            u32 ah[2][4], al[2][4];
#pragma unroll
            for (int mt = 0; mt < 2; mt++) {
                int r = m0 + mt * 16 + (lane & 15);
                int c = kb + ((lane >> 4) << 3);
                u32 off = (u32)(r * NPP + c) * 2;
                ldsm4(ah[mt], sb + NP_AH + off);
                ldsm4(al[mt], sb + NP_AL + off);
            }
#pragma unroll
            for (int nt = 0; nt < 4; nt++) {
                int rn = n0w + nt * 8 + (lane & 7);
                int cn = kb + (((lane >> 3) & 1) << 3);
                u32 offb = (u32)(rn * NPP + cn) * 2;
                u32 bh[2], bl[2];
                ldsm2(bh, sb + NP_WH + offb);
                ldsm2(bl, sb + NP_WL + offb);
#pragma unroll
                for (int mt = 0; mt < 2; mt++) {
                    mma16816(acc[mt][nt], ah[mt], bh);
                    mma16816(acc[mt][nt], ah[mt], bl);
                    mma16816(acc[mt][nt], al[mt], bh);
                }
            }
        }
        // write out
#pragma unroll
        for (int mt = 0; mt < 2; mt++)
#pragma unroll
            for (int nt = 0; nt < 4; nt++) {
                int rA = m0 + mt * 16 + (lane >> 2);
                int rB = rA + 8;
                int c = half * 128 + n0w + nt * 8 + 2 * (lane & 3);
                int nA = n0 + rA, nB = n0 + rB;
                if (nA < NN) {
                    g_pre[(u64)nA * 256 + c]     = acc[mt][nt][0];
                    g_pre[(u64)nA * 256 + c + 1] = acc[mt][nt][1];
                }
                if (nB < NN) {
                    g_pre[(u64)nB * 256 + c]     = acc[mt][nt][2];
                    g_pre[(u64)nB * 256 + c + 1] = acc[mt][nt][3];
                }
            }
        __syncthreads();
    }
}

// ---------------- attention scores (elementwise, decomposed) ----------------
__global__ void __launch_bounds__(256, 4)
k_attn_lite(const float* __restrict__ ea,
            const float* __restrict__ aw1l,   // layer-offset aw1 (64 x 272)
            const float* __restrict__ ab1,
            const float* __restrict__ aw2,
            const float* __restrict__ ab2p, int layer) {
    __shared__ float sea[64 * 17];
    __shared__ float sW[64 * 16];
    __shared__ float sb1[64], sv[64];
    __shared__ unsigned smax;
    int tid = threadIdx.x;
    int e0 = blockIdx.x * 64;
    if (tid == 0) smax = 0x007FFFFFu;
    // load ea rows (fp32, coalesced)
    {
        int r = tid >> 2, c = (tid & 3) * 4;
        float4 v = make_float4(0.f, 0.f, 0.f, 0.f);
        if (e0 + r < NE) v = *(const float4*)&ea[(u64)(e0 + r) * 16 + c];
        sea[r * 17 + c]     = v.x;
        sea[r * 17 + c + 1] = v.y;
        sea[r * 17 + c + 2] = v.z;
        sea[r * 17 + c + 3] = v.w;
    }
    // load W1e_att [64 x 16]
    {
        int r = tid >> 2, c = (tid & 3) * 4;
        float4 wv = *(const float4*)&aw1l[r * 272 + 256 + c];
        *(float4*)&sW[r * 16 + c] = wv;
    }
    if (tid < 64) { sb1[tid] = ab1[tid]; sv[tid] = aw2[tid]; }
    __syncthreads();

    int el = tid >> 2, p = tid & 3;
    int e = e0 + el;
    float score = 0.f;
    if (e < NE) {
        int s = g_src[e], d = g_dst[e];
        const float* ps = &g_pre[(u64)s * 256 + p * 16];
        const float* pd = &g_pre[(u64)d * 256 + 64 + p * 16];
        const float* er = &sea[el * 17];
#pragma unroll
        for (int c4 = 0; c4 < 4; c4++) {
            float4 a4 = *(const float4*)&ps[c4 * 4];
            float4 b4 = *(const float4*)&pd[c4 * 4];
            float av[4] = {a4.x, a4.y, a4.z, a4.w};
            float bv[4] = {b4.x, b4.y, b4.z, b4.w};
#pragma unroll
            for (int j = 0; j < 4; j++) {
                int c = p * 16 + c4 * 4 + j;
                float x = av[j] + bv[j] + sb1[c];
                const float* wr = &sW[c * 16];
#pragma unroll
                for (int k = 0; k < 16; k++) x += er[k] * wr[k];
                x = (x > 0.f) ? x : 0.2f * x;
                score += x * sv[c];
            }
        }
    }
    score += __shfl_xor_sync(0xffffffffu, score, 1);
    score += __shfl_xor_sync(0xffffffffu, score, 2);
    if (p == 0 && e < NE) {
        float sc = score + ab2p[0];
        g_scores[e] = sc;
        atomicMax(&smax, fenc(sc));
    }
    __syncthreads();
    if (tid == 0) atomicMax(&g_maxenc[layer], smax);
}

// ---------------- exp + scatter sum ----------------
__global__ void k_exp(int layer) {
    int i = blockIdx.x * blockDim.x + threadIdx.x;
    if (i >= NE) return;
    float m = fdec(g_maxenc[layer]);
    float es = expf(g_scores[i] - m);
    g_es[i] = es;
    atomicAdd(&g_sumexp[layer * NN + g_dst[i]], es);
}

// ---------------- message MLP (decomposed: K=16 MMA + vh add + GEMM2) ----------------
#define AP2 136
#define M_AH 0
#define M_AL 34816
#define M_WH 69632
#define M_WL 104448
#define M_STG 139264
#define M_META 206848
#define SMEM_MSG2 (206848 + 2560)

__global__ void __launch_bounds__(512, 1)
k_msg(const float* __restrict__ mb1,
      const float* __restrict__ mb2, int layer) {
    extern __shared__ char sm[];
    u16* sAh = (u16*)(sm + M_AH);
    u16* sAl = (u16*)(sm + M_AL);
    u16* sWh = (u16*)(sm + M_WH);
    u16* sWl = (u16*)(sm + M_WL);
    float* stage = (float*)(sm + M_STG);   // 128 x 132 fp32
    int*   ssrc = (int*)(sm + M_META);
    int*   sdst = (int*)(sm + M_META + 512);
    float* swt  = (float*)(sm + M_META + 1024);
    float* smb1 = (float*)(sm + M_META + 1536);
    float* smb2 = (float*)(sm + M_META + 2048);
    u32 sb = smem_u32(sm);

    int tid = threadIdx.x, lane = tid & 31, w = tid >> 5;
    int e0 = blockIdx.x * 128;
    if (tid < 128) {
        int e = e0 + tid;
        if (e < NE) {
            ssrc[tid] = g_src[e];
            int d = g_dst[e];
            sdst[tid] = d;
            swt[tid] = g_es[e] / (g_sumexp[layer * NN + d] + 1e-6f);
        } else {
            ssrc[tid] = 0; sdst[tid] = 0; swt[tid] = 0.f;
        }
        smb1[tid] = mb1[tid];
        smb2[tid] = mb2[tid];
    }
    __syncthreads();

    // ea split -> A tile cols 0..15
    for (int idx = tid; idx < 128 * 2; idx += 512) {
        int r = idx >> 1, c = (idx & 1) * 8;
        int e = min(e0 + r, NE - 1);
        *(uint4*)&sAh[r * AP2 + c] = *(const uint4*)&g_eah[(u64)e * 16 + c];
        *(uint4*)&sAl[r * AP2 + c] = *(const uint4*)&g_eal[(u64)e * 16 + c];
    }
    // W_ea (msg rows 64..191 of g_EW) -> W tile cols 0..15
    {
        const u16* wh = g_EWh + layer * 192 * 16 + 64 * 16;
        const u16* wl = g_EWl + layer * 192 * 16 + 64 * 16;
        for (int idx = tid; idx < 128 * 2; idx += 512) {
            int r = idx >> 1, c = (idx & 1) * 8;
            *(uint4*)&sWh[r * AP2 + c] = *(const uint4*)&wh[r * 16 + c];
            *(uint4*)&sWl[r * AP2 + c] = *(const uint4*)&wl[r * 16 + c];
        }
    }
    // gather vh[src] fp32 -> stage
    {
        int r = tid >> 2, q = tid & 3;
        const float* vp = &g_pre[(u64)ssrc[r] * 256 + 128 + q * 32];
        float* sp = &stage[r * 132 + q * 32];
#pragma unroll
        for (int j = 0; j < 8; j++)
            *(float4*)&sp[j * 4] = *(const float4*)&vp[j * 4];
    }
    __syncthreads();

    int m0 = (w & 3) * 32, n0 = (w >> 2) * 32;
    // GEMM_ea: K=16, 1 kstep x 3 terms
    float acc[2][4][4];
#pragma unroll
    for (int i = 0; i < 2; i++)
#pragma unroll
        for (int j = 0; j < 4; j++)
#pragma unroll
            for (int k = 0; k < 4; k++) acc[i][j][k] = 0.f;
    {
        u32 ah[2][4], al[2][4];
#pragma unroll
        for (int mt = 0; mt < 2; mt++) {
            int r = m0 + mt * 16 + (lane & 15);
            int c = (lane >> 4) << 3;
            u32 off = (u32)(r * AP2 + c) * 2;
            ldsm4(ah[mt], sb + M_AH + off);
            ldsm4(al[mt], sb + M_AL + off);
        }
#pragma unroll
        for (int nt = 0; nt < 4; nt++) {
            int rn = n0 + nt * 8 + (lane & 7);
            int cn = ((lane >> 3) & 1) << 3;
            u32 offb = (u32)(rn * AP2 + cn) * 2;
            u32 bh[2], bl[2];
            ldsm2(bh, sb + M_WH + offb);
            ldsm2(bl, sb + M_WL + offb);
#pragma unroll
            for (int mt = 0; mt < 2; mt++) {
                mma16816(acc[mt][nt], ah[mt], bh);
                mma16816(acc[mt][nt], ah[mt], bl);
                mma16816(acc[mt][nt], al[mt], bh);
            }
        }
    }
    __syncthreads();

    // epilogue-ea: m = relu(eaW + vh + b1) -> split into A tiles (full K=128)
#pragma unroll
    for (int mt = 0; mt < 2; mt++)
#pragma unroll
        for (int nt = 0; nt < 4; nt++) {
            int rA = m0 + mt * 16 + (lane >> 2);
            int rB = rA + 8;
            int c = n0 + nt * 8 + 2 * (lane & 3);
            float b0 = smb1[c], b1 = smb1[c + 1];
            u32 h, l;
            split2(fmaxf(acc[mt][nt][0] + stage[rA * 132 + c]     + b0, 0.f),
                   fmaxf(acc[mt][nt][1] + stage[rA * 132 + c + 1] + b1, 0.f), h, l);
            *(u32*)&sAh[rA * AP2 + c] = h;
            *(u32*)&sAl[rA * AP2 + c] = l;
            split2(fmaxf(acc[mt][nt][2] + stage[rB * 132 + c]     + b0, 0.f),
                   fmaxf(acc[mt][nt][3] + stage[rB * 132 + c + 1] + b1, 0.f), h, l);
            *(u32*)&sAh[rB * AP2 + c] = h;
            *(u32*)&sAl[rB * AP2 + c] = l;
        }
    // W2 load
    {
        const u16* wh = g_W2h + layer * 128 * 128;
        const u16* wl = g_W2l + layer * 128 * 128;
        for (int idx = tid; idx < 128 * 16; idx += 512) {
            int r = idx >> 4, c = (idx & 15) * 8;
            *(uint4*)&sWh[r * AP2 + c] = *(const uint4*)&wh[r * 128 + c];
            *(uint4*)&sWl[r * AP2 + c] = *(const uint4*)&wl[r * 128 + c];
        }
    }
    __syncthreads();

    // GEMM2 K=128
    float acc2[2][4][4];
#pragma unroll
    for (int i = 0; i < 2; i++)
#pragma unroll
        for (int j = 0; j < 4; j++)
#pragma unroll
            for (int k = 0; k < 4; k++) acc2[i][j][k] = 0.f;

    for (int ks = 0; ks < 8; ks++) {
        int kb = ks * 16;
        u32 ah[2][4], al[2][4];
#pragma unroll
        for (int mt = 0; mt < 2; mt++) {
            int r = m0 + mt * 16 + (lane & 15);
            int c = kb + ((lane >> 4) << 3);
            u32 off = (u32)(r * AP2 + c) * 2;
            ldsm4(ah[mt], sb + M_AH + off);
            ldsm4(al[mt], sb + M_AL + off);
        }
#pragma unroll
        for (int nt = 0; nt < 4; nt++) {
            int rn = n0 + nt * 8 + (lane & 7);
            int cn = kb + (((lane >> 3) & 1) << 3);
            u32 offb = (u32)(rn * AP2 + cn) * 2;
            u32 bh[2], bl[2];
            ldsm2(bh, sb + M_WH + offb);
            ldsm2(bl, sb + M_WL + offb);
#pragma unroll
            for (int mt = 0; mt < 2; mt++) {
                mma16816(acc2[mt][nt], ah[mt], bh);
                mma16816(acc2[mt][nt], ah[mt], bl);
                mma16816(acc2[mt][nt], al[mt], bh);
            }
        }
    }

    // epilogue2: weighted atomic scatter (direct)
#pragma unroll
    for (int mt = 0; mt < 2; mt++)
#pragma unroll
        for (int nt = 0; nt < 4; nt++) {
            int rA = m0 + mt * 16 + (lane >> 2);
            int rB = rA + 8;
            int c = n0 + nt * 8 + 2 * (lane & 3);
            float b0 = smb2[c], b1 = smb2[c + 1];
            float wA = swt[rA], wB = swt[rB];
            float* pA = &g_agg[(u64)sdst[rA] * HID + c];
            float* pB = &g_agg[(u64)sdst[rB] * HID + c];
            atomicAdd(pA,     (acc2[mt][nt][0] + b0) * wA);
            atomicAdd(pA + 1, (acc2[mt][nt][1] + b1) * wA);
            atomicAdd(pB,     (acc2[mt][nt][2] + b0) * wB);
            atomicAdd(pB + 1, (acc2[mt][nt][3] + b1) * wB);
        }
}

// ---------------- node update + residual + layernorm (FFMA2, + split store) ----------------
__global__ void __launch_bounds__(256, 2)
k_update(const float* __restrict__ uw1,
         const float* __restrict__ ub1,
         const float* __restrict__ uw2,
         const float* __restrict__ ub2,
         const float* __restrict__ lng,
         const float* __restrict__ lnb) {
    extern __shared__ float smu[];
    float* sAT = smu;
    float* sW  = sAT + 16 * 132;
    float* sM  = sW + 16 * 128;

    int tid = threadIdx.x;
    int n0 = blockIdx.x * 128;
    int tcol = tid & 15, trow = tid >> 4;
    int r0 = trow * 8, c0 = tcol * 8;
    int lrow = tid & 127;
    int lkq0 = (tid >> 7) * 2;

    u64 acc[8][4];
#pragma unroll
    for (int i = 0; i < 8; i++)
#pragma unroll
        for (int j = 0; j < 4; j++) acc[i][j] = 0ull;

    for (int kb = 0; kb < 256; kb += 16) {
#pragma unroll
        for (int q = 0; q < 2; q++) {
            int kq = lkq0 + q;
            int kg = kb + kq * 4;
            int n = n0 + lrow;
            float4 v = make_float4(0.f, 0.f, 0.f, 0.f);
            if (n < NN) {
                if (kg < 128) v = *(const float4*)&g_h[n * HID + kg];
                else {
                    v = *(const float4*)&g_agg[n * HID + (kg - 128)];
                    *(float4*)&g_agg[n * HID + (kg - 128)] =
                        make_float4(0.f, 0.f, 0.f, 0.f);
                }
            }
            sAT[(kq * 4 + 0) * 132 + lrow] = v.x;
            sAT[(kq * 4 + 1) * 132 + lrow] = v.y;
            sAT[(kq * 4 + 2) * 132 + lrow] = v.z;
            sAT[(kq * 4 + 3) * 132 + lrow] = v.w;
        }
#pragma unroll
        for (int q = 0; q < 2; q++) {
            int kq = lkq0 + q;
            float4 w = *(const float4*)&uw1[lrow * 256 + kb + kq * 4];
            sW[(kq * 4 + 0) * 128 + lrow] = w.x;
            sW[(kq * 4 + 1) * 128 + lrow] = w.y;
            sW[(kq * 4 + 2) * 128 + lrow] = w.z;
            sW[(kq * 4 + 3) * 128 + lrow] = w.w;
        }
        __syncthreads();
#pragma unroll
        for (int k = 0; k < 16; k++) {
            float4 a0 = *(const float4*)&sAT[k * 132 + r0];
            float4 a1 = *(const float4*)&sAT[k * 132 + r0 + 4];
            float4 w0 = *(const float4*)&sW[k * 128 + c0];
            float4 w1 = *(const float4*)&sW[k * 128 + c0 + 4];
            u64 ww0 = pack2(w0.x, w0.y), ww1 = pack2(w0.z, w0.w);
            u64 ww2 = pack2(w1.x, w1.y), ww3 = pack2(w1.z, w1.w);
            float av[8] = {a0.x, a0.y, a0.z, a0.w, a1.x, a1.y, a1.z, a1.w};
#pragma unroll
            for (int i = 0; i < 8; i++) {
                u64 ap = pack2s(av[i]);
                ffma2(acc[i][0], ap, ww0);
                ffma2(acc[i][1], ap, ww1);
                ffma2(acc[i][2], ap, ww2);
                ffma2(acc[i][3], ap, ww3);
            }
        }
        __syncthreads();
    }

    {
        float4 b0 = *(const float4*)&ub1[c0];
        float4 b1 = *(const float4*)&ub1[c0 + 4];
        float bb[8] = {b0.x, b0.y, b0.z, b0.w, b1.x, b1.y, b1.z, b1.w};
#pragma unroll
        for (int i = 0; i < 8; i++) {
            float* row = &sM[(r0 + i) * 132 + c0];
#pragma unroll
            for (int jp = 0; jp < 4; jp++) {
                float lo, hi;
                unpack2(acc[i][jp], lo, hi);
                row[2 * jp]     = fmaxf(lo + bb[2 * jp], 0.f);
                row[2 * jp + 1] = fmaxf(hi + bb[2 * jp + 1], 0.f);
            }
        }
    }
    __syncthreads();

    u64 acc2[8][4];
#pragma unroll
    for (int i = 0; i < 8; i++)
#pragma unroll
        for (int j = 0; j < 4; j++) acc2[i][j] = 0ull;

    for (int kb = 0; kb < 128; kb += 16) {
#pragma unroll
        for (int q = 0; q < 2; q++) {
            int kq = lkq0 + q;
            float4 w = *(const float4*)&uw2[lrow * 128 + kb + kq * 4];
            sW[(kq * 4 + 0) * 128 + lrow] = w.x;
            sW[(kq * 4 + 1) * 128 + lrow] = w.y;
            sW[(kq * 4 + 2) * 128 + lrow] = w.z;
            sW[(kq * 4 + 3) * 128 + lrow] = w.w;
        }
        __syncthreads();
#pragma unroll
        for (int k = 0; k < 16; k++) {
            int kg = kb + k;
            float4 w0 = *(const float4*)&sW[k * 128 + c0];
            float4 w1 = *(const float4*)&sW[k * 128 + c0 + 4];
            u64 ww0 = pack2(w0.x, w0.y), ww1 = pack2(w0.z, w0.w);
            u64 ww2 = pack2(w1.x, w1.y), ww3 = pack2(w1.z, w1.w);
#pragma unroll
            for (int i = 0; i < 8; i++) {
                u64 ap = pack2s(sM[(r0 + i) * 132 + kg]);
                ffma2(acc2[i][0], ap, ww0);
                ffma2(acc2[i][1], ap, ww1);
                ffma2(acc2[i][2], ap, ww2);
                ffma2(acc2[i][3], ap, ww3);
            }
        }
        __syncthreads();
    }

    {
        float4 b0 = *(const float4*)&ub2[c0];
        float4 b1 = *(const float4*)&ub2[c0 + 4];
        float bb[8] = {b0.x, b0.y, b0.z, b0.w, b1.x, b1.y, b1.z, b1.w};
        float4 g0 = *(const float4*)&lng[c0];
        float4 g1 = *(const float4*)&lng[c0 + 4];
        float gg[8] = {g0.x, g0.y, g0.z, g0.w, g1.x, g1.y, g1.z, g1.w};
        float4 q0 = *(const float4*)&lnb[c0];
        float4 q1 = *(const float4*)&lnb[c0 + 4];
        float qq[8] = {q0.x, q0.y, q0.z, q0.w, q1.x, q1.y, q1.z, q1.w};

#pragma unroll
        for (int i = 0; i < 8; i++) {
            int n = n0 + r0 + i;
            float v[8];
            if (n < NN) {
                float4 h0 = *(const float4*)&g_h[n * HID + c0];
                float4 h1 = *(const float4*)&g_h[n * HID + c0 + 4];
                float hh[8] = {h0.x, h0.y, h0.z, h0.w, h1.x, h1.y, h1.z, h1.w};
#pragma unroll
                for (int jp = 0; jp < 4; jp++) {
                    float lo, hi;
                    unpack2(acc2[i][jp], lo, hi);
                    v[2 * jp]     = fmaxf(lo + bb[2 * jp] + hh[2 * jp], 0.f);
                    v[2 * jp + 1] = fmaxf(hi + bb[2 * jp + 1] + hh[2 * jp + 1], 0.f);
                }
            } else {
#pragma unroll
                for (int j = 0; j < 8; j++) v[j] = 0.f;
            }
            float s = 0.f, sq = 0.f;
#pragma unroll
            for (int j = 0; j < 8; j++) { s += v[j]; sq += v[j] * v[j]; }
#pragma unroll
            for (int off = 8; off > 0; off >>= 1) {
                s  += __shfl_xor_sync(0xffffffffu, s, off);
                sq += __shfl_xor_sync(0xffffffffu, sq, off);
            }
            float mu = s * (1.f / 128.f);
            float var = sq * (1.f / 128.f) - mu * mu;
            float rs = rsqrtf(var + 1e-5f);
            if (n < NN) {
                float o[8];
#pragma unroll
                for (int j = 0; j < 8; j++)
                    o[j] = (v[j] - mu) * rs * gg[j] + qq[j];
                *(float4*)&g_h[n * HID + c0]     = make_float4(o[0], o[1], o[2], o[3]);
                *(float4*)&g_h[n * HID + c0 + 4] = make_float4(o[4], o[5], o[6], o[7]);
#pragma unroll
                for (int j = 0; j < 8; j += 2) {
                    u32 h, l;
                    split2(o[j], o[j + 1], h, l);
                    *(u32*)&g_hh[n * HID + c0 + j] = h;
                    *(u32*)&g_hl[n * HID + c0 + j] = l;
                }
            }
        }
    }
}

// ---------------- final readout ----------------
__global__ void k_final(const float* __restrict__ gc,
                        const float* __restrict__ qw1,
                        const float* __restrict__ qb1,
                        const float* __restrict__ qw2,
                        const float* __restrict__ qb2p,
                        float* __restrict__ out) {
    __shared__ float sA[32 * 33];
    __shared__ float sW[128 * 33];
    __shared__ float sctx[64];
    __shared__ float sout[32];
    int tid = threadIdx.x;
    int n0 = blockIdx.x * 32;
    if (tid < 64) sctx[tid] = gc[tid];
    if (tid < 32) sout[tid] = qb2p[0];
    __syncthreads();
    int tc = tid & 31, trg = tid >> 5;
    float acc[4][4] = {};
    for (int kb = 0; kb < 192; kb += 32) {
        for (int idx = tid; idx < 32 * 32; idx += NT) {
            int r = idx >> 5, kk = idx & 31;
            int n = n0 + r;
            int kg = kb + kk;
            float v = 0.f;
            if (n < NN) v = (kg < 128) ? g_h[n * HID + kg] : sctx[kg - 128];
            sA[r * 33 + kk] = v;
        }
        for (int idx = tid; idx < 128 * 32; idx += NT) {
            int o = idx >> 5, kk = idx & 31;
            sW[o * 33 + kk] = qw1[o * 192 + kb + kk];
        }
        __syncthreads();
#pragma unroll 8
        for (int k = 0; k < 32; k++) {
            float a[4], w[4];
#pragma unroll
            for (int i = 0; i < 4; i++) a[i] = sA[(trg * 4 + i) * 33 + k];
#pragma unroll
            for (int j = 0; j < 4; j++) w[j] = sW[(tc + 32 * j) * 33 + k];
#pragma unroll
            for (int i = 0; i < 4; i++)
#pragma unroll
                for (int j = 0; j < 4; j++) acc[i][j] += a[i] * w[j];
        }
        __syncthreads();
    }
    float p[4] = {0.f, 0.f, 0.f, 0.f};
#pragma unroll
    for (int j = 0; j < 4; j++) {
        int c = tc + 32 * j;
        float b = qb1[c], w2 = qw2[c];
#pragma unroll
        for (int i = 0; i < 4; i++) {
            float v = fmaxf(acc[i][j] + b, 0.f);
            p[i] += v * w2;
        }
    }
#pragma unroll
    for (int i = 0; i < 4; i++) atomicAdd(&sout[trg * 4 + i], p[i]);
    __syncthreads();
    if (tid < 32) {
        int n = n0 + tid;
        if (n < NN) out[n] = sout[tid];
    }
}

// ---------------- launch ----------------
extern "C" void kernel_launch(void* const* d_in, const int* in_sizes, int n_in,
                              void* d_out, int out_size) {
    const float* x    = (const float*)d_in[0];
    const void*  eidx = d_in[1];
    const float* ea   = (const float*)d_in[2];
    const float* gc   = (const float*)d_in[3];
    const float* npw  = (const float*)d_in[4];
    const float* npb  = (const float*)d_in[5];
    const float* mw1  = (const float*)d_in[6];
    const float* mb1  = (const float*)d_in[7];
    const float* mw2  = (const float*)d_in[8];
    const float* mb2  = (const float*)d_in[9];
    const float* aw1  = (const float*)d_in[10];
    const float* ab1  = (const float*)d_in[11];
    const float* aw2  = (const float*)d_in[12];
    const float* ab2  = (const float*)d_in[13];
    const float* uw1  = (const float*)d_in[14];
    const float* ub1  = (const float*)d_in[15];
    const float* uw2  = (const float*)d_in[16];
    const float* ub2  = (const float*)d_in[17];
    const float* lng  = (const float*)d_in[18];
    const float* lnb  = (const float*)d_in[19];
    const float* qw1  = (const float*)d_in[20];
    const float* qb1  = (const float*)d_in[21];
    const float* qw2  = (const float*)d_in[22];
    const float* qb2  = (const float*)d_in[23];
    float* out = (float*)d_out;

    const int smem_upd = (16 * 132 + 16 * 128 + 128 * 132) * 4;
    cudaFuncSetAttribute(k_msg, cudaFuncAttributeMaxDynamicSharedMemorySize, SMEM_MSG2);
    cudaFuncSetAttribute(k_node_pre, cudaFuncAttributeMaxDynamicSharedMemorySize, SMEM_NP);
    cudaFuncSetAttribute(k_update, cudaFuncAttributeMaxDynamicSharedMemorySize, smem_upd);

    k_prep<<<(3 * (256 * 128 + 192 * 16 + 128 * 128) + 255) / 256, 256>>>(mw1, mw2, aw1);
    k_detect<<<1, NT>>>((const unsigned*)eidx);
    k_convert<<<(NE + NT - 1) / NT, NT>>>(eidx, ea);
    k_nodeproj<<<(NN + 31) / 32, NT>>>(x, npw, npb);

    int ngrid = (NN + 127) / 128;
    for (int l = 0; l < 3; l++) {
        k_node_pre<<<ngrid, 512, SMEM_NP>>>(l);
        k_attn_lite<<<(NE + 63) / 64, 256>>>(ea, aw1 + l * 64 * 272, ab1 + l * 64,
                                             aw2 + l * 64, ab2 + l, l);
        k_exp<<<(NE + NT - 1) / NT, NT>>>(l);
        k_msg<<<(NE + 127) / 128, 512, SMEM_MSG2>>>(mb1 + l * 128, mb2 + l * 128, l);
        k_update<<<(NN + 127) / 128, NT, smem_upd>>>(uw1 + l * 128 * 256, ub1 + l * 128,
                                                     uw2 + l * 128 * 128, ub2 + l * 128,
                                                     lng + l * 128, lnb + l * 128);
    }
    k_final<<<(NN + 31) / 32, NT>>>(gc, qw1, qb1, qw2, qb2, out);
}

// round 8
// speedup vs baseline: 1.3190x; 1.2107x over previous
#include <cuda_runtime.h>
#include <cuda_bf16.h>

#define NN 50000
#define NE 600000
#define HID 128
#define NT 256

typedef unsigned long long u64;
typedef unsigned int u32;
typedef unsigned short u16;

// ---------------- scratch ----------------
__device__ float g_h[NN * HID];
__device__ float g_pre[NN * 256];      // [0:64)=u_s, [64:128)=u_d, [128:256)=vh
__device__ float g_msgbuf[(u64)NE * 128];
__device__ float g_sumexp[3 * NN];
__device__ float g_scores[NE];
__device__ float g_es[NE];
__device__ int   g_src[NE];
__device__ int   g_dst[NE];
__device__ unsigned g_maxenc[3];
__device__ int   g_is64;
// CSR by dst
__device__ int g_cnt[NN];
__device__ int g_row[NN];
__device__ int g_cur[NN];
__device__ int g_eord[NE];
// bf16 hi/lo splits
__device__ __align__(16) u16 g_hh[NN * HID];
__device__ __align__(16) u16 g_hl[NN * HID];
__device__ __align__(16) u16 g_eah[NE * 16];
__device__ __align__(16) u16 g_eal[NE * 16];
__device__ __align__(16) u16 g_NPh[3 * 256 * 128];
__device__ __align__(16) u16 g_NPl[3 * 256 * 128];
__device__ __align__(16) u16 g_EWh[3 * 192 * 16];
__device__ __align__(16) u16 g_EWl[3 * 192 * 16];
__device__ __align__(16) u16 g_W2h[3 * 128 * 128];
__device__ __align__(16) u16 g_W2l[3 * 128 * 128];
__device__ __align__(16) u16 g_U1h[3 * 256 * 128];  // [half][out][in-half]
__device__ __align__(16) u16 g_U1l[3 * 256 * 128];
__device__ __align__(16) u16 g_U2h[3 * 128 * 128];
__device__ __align__(16) u16 g_U2l[3 * 128 * 128];

__device__ __forceinline__ unsigned fenc(float f) {
    unsigned u = __float_as_uint(f);
    return (u & 0x80000000u) ? ~u : (u | 0x80000000u);
}
__device__ __forceinline__ float fdec(unsigned u) {
    return (u & 0x80000000u) ? __uint_as_float(u & 0x7fffffffu)
                             : __uint_as_float(~u);
}

// ---------------- bf16 split helpers ----------------
__device__ __forceinline__ void split_bf16(float v, u16 &h, u16 &l) {
    __nv_bfloat16 bh = __float2bfloat16(v);
    __nv_bfloat16 bl = __float2bfloat16(v - __bfloat162float(bh));
    h = __bfloat16_as_ushort(bh);
    l = __bfloat16_as_ushort(bl);
}
__device__ __forceinline__ void split2(float a, float b, u32 &h, u32 &l) {
    u16 h0, l0, h1, l1;
    split_bf16(a, h0, l0);
    split_bf16(b, h1, l1);
    h = (u32)h0 | ((u32)h1 << 16);
    l = (u32)l0 | ((u32)l1 << 16);
}

// ---------------- HMMA helpers ----------------
__device__ __forceinline__ u32 smem_u32(const void* p) {
    u32 a;
    asm("{ .reg .u64 t; cvta.to.shared.u64 t, %1; cvt.u32.u64 %0, t; }"
        : "=r"(a) : "l"(p));
    return a;
}
__device__ __forceinline__ void ldsm4(u32* r, u32 addr) {
    asm volatile("ldmatrix.sync.aligned.m8n8.x4.shared.b16 {%0,%1,%2,%3}, [%4];"
        : "=r"(r[0]), "=r"(r[1]), "=r"(r[2]), "=r"(r[3]) : "r"(addr));
}
__device__ __forceinline__ void ldsm2(u32* r, u32 addr) {
    asm volatile("ldmatrix.sync.aligned.m8n8.x2.shared.b16 {%0,%1}, [%2];"
        : "=r"(r[0]), "=r"(r[1]) : "r"(addr));
}
__device__ __forceinline__ void mma16816(float* d, const u32* a, const u32* b) {
    asm volatile("mma.sync.aligned.m16n8k16.row.col.f32.bf16.bf16.f32 "
        "{%0,%1,%2,%3}, {%4,%5,%6,%7}, {%8,%9}, {%0,%1,%2,%3};"
        : "+f"(d[0]), "+f"(d[1]), "+f"(d[2]), "+f"(d[3])
        : "r"(a[0]), "r"(a[1]), "r"(a[2]), "r"(a[3]), "r"(b[0]), "r"(b[1]));
}

// ---------------- weight preconversion ----------------
__global__ void k_prep(const float* __restrict__ mw1, const float* __restrict__ mw2,
                       const float* __restrict__ aw1, const float* __restrict__ uw1,
                       const float* __restrict__ uw2) {
    int idx = blockIdx.x * blockDim.x + threadIdx.x;
    const int NP = 3 * 256 * 128, EW = 3 * 192 * 16, W2 = 3 * 128 * 128;
    const int U1 = 3 * 256 * 128, U2 = 3 * 128 * 128;
    u16 h, l;
    if (idx < NP) {
        int lyr = idx / (256 * 128);
        int rem = idx % (256 * 128);
        int n = rem / 128, k = rem % 128;
        float v;
        if (n < 64)        v = aw1[lyr * 64 * 272 + n * 272 + k];
        else if (n < 128)  v = aw1[lyr * 64 * 272 + (n - 64) * 272 + 128 + k];
        else               v = mw1[lyr * 128 * 144 + (n - 128) * 144 + k];
        split_bf16(v, h, l);
        g_NPh[idx] = h; g_NPl[idx] = l;
    } else if (idx < NP + EW) {
        int i = idx - NP;
        int lyr = i / (192 * 16);
        int rem = i % (192 * 16);
        int n = rem / 16, k = rem % 16;
        float v = (n < 64) ? aw1[lyr * 64 * 272 + n * 272 + 256 + k]
                           : mw1[lyr * 128 * 144 + (n - 64) * 144 + 128 + k];
        split_bf16(v, h, l);
        g_EWh[i] = h; g_EWl[i] = l;
    } else if (idx < NP + EW + W2) {
        int i = idx - NP - EW;
        split_bf16(mw2[i], h, l);
        g_W2h[i] = h; g_W2l[i] = l;
    } else if (idx < NP + EW + W2 + U1) {
        int i = idx - NP - EW - W2;
        int lyr = i / 32768;
        int rem = i % 32768;
        int half = rem / 16384;
        int r2 = rem % 16384;
        int n = r2 / 128, k = r2 % 128;
        split_bf16(uw1[lyr * 32768 + n * 256 + half * 128 + k], h, l);
        g_U1h[i] = h; g_U1l[i] = l;
    } else if (idx < NP + EW + W2 + U1 + U2) {
        int i = idx - NP - EW - W2 - U1;
        split_bf16(uw2[i], h, l);
        g_U2h[i] = h; g_U2l[i] = l;
    }
}

// ---------------- detect + convert + ea split + zero ----------------
__global__ void k_detect(const unsigned* __restrict__ raw) {
    __shared__ int nz;
    if (threadIdx.x == 0) nz = 0;
    __syncthreads();
    for (int i = threadIdx.x; i < 2048; i += NT)
        if (raw[2 * i + 1] != 0u) atomicOr(&nz, 1);
    __syncthreads();
    if (threadIdx.x == 0) g_is64 = (nz == 0) ? 1 : 0;
}

__global__ void k_convert(const void* __restrict__ eidx, const float* __restrict__ ea) {
    int i = blockIdx.x * blockDim.x + threadIdx.x;
    long long stride = (long long)gridDim.x * blockDim.x;
    if (i < NE) {
        if (g_is64) {
            const long long* p = (const long long*)eidx;
            g_src[i] = (int)p[i];
            g_dst[i] = (int)p[NE + i];
        } else {
            const int* p = (const int*)eidx;
            g_src[i] = p[i];
            g_dst[i] = p[NE + i];
        }
    }
    for (long long j = i; j < (long long)NE * 16; j += stride) {
        u16 h, l;
        split_bf16(ea[j], h, l);
        g_eah[j] = h; g_eal[j] = l;
    }
    for (long long j = i; j < 3 * NN; j += stride) g_sumexp[j] = 0.f;
    for (long long j = i; j < NN; j += stride) g_cnt[j] = 0;
    if (i == 0) {
        g_maxenc[0] = 0x007FFFFFu;
        g_maxenc[1] = 0x007FFFFFu;
        g_maxenc[2] = 0x007FFFFFu;
    }
}

// ---------------- counting sort by dst (CSR) ----------------
__global__ void k_hist() {
    int i = blockIdx.x * blockDim.x + threadIdx.x;
    if (i < NE) atomicAdd(&g_cnt[g_dst[i]], 1);
}

__global__ void k_scan() {
    __shared__ int warpsum[32];
    __shared__ int scarry;
    int tid = threadIdx.x, lane = tid & 31, wid = tid >> 5;
    if (tid == 0) scarry = 0;
    __syncthreads();
    for (int base = 0; base < NN; base += 1024) {
        int i = base + tid;
        int v = (i < NN) ? g_cnt[i] : 0;
        int s = v;
#pragma unroll
        for (int off = 1; off < 32; off <<= 1) {
            int t = __shfl_up_sync(0xffffffffu, s, off);
            if (lane >= off) s += t;
        }
        if (lane == 31) warpsum[wid] = s;
        __syncthreads();
        if (wid == 0) {
            int ws = warpsum[lane];
#pragma unroll
            for (int off = 1; off < 32; off <<= 1) {
                int t = __shfl_up_sync(0xffffffffu, ws, off);
                if (lane >= off) ws += t;
            }
            warpsum[lane] = ws;
        }
        __syncthreads();
        int incl = s + (wid > 0 ? warpsum[wid - 1] : 0) + scarry;
        if (i < NN) { g_row[i] = incl - v; g_cur[i] = incl - v; }
        __syncthreads();
        if (tid == 1023) scarry = incl;
        __syncthreads();
    }
}

__global__ void k_scatter() {
    int i = blockIdx.x * blockDim.x + threadIdx.x;
    if (i < NE) {
        int pos = atomicAdd(&g_cur[g_dst[i]], 1);
        g_eord[pos] = i;
    }
}

// ---------------- node projection (+ split store) ----------------
__global__ void k_nodeproj(const float* __restrict__ x,
                           const float* __restrict__ W,
                           const float* __restrict__ b) {
    __shared__ float sA[32 * 33];
    __shared__ float sW[128 * 33];
    int tid = threadIdx.x;
    int n0 = blockIdx.x * 32;
    for (int idx = tid; idx < 32 * 32; idx += NT) {
        int r = idx >> 5, k = idx & 31;
        int n = n0 + r;
        sA[r * 33 + k] = (n < NN) ? x[n * 32 + k] : 0.f;
    }
    for (int idx = tid; idx < 128 * 32; idx += NT) {
        int o = idx >> 5, k = idx & 31;
        sW[o * 33 + k] = W[o * 32 + k];
    }
    __syncthreads();
    int tc = tid & 31, trg = tid >> 5;
    float acc[4][4] = {};
#pragma unroll 8
    for (int k = 0; k < 32; k++) {
        float a[4], w[4];
#pragma unroll
        for (int i = 0; i < 4; i++) a[i] = sA[(trg * 4 + i) * 33 + k];
#pragma unroll
        for (int j = 0; j < 4; j++) w[j] = sW[(tc + 32 * j) * 33 + k];
#pragma unroll
        for (int i = 0; i < 4; i++)
#pragma unroll
            for (int j = 0; j < 4; j++) acc[i][j] += a[i] * w[j];
    }
#pragma unroll
    for (int i = 0; i < 4; i++) {
        int n = n0 + trg * 4 + i;
        if (n < NN)
#pragma unroll
            for (int j = 0; j < 4; j++) {
                int c = tc + 32 * j;
                float v = fmaxf(acc[i][j] + b[c], 0.f);
                g_h[n * HID + c] = v;
                u16 h, l;
                split_bf16(v, h, l);
                g_hh[n * HID + c] = h;
                g_hl[n * HID + c] = l;
            }
    }
}

// ---------------- node precompute GEMM: g_pre = h @ NPW^T (HMMA) ----------------
#define NPP 136
#define NP_AH 0
#define NP_AL 34816
#define NP_WH 69632
#define NP_WL 104448
#define SMEM_NP 139264

__global__ void __launch_bounds__(512, 1)
k_node_pre(int layer) {
    extern __shared__ char sm[];
    u16* sAh = (u16*)(sm + NP_AH);
    u16* sAl = (u16*)(sm + NP_AL);
    u16* sWh = (u16*)(sm + NP_WH);
    u16* sWl = (u16*)(sm + NP_WL);
    u32 sb = smem_u32(sm);
    int tid = threadIdx.x, lane = tid & 31, w = tid >> 5;
    int n0 = blockIdx.x * 128;

    for (int idx = tid; idx < 128 * 16; idx += 512) {
        int r = idx >> 4, c = (idx & 15) * 8;
        int n = n0 + r;
        if (n < NN) {
            *(uint4*)&sAh[r * NPP + c] = *(const uint4*)&g_hh[n * HID + c];
            *(uint4*)&sAl[r * NPP + c] = *(const uint4*)&g_hl[n * HID + c];
        } else {
            uint4 z = make_uint4(0, 0, 0, 0);
            *(uint4*)&sAh[r * NPP + c] = z;
            *(uint4*)&sAl[r * NPP + c] = z;
        }
    }

    int m0 = (w & 3) * 32, n0w = (w >> 2) * 32;
    for (int half = 0; half < 2; half++) {
        const u16* wh = g_NPh + layer * 256 * 128 + half * 128 * 128;
        const u16* wl = g_NPl + layer * 256 * 128 + half * 128 * 128;
        for (int idx = tid; idx < 128 * 16; idx += 512) {
            int r = idx >> 4, c = (idx & 15) * 8;
            *(uint4*)&sWh[r * NPP + c] = *(const uint4*)&wh[r * 128 + c];
            *(uint4*)&sWl[r * NPP + c] = *(const uint4*)&wl[r * 128 + c];
        }
        __syncthreads();
        float acc[2][4][4];
#pragma unroll
        for (int i = 0; i < 2; i++)
#pragma unroll
            for (int j = 0; j < 4; j++)
#pragma unroll
                for (int k = 0; k < 4; k++) acc[i][j][k] = 0.f;
        for (int ks = 0; ks < 8; ks++) {
            int kb = ks * 16;
            u32 ah[2][4], al[2][4];
#pragma unroll
            for (int mt = 0; mt < 2; mt++) {
                int r = m0 + mt * 16 + (lane & 15);
                int c = kb + ((lane >> 4) << 3);
                u32 off = (u32)(r * NPP + c) * 2;
                ldsm4(ah[mt], sb + NP_AH + off);
                ldsm4(al[mt], sb + NP_AL + off);
            }
#pragma unroll
            for (int nt = 0; nt < 4; nt++) {
                int rn = n0w + nt * 8 + (lane & 7);
                int cn = kb + (((lane >> 3) & 1) << 3);
                u32 offb = (u32)(rn * NPP + cn) * 2;
                u32 bh[2], bl[2];
                ldsm2(bh, sb + NP_WH + offb);
                ldsm2(bl, sb + NP_WL + offb);
#pragma unroll
                for (int mt = 0; mt < 2; mt++) {
                    mma16816(acc[mt][nt], ah[mt], bh);
                    mma16816(acc[mt][nt], ah[mt], bl);
                    mma16816(acc[mt][nt], al[mt], bh);
                }
            }
        }
#pragma unroll
        for (int mt = 0; mt < 2; mt++)
#pragma unroll
            for (int nt = 0; nt < 4; nt++) {
                int rA = m0 + mt * 16 + (lane >> 2);
                int rB = rA + 8;
                int c = half * 128 + n0w + nt * 8 + 2 * (lane & 3);
                int nA = n0 + rA, nB = n0 + rB;
                if (nA < NN) {
                    g_pre[(u64)nA * 256 + c]     = acc[mt][nt][0];
                    g_pre[(u64)nA * 256 + c + 1] = acc[mt][nt][1];
                }
                if (nB < NN) {
                    g_pre[(u64)nB * 256 + c]     = acc[mt][nt][2];
                    g_pre[(u64)nB * 256 + c + 1] = acc[mt][nt][3];
                }
            }
        __syncthreads();
    }
}

// ---------------- attention scores (elementwise, decomposed) ----------------
__global__ void __launch_bounds__(256, 4)
k_attn_lite(const float* __restrict__ ea,
            const float* __restrict__ aw1l,
            const float* __restrict__ ab1,
            const float* __restrict__ aw2,
            const float* __restrict__ ab2p, int layer) {
    __shared__ float sea[64 * 17];
    __shared__ float sW[64 * 16];
    __shared__ float sb1[64], sv[64];
    __shared__ unsigned smax;
    int tid = threadIdx.x;
    int e0 = blockIdx.x * 64;
    if (tid == 0) smax = 0x007FFFFFu;
    {
        int r = tid >> 2, c = (tid & 3) * 4;
        float4 v = make_float4(0.f, 0.f, 0.f, 0.f);
        if (e0 + r < NE) v = *(const float4*)&ea[(u64)(e0 + r) * 16 + c];
        sea[r * 17 + c]     = v.x;
        sea[r * 17 + c + 1] = v.y;
        sea[r * 17 + c + 2] = v.z;
        sea[r * 17 + c + 3] = v.w;
    }
    {
        int r = tid >> 2, c = (tid & 3) * 4;
        float4 wv = *(const float4*)&aw1l[r * 272 + 256 + c];
        *(float4*)&sW[r * 16 + c] = wv;
    }
    if (tid < 64) { sb1[tid] = ab1[tid]; sv[tid] = aw2[tid]; }
    __syncthreads();

    int el = tid >> 2, p = tid & 3;
    int e = e0 + el;
    float score = 0.f;
    if (e < NE) {
        int s = g_src[e], d = g_dst[e];
        const float* ps = &g_pre[(u64)s * 256 + p * 16];
        const float* pd = &g_pre[(u64)d * 256 + 64 + p * 16];
        const float* er = &sea[el * 17];
#pragma unroll
        for (int c4 = 0; c4 < 4; c4++) {
            float4 a4 = *(const float4*)&ps[c4 * 4];
            float4 b4 = *(const float4*)&pd[c4 * 4];
            float av[4] = {a4.x, a4.y, a4.z, a4.w};
            float bv[4] = {b4.x, b4.y, b4.z, b4.w};
#pragma unroll
            for (int j = 0; j < 4; j++) {
                int c = p * 16 + c4 * 4 + j;
                float x = av[j] + bv[j] + sb1[c];
                const float* wr = &sW[c * 16];
#pragma unroll
                for (int k = 0; k < 16; k++) x += er[k] * wr[k];
                x = (x > 0.f) ? x : 0.2f * x;
                score += x * sv[c];
            }
        }
    }
    score += __shfl_xor_sync(0xffffffffu, score, 1);
    score += __shfl_xor_sync(0xffffffffu, score, 2);
    if (p == 0 && e < NE) {
        float sc = score + ab2p[0];
        g_scores[e] = sc;
        atomicMax(&smax, fenc(sc));
    }
    __syncthreads();
    if (tid == 0) atomicMax(&g_maxenc[layer], smax);
}

// ---------------- exp + scatter sum ----------------
__global__ void k_exp(int layer) {
    int i = blockIdx.x * blockDim.x + threadIdx.x;
    if (i >= NE) return;
    float m = fdec(g_maxenc[layer]);
    float es = expf(g_scores[i] - m);
    g_es[i] = es;
    atomicAdd(&g_sumexp[layer * NN + g_dst[i]], es);
}

// ---------------- message MLP (decomposed; stores weighted msg to g_msgbuf) ----------------
#define AP2 136
#define M_AH 0
#define M_AL 34816
#define M_WH 69632
#define M_WL 104448
#define M_STG 139264
#define M_META 206848
#define SMEM_MSG2 (206848 + 2560)

__global__ void __launch_bounds__(512, 1)
k_msg(const float* __restrict__ mb1,
      const float* __restrict__ mb2, int layer) {
    extern __shared__ char sm[];
    u16* sAh = (u16*)(sm + M_AH);
    u16* sAl = (u16*)(sm + M_AL);
    u16* sWh = (u16*)(sm + M_WH);
    u16* sWl = (u16*)(sm + M_WL);
    float* stage = (float*)(sm + M_STG);
    int*   ssrc = (int*)(sm + M_META);
    float* swt  = (float*)(sm + M_META + 1024);
    float* smb1 = (float*)(sm + M_META + 1536);
    float* smb2 = (float*)(sm + M_META + 2048);
    u32 sb = smem_u32(sm);

    int tid = threadIdx.x, lane = tid & 31, w = tid >> 5;
    int e0 = blockIdx.x * 128;
    if (tid < 128) {
        int e = e0 + tid;
        if (e < NE) {
            ssrc[tid] = g_src[e];
            int d = g_dst[e];
            swt[tid] = g_es[e] / (g_sumexp[layer * NN + d] + 1e-6f);
        } else {
            ssrc[tid] = 0; swt[tid] = 0.f;
        }
        smb1[tid] = mb1[tid];
        smb2[tid] = mb2[tid];
    }
    __syncthreads();

    for (int idx = tid; idx < 128 * 2; idx += 512) {
        int r = idx >> 1, c = (idx & 1) * 8;
        int e = min(e0 + r, NE - 1);
        *(uint4*)&sAh[r * AP2 + c] = *(const uint4*)&g_eah[(u64)e * 16 + c];
        *(uint4*)&sAl[r * AP2 + c] = *(const uint4*)&g_eal[(u64)e * 16 + c];
    }
    {
        const u16* wh = g_EWh + layer * 192 * 16 + 64 * 16;
        const u16* wl = g_EWl + layer * 192 * 16 + 64 * 16;
        for (int idx = tid; idx < 128 * 2; idx += 512) {
            int r = idx >> 1, c = (idx & 1) * 8;
            *(uint4*)&sWh[r * AP2 + c] = *(const uint4*)&wh[r * 16 + c];
            *(uint4*)&sWl[r * AP2 + c] = *(const uint4*)&wl[r * 16 + c];
        }
    }
    {
        int r = tid >> 2, q = tid & 3;
        const float* vp = &g_pre[(u64)ssrc[r] * 256 + 128 + q * 32];
        float* sp = &stage[r * 132 + q * 32];
#pragma unroll
        for (int j = 0; j < 8; j++)
            *(float4*)&sp[j * 4] = *(const float4*)&vp[j * 4];
    }
    __syncthreads();

    int m0 = (w & 3) * 32, n0 = (w >> 2) * 32;
    float acc[2][4][4];
#pragma unroll
    for (int i = 0; i < 2; i++)
#pragma unroll
        for (int j = 0; j < 4; j++)
#pragma unroll
            for (int k = 0; k < 4; k++) acc[i][j][k] = 0.f;
    {
        u32 ah[2][4], al[2][4];
#pragma unroll
        for (int mt = 0; mt < 2; mt++) {
            int r = m0 + mt * 16 + (lane & 15);
            int c = (lane >> 4) << 3;
            u32 off = (u32)(r * AP2 + c) * 2;
            ldsm4(ah[mt], sb + M_AH + off);
            ldsm4(al[mt], sb + M_AL + off);
        }
#pragma unroll
        for (int nt = 0; nt < 4; nt++) {
            int rn = n0 + nt * 8 + (lane & 7);
            int cn = ((lane >> 3) & 1) << 3;
            u32 offb = (u32)(rn * AP2 + cn) * 2;
            u32 bh[2], bl[2];
            ldsm2(bh, sb + M_WH + offb);
            ldsm2(bl, sb + M_WL + offb);
#pragma unroll
            for (int mt = 0; mt < 2; mt++) {
                mma16816(acc[mt][nt], ah[mt], bh);
                mma16816(acc[mt][nt], ah[mt], bl);
                mma16816(acc[mt][nt], al[mt], bh);
            }
        }
    }
    __syncthreads();

#pragma unroll
    for (int mt = 0; mt < 2; mt++)
#pragma unroll
        for (int nt = 0; nt < 4; nt++) {
            int rA = m0 + mt * 16 + (lane >> 2);
            int rB = rA + 8;
            int c = n0 + nt * 8 + 2 * (lane & 3);
            float b0 = smb1[c], b1 = smb1[c + 1];
            u32 h, l;
            split2(fmaxf(acc[mt][nt][0] + stage[rA * 132 + c]     + b0, 0.f),
                   fmaxf(acc[mt][nt][1] + stage[rA * 132 + c + 1] + b1, 0.f), h, l);
            *(u32*)&sAh[rA * AP2 + c] = h;
            *(u32*)&sAl[rA * AP2 + c] = l;
            split2(fmaxf(acc[mt][nt][2] + stage[rB * 132 + c]     + b0, 0.f),
                   fmaxf(acc[mt][nt][3] + stage[rB * 132 + c + 1] + b1, 0.f), h, l);
            *(u32*)&sAh[rB * AP2 + c] = h;
            *(u32*)&sAl[rB * AP2 + c] = l;
        }
    {
        const u16* wh = g_W2h + layer * 128 * 128;
        const u16* wl = g_W2l + layer * 128 * 128;
        for (int idx = tid; idx < 128 * 16; idx += 512) {
            int r = idx >> 4, c = (idx & 15) * 8;
            *(uint4*)&sWh[r * AP2 + c] = *(const uint4*)&wh[r * 128 + c];
            *(uint4*)&sWl[r * AP2 + c] = *(const uint4*)&wl[r * 128 + c];
        }
    }
    __syncthreads();

    float acc2[2][4][4];
#pragma unroll
    for (int i = 0; i < 2; i++)
#pragma unroll
        for (int j = 0; j < 4; j++)
#pragma unroll
            for (int k = 0; k < 4; k++) acc2[i][j][k] = 0.f;

    for (int ks = 0; ks < 8; ks++) {
        int kb = ks * 16;
        u32 ah[2][4], al[2][4];
#pragma unroll
        for (int mt = 0; mt < 2; mt++) {
            int r = m0 + mt * 16 + (lane & 15);
            int c = kb + ((lane >> 4) << 3);
            u32 off = (u32)(r * AP2 + c) * 2;
            ldsm4(ah[mt], sb + M_AH + off);
            ldsm4(al[mt], sb + M_AL + off);
        }
#pragma unroll
        for (int nt = 0; nt < 4; nt++) {
            int rn = n0 + nt * 8 + (lane & 7);
            int cn = kb + (((lane >> 3) & 1) << 3);
            u32 offb = (u32)(rn * AP2 + cn) * 2;
            u32 bh[2], bl[2];
            ldsm2(bh, sb + M_WH + offb);
            ldsm2(bl, sb + M_WL + offb);
#pragma unroll
            for (int mt = 0; mt < 2; mt++) {
                mma16816(acc2[mt][nt], ah[mt], bh);
                mma16816(acc2[mt][nt], ah[mt], bl);
                mma16816(acc2[mt][nt], al[mt], bh);
            }
        }
    }

    // epilogue2: weighted message -> coalesced store to g_msgbuf
#pragma unroll
    for (int mt = 0; mt < 2; mt++)
#pragma unroll
        for (int nt = 0; nt < 4; nt++) {
            int rA = m0 + mt * 16 + (lane >> 2);
            int rB = rA + 8;
            int c = n0 + nt * 8 + 2 * (lane & 3);
            float b0 = smb2[c], b1 = smb2[c + 1];
            float wA = swt[rA], wB = swt[rB];
            int eA = e0 + rA, eB = e0 + rB;
            if (eA < NE) {
                float2 v;
                v.x = (acc2[mt][nt][0] + b0) * wA;
                v.y = (acc2[mt][nt][1] + b1) * wA;
                *(float2*)&g_msgbuf[(u64)eA * 128 + c] = v;
            }
            if (eB < NE) {
                float2 v;
                v.x = (acc2[mt][nt][2] + b0) * wB;
                v.y = (acc2[mt][nt][3] + b1) * wB;
                *(float2*)&g_msgbuf[(u64)eB * 128 + c] = v;
            }
        }
}

// ---------------- node update: CSR gather + HMMA MLP + residual + LN ----------------
#define UPP 136
#define U_AH 0
#define U_AL 34816
#define U_WH 69632
#define U_WL 104448
#define SMEM_UPD 139264

__global__ void __launch_bounds__(512, 1)
k_update(const float* __restrict__ ub1,
         const float* __restrict__ ub2,
         const float* __restrict__ lng,
         const float* __restrict__ lnb, int layer) {
    extern __shared__ char sm[];
    u16* sAh = (u16*)(sm + U_AH);
    u16* sAl = (u16*)(sm + U_AL);
    u16* sWh = (u16*)(sm + U_WH);
    u16* sWl = (u16*)(sm + U_WL);
    float* stage = (float*)(sm + U_WH);  // reused after GEMM2
    u32 sb = smem_u32(sm);
    int tid = threadIdx.x, lane = tid & 31, w = tid >> 5;
    int n0 = blockIdx.x * 128;

    // phase 0: CSR gather of weighted messages (agg in registers)
    int ln = tid >> 2, q = tid & 3;
    int nn = n0 + ln;
    float agg[32];
#pragma unroll
    for (int t = 0; t < 32; t++) agg[t] = 0.f;
    if (nn < NN) {
        int j0 = g_row[nn], j1 = g_cur[nn];
        for (int j = j0; j < j1; j++) {
            int e = g_eord[j];
            const float* mp = &g_msgbuf[(u64)e * 128 + q * 32];
#pragma unroll
            for (int t = 0; t < 8; t++) {
                float4 v = *(const float4*)&mp[t * 4];
                agg[t * 4]     += v.x;
                agg[t * 4 + 1] += v.y;
                agg[t * 4 + 2] += v.z;
                agg[t * 4 + 3] += v.w;
            }
        }
    }

    // A1 = h split
    for (int idx = tid; idx < 128 * 16; idx += 512) {
        int r = idx >> 4, c = (idx & 15) * 8;
        int n = n0 + r;
        if (n < NN) {
            *(uint4*)&sAh[r * UPP + c] = *(const uint4*)&g_hh[n * HID + c];
            *(uint4*)&sAl[r * UPP + c] = *(const uint4*)&g_hl[n * HID + c];
        } else {
            uint4 z = make_uint4(0, 0, 0, 0);
            *(uint4*)&sAh[r * UPP + c] = z;
            *(uint4*)&sAl[r * UPP + c] = z;
        }
    }
    // Wa (uw1 in-half 0)
    {
        const u16* wh = g_U1h + layer * 32768;
        const u16* wl = g_U1l + layer * 32768;
        for (int idx = tid; idx < 128 * 16; idx += 512) {
            int r = idx >> 4, c = (idx & 15) * 8;
            *(uint4*)&sWh[r * UPP + c] = *(const uint4*)&wh[r * 128 + c];
            *(uint4*)&sWl[r * UPP + c] = *(const uint4*)&wl[r * 128 + c];
        }
    }
    __syncthreads();

    int m0 = (w & 3) * 32, nw0 = (w >> 2) * 32;
    float acc[2][4][4];
#pragma unroll
    for (int i = 0; i < 2; i++)
#pragma unroll
        for (int j = 0; j < 4; j++)
#pragma unroll
            for (int k = 0; k < 4; k++) acc[i][j][k] = 0.f;

    for (int ks = 0; ks < 8; ks++) {
        int kb = ks * 16;
        u32 ah[2][4], al[2][4];
#pragma unroll
        for (int mt = 0; mt < 2; mt++) {
            int r = m0 + mt * 16 + (lane & 15);
            int c = kb + ((lane >> 4) << 3);
            u32 off = (u32)(r * UPP + c) * 2;
            ldsm4(ah[mt], sb + U_AH + off);
            ldsm4(al[mt], sb + U_AL + off);
        }
#pragma unroll
        for (int nt = 0; nt < 4; nt++) {
            int rn = nw0 + nt * 8 + (lane & 7);
            int cn = kb + (((lane >> 3) & 1) << 3);
            u32 offb = (u32)(rn * UPP + cn) * 2;
            u32 bh[2], bl[2];
            ldsm2(bh, sb + U_WH + offb);
            ldsm2(bl, sb + U_WL + offb);
#pragma unroll
            for (int mt = 0; mt < 2; mt++) {
                mma16816(acc[mt][nt], ah[mt], bh);
                mma16816(acc[mt][nt], ah[mt], bl);
                mma16816(acc[mt][nt], al[mt], bh);
            }
        }
    }
    __syncthreads();

    // A2 = agg split; Wb (uw1 in-half 1)
    {
#pragma unroll
        for (int t = 0; t < 16; t++) {
            u32 h, l;
            split2(agg[2 * t], agg[2 * t + 1], h, l);
            *(u32*)&sAh[ln * UPP + q * 32 + 2 * t] = h;
            *(u32*)&sAl[ln * UPP + q * 32 + 2 * t] = l;
        }
        const u16* wh = g_U1h + layer * 32768 + 16384;
        const u16* wl = g_U1l + layer * 32768 + 16384;
        for (int idx = tid; idx < 128 * 16; idx += 512) {
            int r = idx >> 4, c = (idx & 15) * 8;
            *(uint4*)&sWh[r * UPP + c] = *(const uint4*)&wh[r * 128 + c];
            *(uint4*)&sWl[r * UPP + c] = *(const uint4*)&wl[r * 128 + c];
        }
    }
    __syncthreads();

    for (int ks = 0; ks < 8; ks++) {
        int kb = ks * 16;
        u32 ah[2][4], al[2][4];
#pragma unroll
        for (int mt = 0; mt < 2; mt++) {
            int r = m0 + mt * 16 + (lane & 15);
            int c = kb + ((lane >> 4) << 3);
            u32 off = (u32)(r * UPP + c) * 2;
            ldsm4(ah[mt], sb + U_AH + off);
            ldsm4(al[mt], sb + U_AL + off);
        }
#pragma unroll
        for (int nt = 0; nt < 4; nt++) {
            int rn = nw0 + nt * 8 + (lane & 7);
            int cn = kb + (((lane >> 3) & 1) << 3);
            u32 offb = (u32)(rn * UPP + cn) * 2;
            u32 bh[2], bl[2];
            ldsm2(bh, sb + U_WH + offb);
            ldsm2(bl, sb + U_WL + offb);
#pragma unroll
            for (int mt = 0; mt < 2; mt++) {
                mma16816(acc[mt][nt], ah[mt], bh);
                mma16816(acc[mt][nt], ah[mt], bl);
                mma16816(acc[mt][nt], al[mt], bh);
            }
        }
    }
    __syncthreads();

    // relu(acc + ub1) -> re-split into A tiles
#pragma unroll
    for (int mt = 0; mt < 2; mt++)
#pragma unroll
        for (int nt = 0; nt < 4; nt++) {
            int rA = m0 + mt * 16 + (lane >> 2);
            int rB = rA + 8;
            int c = nw0 + nt * 8 + 2 * (lane & 3);
            float b0 = ub1[c], b1 = ub1[c + 1];
            u32 h, l;
            split2(fmaxf(acc[mt][nt][0] + b0, 0.f),
                   fmaxf(acc[mt][nt][1] + b1, 0.f), h, l);
            *(u32*)&sAh[rA * UPP + c] = h;
            *(u32*)&sAl[rA * UPP + c] = l;
            split2(fmaxf(acc[mt][nt][2] + b0, 0.f),
                   fmaxf(acc[mt][nt][3] + b1, 0.f), h, l);
            *(u32*)&sAh[rB * UPP + c] = h;
            *(u32*)&sAl[rB * UPP + c] = l;
        }
    // W2 = uw2 split
    {
        const u16* wh = g_U2h + layer * 128 * 128;
        const u16* wl = g_U2l + layer * 128 * 128;
        for (int idx = tid; idx < 128 * 16; idx += 512) {
            int r = idx >> 4, c = (idx & 15) * 8;
            *(uint4*)&sWh[r * UPP + c] = *(const uint4*)&wh[r * 128 + c];
            *(uint4*)&sWl[r * UPP + c] = *(const uint4*)&wl[r * 128 + c];
        }
    }
    __syncthreads();

    float acc2[2][4][4];
#pragma unroll
    for (int i = 0; i < 2; i++)
#pragma unroll
        for (int j = 0; j < 4; j++)
#pragma unroll
            for (int k = 0; k < 4; k++) acc2[i][j][k] = 0.f;

    for (int ks = 0; ks < 8; ks++) {
        int kb = ks * 16;
        u32 ah[2][4], al[2][4];
#pragma unroll
        for (int mt = 0; mt < 2; mt++) {
            int r = m0 + mt * 16 + (lane & 15);
            int c = kb + ((lane >> 4) << 3);
            u32 off = (u32)(r * UPP + c) * 2;
            ldsm4(ah[mt], sb + U_AH + off);
            ldsm4(al[mt], sb + U_AL + off);
        }
#pragma unroll
        for (int nt = 0; nt < 4; nt++) {
            int rn = nw0 + nt * 8 + (lane & 7);
            int cn = kb + (((lane >> 3) & 1) << 3);
            u32 offb = (u32)(rn * UPP + cn) * 2;
            u32 bh[2], bl[2];
            ldsm2(bh, sb + U_WH + offb);
            ldsm2(bl, sb + U_WL + offb);
#pragma unroll
            for (int mt = 0; mt < 2; mt++) {
                mma16816(acc2[mt][nt], ah[mt], bh);
                mma16816(acc2[mt][nt], ah[mt], bl);
                mma16816(acc2[mt][nt], al[mt], bh);
            }
        }
    }
    __syncthreads();  // W tiles dead -> stage

#pragma unroll
    for (int mt = 0; mt < 2; mt++)
#pragma unroll
        for (int nt = 0; nt < 4; nt++) {
            int rA = m0 + mt * 16 + (lane >> 2);
            int rB = rA + 8;
            int c = nw0 + nt * 8 + 2 * (lane & 3);
            stage[rA * 132 + c]     = acc2[mt][nt][0];
            stage[rA * 132 + c + 1] = acc2[mt][nt][1];
            stage[rB * 132 + c]     = acc2[mt][nt][2];
            stage[rB * 132 + c + 1] = acc2[mt][nt][3];
        }
    __syncthreads();

    // LN: 4 threads per row (ln, q)
    {
        int c0 = q * 32;
        float v[32];
        float s = 0.f, sq = 0.f;
        if (nn < NN) {
#pragma unroll
            for (int t4 = 0; t4 < 8; t4++) {
                float4 hres = *(const float4*)&g_h[nn * HID + c0 + t4 * 4];
                float hr[4] = {hres.x, hres.y, hres.z, hres.w};
#pragma unroll
                for (int j = 0; j < 4; j++) {
                    int t = t4 * 4 + j;
                    float val = stage[ln * 132 + c0 + t] + ub2[c0 + t] + hr[j];
                    val = fmaxf(val, 0.f);
                    v[t] = val;
                    s += val;
                    sq += val * val;
                }
            }
        } else {
#pragma unroll
            for (int t = 0; t < 32; t++) v[t] = 0.f;
        }
        s  += __shfl_xor_sync(0xffffffffu, s, 1);
        s  += __shfl_xor_sync(0xffffffffu, s, 2);
        sq += __shfl_xor_sync(0xffffffffu, sq, 1);
        sq += __shfl_xor_sync(0xffffffffu, sq, 2);
        float mu = s * (1.f / 128.f);
        float var = sq * (1.f / 128.f) - mu * mu;
        float rs = rsqrtf(var + 1e-5f);
        if (nn < NN) {
#pragma unroll
            for (int t4 = 0; t4 < 8; t4++) {
                float o[4];
#pragma unroll
                for (int j = 0; j < 4; j++) {
                    int t = t4 * 4 + j;
                    o[j] = (v[t] - mu) * rs * lng[c0 + t] + lnb[c0 + t];
                }
                *(float4*)&g_h[nn * HID + c0 + t4 * 4] =
                    make_float4(o[0], o[1], o[2], o[3]);
                u32 h0, l0, h1, l1;
                split2(o[0], o[1], h0, l0);
                split2(o[2], o[3], h1, l1);
                *(u32*)&g_hh[nn * HID + c0 + t4 * 4]     = h0;
                *(u32*)&g_hh[nn * HID + c0 + t4 * 4 + 2] = h1;
                *(u32*)&g_hl[nn * HID + c0 + t4 * 4]     = l0;
                *(u32*)&g_hl[nn * HID + c0 + t4 * 4 + 2] = l1;
            }
        }
    }
}

// ---------------- final readout ----------------
__global__ void k_final(const float* __restrict__ gc,
                        const float* __restrict__ qw1,
                        const float* __restrict__ qb1,
                        const float* __restrict__ qw2,
                        const float* __restrict__ qb2p,
                        float* __restrict__ out) {
    __shared__ float sA[32 * 33];
    __shared__ float sW[128 * 33];
    __shared__ float sctx[64];
    __shared__ float sout[32];
    int tid = threadIdx.x;
    int n0 = blockIdx.x * 32;
    if (tid < 64) sctx[tid] = gc[tid];
    if (tid < 32) sout[tid] = qb2p[0];
    __syncthreads();
    int tc = tid & 31, trg = tid >> 5;
    float acc[4][4] = {};
    for (int kb = 0; kb < 192; kb += 32) {
        for (int idx = tid; idx < 32 * 32; idx += NT) {
            int r = idx >> 5, kk = idx & 31;
            int n = n0 + r;
            int kg = kb + kk;
            float v = 0.f;
            if (n < NN) v = (kg < 128) ? g_h[n * HID + kg] : sctx[kg - 128];
            sA[r * 33 + kk] = v;
        }
        for (int idx = tid; idx < 128 * 32; idx += NT) {
            int o = idx >> 5, kk = idx & 31;
            sW[o * 33 + kk] = qw1[o * 192 + kb + kk];
        }
        __syncthreads();
#pragma unroll 8
        for (int k = 0; k < 32; k++) {
            float a[4], w[4];
#pragma unroll
            for (int i = 0; i < 4; i++) a[i] = sA[(trg * 4 + i) * 33 + k];
#pragma unroll
            for (int j = 0; j < 4; j++) w[j] = sW[(tc + 32 * j) * 33 + k];
#pragma unroll
            for (int i = 0; i < 4; i++)
#pragma unroll
                for (int j = 0; j < 4; j++) acc[i][j] += a[i] * w[j];
        }
        __syncthreads();
    }
    float p[4] = {0.f, 0.f, 0.f, 0.f};
#pragma unroll
    for (int j = 0; j < 4; j++) {
        int c = tc + 32 * j;
        float b = qb1[c], w2 = qw2[c];
#pragma unroll
        for (int i = 0; i < 4; i++) {
            float v = fmaxf(acc[i][j] + b, 0.f);
            p[i] += v * w2;
        }
    }
#pragma unroll
    for (int i = 0; i < 4; i++) atomicAdd(&sout[trg * 4 + i], p[i]);
    __syncthreads();
    if (tid < 32) {
        int n = n0 + tid;
        if (n < NN) out[n] = sout[tid];
    }
}

// ---------------- launch ----------------
extern "C" void kernel_launch(void* const* d_in, const int* in_sizes, int n_in,
                              void* d_out, int out_size) {
    const float* x    = (const float*)d_in[0];
    const void*  eidx = d_in[1];
    const float* ea   = (const float*)d_in[2];
    const float* gc   = (const float*)d_in[3];
    const float* npw  = (const float*)d_in[4];
    const float* npb  = (const float*)d_in[5];
    const float* mw1  = (const float*)d_in[6];
    const float* mb1  = (const float*)d_in[7];
    const float* mw2  = (const float*)d_in[8];
    const float* mb2  = (const float*)d_in[9];
    const float* aw1  = (const float*)d_in[10];
    const float* ab1  = (const float*)d_in[11];
    const float* aw2  = (const float*)d_in[12];
    const float* ab2  = (const float*)d_in[13];
    const float* uw1  = (const float*)d_in[14];
    const float* ub1  = (const float*)d_in[15];
    const float* uw2  = (const float*)d_in[16];
    const float* ub2  = (const float*)d_in[17];
    const float* lng  = (const float*)d_in[18];
    const float* lnb  = (const float*)d_in[19];
    const float* qw1  = (const float*)d_in[20];
    const float* qb1  = (const float*)d_in[21];
    const float* qw2  = (const float*)d_in[22];
    const float* qb2  = (const float*)d_in[23];
    float* out = (float*)d_out;

    cudaFuncSetAttribute(k_msg, cudaFuncAttributeMaxDynamicSharedMemorySize, SMEM_MSG2);
    cudaFuncSetAttribute(k_node_pre, cudaFuncAttributeMaxDynamicSharedMemorySize, SMEM_NP);
    cudaFuncSetAttribute(k_update, cudaFuncAttributeMaxDynamicSharedMemorySize, SMEM_UPD);

    int prep_tot = 3 * (256 * 128 + 192 * 16 + 128 * 128 + 256 * 128 + 128 * 128);
    k_prep<<<(prep_tot + 255) / 256, 256>>>(mw1, mw2, aw1, uw1, uw2);
    k_detect<<<1, NT>>>((const unsigned*)eidx);
    k_convert<<<(NE + NT - 1) / NT, NT>>>(eidx, ea);
    k_hist<<<(NE + 255) / 256, 256>>>();
    k_scan<<<1, 1024>>>();
    k_scatter<<<(NE + 255) / 256, 256>>>();
    k_nodeproj<<<(NN + 31) / 32, NT>>>(x, npw, npb);

    int ngrid = (NN + 127) / 128;
    for (int l = 0; l < 3; l++) {
        k_node_pre<<<ngrid, 512, SMEM_NP>>>(l);
        k_attn_lite<<<(NE + 63) / 64, 256>>>(ea, aw1 + l * 64 * 272, ab1 + l * 64,
                                             aw2 + l * 64, ab2 + l, l);
        k_exp<<<(NE + NT - 1) / NT, NT>>>(l);
        k_msg<<<(NE + 127) / 128, 512, SMEM_MSG2>>>(mb1 + l * 128, mb2 + l * 128, l);
        k_update<<<ngrid, 512, SMEM_UPD>>>(ub1 + l * 128, ub2 + l * 128,
                                           lng + l * 128, lnb + l * 128, l);
    }
    k_final<<<(NN + 31) / 32, NT>>>(gc, qw1, qb1, qw2, qb2, out);
}

// round 9
// speedup vs baseline: 1.4286x; 1.0830x over previous
#include <cuda_runtime.h>
#include <cuda_bf16.h>

#define NN 50000
#define NE 600000
#define HID 128
#define NT 256

typedef unsigned long long u64;
typedef unsigned int u32;
typedef unsigned short u16;

// ---------------- scratch ----------------
__device__ float g_h[NN * HID];
__device__ float g_pre[NN * 256];      // [0:64)=u_s, [64:128)=u_d, [128:256)=vh
__device__ float g_msgbuf[(u64)NE * 128];
__device__ float g_sumexp[3 * NN];
__device__ float g_scores[NE];
__device__ float g_es[NE];
__device__ int   g_src[NE];
__device__ int   g_dst[NE];
__device__ unsigned g_maxenc[3];
__device__ int   g_is64;
// CSR by dst
__device__ int g_cnt[NN];
__device__ int g_row[NN];
__device__ int g_cur[NN];
__device__ int g_eord[NE];
// bf16 hi/lo splits
__device__ __align__(16) u16 g_hh[NN * HID];
__device__ __align__(16) u16 g_hl[NN * HID];
__device__ __align__(16) u16 g_eah[NE * 16];
__device__ __align__(16) u16 g_eal[NE * 16];
__device__ __align__(16) u16 g_NPh[3 * 256 * 128];
__device__ __align__(16) u16 g_NPl[3 * 256 * 128];
__device__ __align__(16) u16 g_EWh[3 * 192 * 16];
__device__ __align__(16) u16 g_EWl[3 * 192 * 16];
__device__ __align__(16) u16 g_W2h[3 * 128 * 128];
__device__ __align__(16) u16 g_W2l[3 * 128 * 128];
__device__ __align__(16) u16 g_U1h[3 * 256 * 128];
__device__ __align__(16) u16 g_U1l[3 * 256 * 128];
__device__ __align__(16) u16 g_U2h[3 * 128 * 128];
__device__ __align__(16) u16 g_U2l[3 * 128 * 128];

__device__ __forceinline__ unsigned fenc(float f) {
    unsigned u = __float_as_uint(f);
    return (u & 0x80000000u) ? ~u : (u | 0x80000000u);
}
__device__ __forceinline__ float fdec(unsigned u) {
    return (u & 0x80000000u) ? __uint_as_float(u & 0x7fffffffu)
                             : __uint_as_float(~u);
}

// ---------------- bf16 split helpers ----------------
__device__ __forceinline__ void split_bf16(float v, u16 &h, u16 &l) {
    __nv_bfloat16 bh = __float2bfloat16(v);
    __nv_bfloat16 bl = __float2bfloat16(v - __bfloat162float(bh));
    h = __bfloat16_as_ushort(bh);
    l = __bfloat16_as_ushort(bl);
}
__device__ __forceinline__ void split2(float a, float b, u32 &h, u32 &l) {
    u16 h0, l0, h1, l1;
    split_bf16(a, h0, l0);
    split_bf16(b, h1, l1);
    h = (u32)h0 | ((u32)h1 << 16);
    l = (u32)l0 | ((u32)l1 << 16);
}

// ---------------- HMMA helpers ----------------
__device__ __forceinline__ u32 smem_u32(const void* p) {
    u32 a;
    asm("{ .reg .u64 t; cvta.to.shared.u64 t, %1; cvt.u32.u64 %0, t; }"
        : "=r"(a) : "l"(p));
    return a;
}
__device__ __forceinline__ void ldsm4(u32* r, u32 addr) {
    asm volatile("ldmatrix.sync.aligned.m8n8.x4.shared.b16 {%0,%1,%2,%3}, [%4];"
        : "=r"(r[0]), "=r"(r[1]), "=r"(r[2]), "=r"(r[3]) : "r"(addr));
}
__device__ __forceinline__ void ldsm2(u32* r, u32 addr) {
    asm volatile("ldmatrix.sync.aligned.m8n8.x2.shared.b16 {%0,%1}, [%2];"
        : "=r"(r[0]), "=r"(r[1]) : "r"(addr));
}
__device__ __forceinline__ void mma16816(float* d, const u32* a, const u32* b) {
    asm volatile("mma.sync.aligned.m16n8k16.row.col.f32.bf16.bf16.f32 "
        "{%0,%1,%2,%3}, {%4,%5,%6,%7}, {%8,%9}, {%0,%1,%2,%3};"
        : "+f"(d[0]), "+f"(d[1]), "+f"(d[2]), "+f"(d[3])
        : "r"(a[0]), "r"(a[1]), "r"(a[2]), "r"(a[3]), "r"(b[0]), "r"(b[1]));
}

// ---------------- weight preconversion ----------------
__global__ void k_prep(const float* __restrict__ mw1, const float* __restrict__ mw2,
                       const float* __restrict__ aw1, const float* __restrict__ uw1,
                       const float* __restrict__ uw2) {
    int idx = blockIdx.x * blockDim.x + threadIdx.x;
    const int NP = 3 * 256 * 128, EW = 3 * 192 * 16, W2 = 3 * 128 * 128;
    const int U1 = 3 * 256 * 128, U2 = 3 * 128 * 128;
    u16 h, l;
    if (idx < NP) {
        int lyr = idx / (256 * 128);
        int rem = idx % (256 * 128);
        int n = rem / 128, k = rem % 128;
        float v;
        if (n < 64)        v = aw1[lyr * 64 * 272 + n * 272 + k];
        else if (n < 128)  v = aw1[lyr * 64 * 272 + (n - 64) * 272 + 128 + k];
        else               v = mw1[lyr * 128 * 144 + (n - 128) * 144 + k];
        split_bf16(v, h, l);
        g_NPh[idx] = h; g_NPl[idx] = l;
    } else if (idx < NP + EW) {
        int i = idx - NP;
        int lyr = i / (192 * 16);
        int rem = i % (192 * 16);
        int n = rem / 16, k = rem % 16;
        float v = (n < 64) ? aw1[lyr * 64 * 272 + n * 272 + 256 + k]
                           : mw1[lyr * 128 * 144 + (n - 64) * 144 + 128 + k];
        split_bf16(v, h, l);
        g_EWh[i] = h; g_EWl[i] = l;
    } else if (idx < NP + EW + W2) {
        int i = idx - NP - EW;
        split_bf16(mw2[i], h, l);
        g_W2h[i] = h; g_W2l[i] = l;
    } else if (idx < NP + EW + W2 + U1) {
        int i = idx - NP - EW - W2;
        int lyr = i / 32768;
        int rem = i % 32768;
        int half = rem / 16384;
        int r2 = rem % 16384;
        int n = r2 / 128, k = r2 % 128;
        split_bf16(uw1[lyr * 32768 + n * 256 + half * 128 + k], h, l);
        g_U1h[i] = h; g_U1l[i] = l;
    } else if (idx < NP + EW + W2 + U1 + U2) {
        int i = idx - NP - EW - W2 - U1;
        split_bf16(uw2[i], h, l);
        g_U2h[i] = h; g_U2l[i] = l;
    }
}

// ---------------- detect + convert + ea split + zero ----------------
__global__ void k_detect(const unsigned* __restrict__ raw) {
    __shared__ int nz;
    if (threadIdx.x == 0) nz = 0;
    __syncthreads();
    for (int i = threadIdx.x; i < 2048; i += NT)
        if (raw[2 * i + 1] != 0u) atomicOr(&nz, 1);
    __syncthreads();
    if (threadIdx.x == 0) g_is64 = (nz == 0) ? 1 : 0;
}

__global__ void k_convert(const void* __restrict__ eidx, const float* __restrict__ ea) {
    int i = blockIdx.x * blockDim.x + threadIdx.x;
    long long stride = (long long)gridDim.x * blockDim.x;
    if (i < NE) {
        if (g_is64) {
            const long long* p = (const long long*)eidx;
            g_src[i] = (int)p[i];
            g_dst[i] = (int)p[NE + i];
        } else {
            const int* p = (const int*)eidx;
            g_src[i] = p[i];
            g_dst[i] = p[NE + i];
        }
    }
    for (long long j = i; j < (long long)NE * 16; j += stride) {
        u16 h, l;
        split_bf16(ea[j], h, l);
        g_eah[j] = h; g_eal[j] = l;
    }
    for (long long j = i; j < 3 * NN; j += stride) g_sumexp[j] = 0.f;
    for (long long j = i; j < NN; j += stride) g_cnt[j] = 0;
    if (i == 0) {
        g_maxenc[0] = 0x007FFFFFu;
        g_maxenc[1] = 0x007FFFFFu;
        g_maxenc[2] = 0x007FFFFFu;
    }
}

// ---------------- counting sort by dst (CSR) ----------------
__global__ void k_hist() {
    int i = blockIdx.x * blockDim.x + threadIdx.x;
    if (i < NE) atomicAdd(&g_cnt[g_dst[i]], 1);
}

__global__ void k_scan() {
    __shared__ int warpsum[32];
    __shared__ int scarry;
    int tid = threadIdx.x, lane = tid & 31, wid = tid >> 5;
    if (tid == 0) scarry = 0;
    __syncthreads();
    for (int base = 0; base < NN; base += 1024) {
        int i = base + tid;
        int v = (i < NN) ? g_cnt[i] : 0;
        int s = v;
#pragma unroll
        for (int off = 1; off < 32; off <<= 1) {
            int t = __shfl_up_sync(0xffffffffu, s, off);
            if (lane >= off) s += t;
        }
        if (lane == 31) warpsum[wid] = s;
        __syncthreads();
        if (wid == 0) {
            int ws = warpsum[lane];
#pragma unroll
            for (int off = 1; off < 32; off <<= 1) {
                int t = __shfl_up_sync(0xffffffffu, ws, off);
                if (lane >= off) ws += t;
            }
            warpsum[lane] = ws;
        }
        __syncthreads();
        int incl = s + (wid > 0 ? warpsum[wid - 1] : 0) + scarry;
        if (i < NN) { g_row[i] = incl - v; g_cur[i] = incl - v; }
        __syncthreads();
        if (tid == 1023) scarry = incl;
        __syncthreads();
    }
}

__global__ void k_scatter() {
    int i = blockIdx.x * blockDim.x + threadIdx.x;
    if (i < NE) {
        int pos = atomicAdd(&g_cur[g_dst[i]], 1);
        g_eord[pos] = i;
    }
}

// ---------------- node projection (+ split store) ----------------
__global__ void k_nodeproj(const float* __restrict__ x,
                           const float* __restrict__ W,
                           const float* __restrict__ b) {
    __shared__ float sA[32 * 33];
    __shared__ float sW[128 * 33];
    int tid = threadIdx.x;
    int n0 = blockIdx.x * 32;
    for (int idx = tid; idx < 32 * 32; idx += NT) {
        int r = idx >> 5, k = idx & 31;
        int n = n0 + r;
        sA[r * 33 + k] = (n < NN) ? x[n * 32 + k] : 0.f;
    }
    for (int idx = tid; idx < 128 * 32; idx += NT) {
        int o = idx >> 5, k = idx & 31;
        sW[o * 33 + k] = W[o * 32 + k];
    }
    __syncthreads();
    int tc = tid & 31, trg = tid >> 5;
    float acc[4][4] = {};
#pragma unroll 8
    for (int k = 0; k < 32; k++) {
        float a[4], w[4];
#pragma unroll
        for (int i = 0; i < 4; i++) a[i] = sA[(trg * 4 + i) * 33 + k];
#pragma unroll
        for (int j = 0; j < 4; j++) w[j] = sW[(tc + 32 * j) * 33 + k];
#pragma unroll
        for (int i = 0; i < 4; i++)
#pragma unroll
            for (int j = 0; j < 4; j++) acc[i][j] += a[i] * w[j];
    }
#pragma unroll
    for (int i = 0; i < 4; i++) {
        int n = n0 + trg * 4 + i;
        if (n < NN)
#pragma unroll
            for (int j = 0; j < 4; j++) {
                int c = tc + 32 * j;
                float v = fmaxf(acc[i][j] + b[c], 0.f);
                g_h[n * HID + c] = v;
                u16 h, l;
                split_bf16(v, h, l);
                g_hh[n * HID + c] = h;
                g_hl[n * HID + c] = l;
            }
    }
}

// ---------------- node precompute GEMM: M=64 tiles, 2 CTAs/SM ----------------
#define NPP 136
#define NP_AH 0
#define NP_AL 17408
#define NP_WH 34816
#define NP_WL 69632
#define SMEM_NP 104448

__global__ void __launch_bounds__(256, 2)
k_node_pre(int layer) {
    extern __shared__ char sm[];
    u16* sAh = (u16*)(sm + NP_AH);
    u16* sAl = (u16*)(sm + NP_AL);
    u16* sWh = (u16*)(sm + NP_WH);
    u16* sWl = (u16*)(sm + NP_WL);
    u32 sb = smem_u32(sm);
    int tid = threadIdx.x, lane = tid & 31, w = tid >> 5;
    int n0 = blockIdx.x * 64;

    for (int idx = tid; idx < 64 * 16; idx += 256) {
        int r = idx >> 4, c = (idx & 15) * 8;
        int n = n0 + r;
        if (n < NN) {
            *(uint4*)&sAh[r * NPP + c] = *(const uint4*)&g_hh[n * HID + c];
            *(uint4*)&sAl[r * NPP + c] = *(const uint4*)&g_hl[n * HID + c];
        } else {
            uint4 z = make_uint4(0, 0, 0, 0);
            *(uint4*)&sAh[r * NPP + c] = z;
            *(uint4*)&sAl[r * NPP + c] = z;
        }
    }

    int m0 = (w & 1) * 32, n0w = (w >> 1) * 32;
    for (int half = 0; half < 2; half++) {
        const u16* wh = g_NPh + layer * 256 * 128 + half * 128 * 128;
        const u16* wl = g_NPl + layer * 256 * 128 + half * 128 * 128;
        for (int idx = tid; idx < 128 * 16; idx += 256) {
            int r = idx >> 4, c = (idx & 15) * 8;
            *(uint4*)&sWh[r * NPP + c] = *(const uint4*)&wh[r * 128 + c];
            *(uint4*)&sWl[r * NPP + c] = *(const uint4*)&wl[r * 128 + c];
        }
        __syncthreads();
        float acc[2][4][4];
#pragma unroll
        for (int i = 0; i < 2; i++)
#pragma unroll
            for (int j = 0; j < 4; j++)
#pragma unroll
                for (int k = 0; k < 4; k++) acc[i][j][k] = 0.f;
        for (int ks = 0; ks < 8; ks++) {
            int kb = ks * 16;
            u32 ah[2][4], al[2][4];
#pragma unroll
            for (int mt = 0; mt < 2; mt++) {
                int r = m0 + mt * 16 + (lane & 15);
                int c = kb + ((lane >> 4) << 3);
                u32 off = (u32)(r * NPP + c) * 2;
                ldsm4(ah[mt], sb + NP_AH + off);
                ldsm4(al[mt], sb + NP_AL + off);
            }
#pragma unroll
            for (int nt = 0; nt < 4; nt++) {
                int rn = n0w + nt * 8 + (lane & 7);
                int cn = kb + (((lane >> 3) & 1) << 3);
                u32 offb = (u32)(rn * NPP + cn) * 2;
                u32 bh[2], bl[2];
                ldsm2(bh, sb + NP_WH + offb);
                ldsm2(bl, sb + NP_WL + offb);
#pragma unroll
                for (int mt = 0; mt < 2; mt++) {
                    mma16816(acc[mt][nt], ah[mt], bh);
                    mma16816(acc[mt][nt], ah[mt], bl);
                    mma16816(acc[mt][nt], al[mt], bh);
                }
            }
        }
#pragma unroll
        for (int mt = 0; mt < 2; mt++)
#pragma unroll
            for (int nt = 0; nt < 4; nt++) {
                int rA = m0 + mt * 16 + (lane >> 2);
                int rB = rA + 8;
                int c = half * 128 + n0w + nt * 8 + 2 * (lane & 3);
                int nA = n0 + rA, nB = n0 + rB;
                if (nA < NN) {
                    g_pre[(u64)nA * 256 + c]     = acc[mt][nt][0];
                    g_pre[(u64)nA * 256 + c + 1] = acc[mt][nt][1];
                }
                if (nB < NN) {
                    g_pre[(u64)nB * 256 + c]     = acc[mt][nt][2];
                    g_pre[(u64)nB * 256 + c + 1] = acc[mt][nt][3];
                }
            }
        __syncthreads();
    }
}

// ---------------- attention scores (elementwise, decomposed) ----------------
__global__ void __launch_bounds__(256, 4)
k_attn_lite(const float* __restrict__ ea,
            const float* __restrict__ aw1l,
            const float* __restrict__ ab1,
            const float* __restrict__ aw2,
            const float* __restrict__ ab2p, int layer) {
    __shared__ float sea[64 * 17];
    __shared__ float sW[64 * 16];
    __shared__ float sb1[64], sv[64];
    __shared__ unsigned smax;
    int tid = threadIdx.x;
    int e0 = blockIdx.x * 64;
    if (tid == 0) smax = 0x007FFFFFu;
    {
        int r = tid >> 2, c = (tid & 3) * 4;
        float4 v = make_float4(0.f, 0.f, 0.f, 0.f);
        if (e0 + r < NE) v = *(const float4*)&ea[(u64)(e0 + r) * 16 + c];
        sea[r * 17 + c]     = v.x;
        sea[r * 17 + c + 1] = v.y;
        sea[r * 17 + c + 2] = v.z;
        sea[r * 17 + c + 3] = v.w;
    }
    {
        int r = tid >> 2, c = (tid & 3) * 4;
        float4 wv = *(const float4*)&aw1l[r * 272 + 256 + c];
        *(float4*)&sW[r * 16 + c] = wv;
    }
    if (tid < 64) { sb1[tid] = ab1[tid]; sv[tid] = aw2[tid]; }
    __syncthreads();

    int el = tid >> 2, p = tid & 3;
    int e = e0 + el;
    float score = 0.f;
    if (e < NE) {
        int s = g_src[e], d = g_dst[e];
        const float* ps = &g_pre[(u64)s * 256 + p * 16];
        const float* pd = &g_pre[(u64)d * 256 + 64 + p * 16];
        const float* er = &sea[el * 17];
#pragma unroll
        for (int c4 = 0; c4 < 4; c4++) {
            float4 a4 = *(const float4*)&ps[c4 * 4];
            float4 b4 = *(const float4*)&pd[c4 * 4];
            float av[4] = {a4.x, a4.y, a4.z, a4.w};
            float bv[4] = {b4.x, b4.y, b4.z, b4.w};
#pragma unroll
            for (int j = 0; j < 4; j++) {
                int c = p * 16 + c4 * 4 + j;
                float x = av[j] + bv[j] + sb1[c];
                const float* wr = &sW[c * 16];
#pragma unroll
                for (int k = 0; k < 16; k++) x += er[k] * wr[k];
                x = (x > 0.f) ? x : 0.2f * x;
                score += x * sv[c];
            }
        }
    }
    score += __shfl_xor_sync(0xffffffffu, score, 1);
    score += __shfl_xor_sync(0xffffffffu, score, 2);
    if (p == 0 && e < NE) {
        float sc = score + ab2p[0];
        g_scores[e] = sc;
        atomicMax(&smax, fenc(sc));
    }
    __syncthreads();
    if (tid == 0) atomicMax(&g_maxenc[layer], smax);
}

// ---------------- exp + scatter sum ----------------
__global__ void k_exp(int layer) {
    int i = blockIdx.x * blockDim.x + threadIdx.x;
    if (i >= NE) return;
    float m = fdec(g_maxenc[layer]);
    float es = expf(g_scores[i] - m);
    g_es[i] = es;
    atomicAdd(&g_sumexp[layer * NN + g_dst[i]], es);
}

// ---------------- message MLP: M=64 tiles, 2 CTAs/SM ----------------
#define AP2 136
#define M_AH 0
#define M_AL 17408
#define M_WH 34816
#define M_WL 69632
#define M_META 104448
#define SMEM_MSG2 (104448 + 2048)

__global__ void __launch_bounds__(256, 2)
k_msg(const float* __restrict__ mb1,
      const float* __restrict__ mb2, int layer) {
    extern __shared__ char sm[];
    u16* sAh = (u16*)(sm + M_AH);
    u16* sAl = (u16*)(sm + M_AL);
    u16* sWh = (u16*)(sm + M_WH);
    u16* sWl = (u16*)(sm + M_WL);
    int*   ssrc = (int*)(sm + M_META);
    float* swt  = (float*)(sm + M_META + 256);
    float* smb1 = (float*)(sm + M_META + 512);
    float* smb2 = (float*)(sm + M_META + 1024);
    u32 sb = smem_u32(sm);

    int tid = threadIdx.x, lane = tid & 31, w = tid >> 5;
    int e0 = blockIdx.x * 64;
    if (tid < 64) {
        int e = e0 + tid;
        if (e < NE) {
            ssrc[tid] = g_src[e];
            int d = g_dst[e];
            swt[tid] = g_es[e] / (g_sumexp[layer * NN + d] + 1e-6f);
        } else {
            ssrc[tid] = 0; swt[tid] = 0.f;
        }
    }
    if (tid < 128) {
        smb1[tid] = mb1[tid];
        smb2[tid] = mb2[tid];
    }
    __syncthreads();

    // ea split -> A tile cols 0..15
    for (int idx = tid; idx < 64 * 2; idx += 256) {
        int r = idx >> 1, c = (idx & 1) * 8;
        int e = min(e0 + r, NE - 1);
        *(uint4*)&sAh[r * AP2 + c] = *(const uint4*)&g_eah[(u64)e * 16 + c];
        *(uint4*)&sAl[r * AP2 + c] = *(const uint4*)&g_eal[(u64)e * 16 + c];
    }
    // W_ea
    {
        const u16* wh = g_EWh + layer * 192 * 16 + 64 * 16;
        const u16* wl = g_EWl + layer * 192 * 16 + 64 * 16;
        for (int idx = tid; idx < 128 * 2; idx += 256) {
            int r = idx >> 1, c = (idx & 1) * 8;
            *(uint4*)&sWh[r * AP2 + c] = *(const uint4*)&wh[r * 16 + c];
            *(uint4*)&sWl[r * AP2 + c] = *(const uint4*)&wl[r * 16 + c];
        }
    }
    __syncthreads();

    int m0 = (w & 1) * 32, n0 = (w >> 1) * 32;
    // GEMM_ea: K=16
    float acc[2][4][4];
#pragma unroll
    for (int i = 0; i < 2; i++)
#pragma unroll
        for (int j = 0; j < 4; j++)
#pragma unroll
            for (int k = 0; k < 4; k++) acc[i][j][k] = 0.f;
    {
        u32 ah[2][4], al[2][4];
#pragma unroll
        for (int mt = 0; mt < 2; mt++) {
            int r = m0 + mt * 16 + (lane & 15);
            int c = (lane >> 4) << 3;
            u32 off = (u32)(r * AP2 + c) * 2;
            ldsm4(ah[mt], sb + M_AH + off);
            ldsm4(al[mt], sb + M_AL + off);
        }
#pragma unroll
        for (int nt = 0; nt < 4; nt++) {
            int rn = n0 + nt * 8 + (lane & 7);
            int cn = ((lane >> 3) & 1) << 3;
            u32 offb = (u32)(rn * AP2 + cn) * 2;
            u32 bh[2], bl[2];
            ldsm2(bh, sb + M_WH + offb);
            ldsm2(bl, sb + M_WL + offb);
#pragma unroll
            for (int mt = 0; mt < 2; mt++) {
                mma16816(acc[mt][nt], ah[mt], bh);
                mma16816(acc[mt][nt], ah[mt], bl);
                mma16816(acc[mt][nt], al[mt], bh);
            }
        }
    }
    __syncthreads();

    // epilogue-ea: m = relu(eaW + vh + b1) -> split into A tiles (vh direct from L2)
#pragma unroll
    for (int mt = 0; mt < 2; mt++)
#pragma unroll
        for (int nt = 0; nt < 4; nt++) {
            int rA = m0 + mt * 16 + (lane >> 2);
            int rB = rA + 8;
            int c = n0 + nt * 8 + 2 * (lane & 3);
            float b0 = smb1[c], b1 = smb1[c + 1];
            float2 vA = *(const float2*)&g_pre[(u64)ssrc[rA] * 256 + 128 + c];
            float2 vB = *(const float2*)&g_pre[(u64)ssrc[rB] * 256 + 128 + c];
            u32 h, l;
            split2(fmaxf(acc[mt][nt][0] + vA.x + b0, 0.f),
                   fmaxf(acc[mt][nt][1] + vA.y + b1, 0.f), h, l);
            *(u32*)&sAh[rA * AP2 + c] = h;
            *(u32*)&sAl[rA * AP2 + c] = l;
            split2(fmaxf(acc[mt][nt][2] + vB.x + b0, 0.f),
                   fmaxf(acc[mt][nt][3] + vB.y + b1, 0.f), h, l);
            *(u32*)&sAh[rB * AP2 + c] = h;
            *(u32*)&sAl[rB * AP2 + c] = l;
        }
    // W2 load
    {
        const u16* wh = g_W2h + layer * 128 * 128;
        const u16* wl = g_W2l + layer * 128 * 128;
        for (int idx = tid; idx < 128 * 16; idx += 256) {
            int r = idx >> 4, c = (idx & 15) * 8;
            *(uint4*)&sWh[r * AP2 + c] = *(const uint4*)&wh[r * 128 + c];
            *(uint4*)&sWl[r * AP2 + c] = *(const uint4*)&wl[r * 128 + c];
        }
    }
    __syncthreads();

    // GEMM2 K=128
    float acc2[2][4][4];
#pragma unroll
    for (int i = 0; i < 2; i++)
#pragma unroll
        for (int j = 0; j < 4; j++)
#pragma unroll
            for (int k = 0; k < 4; k++) acc2[i][j][k] = 0.f;

    for (int ks = 0; ks < 8; ks++) {
        int kb = ks * 16;
        u32 ah[2][4], al[2][4];
#pragma unroll
        for (int mt = 0; mt < 2; mt++) {
            int r = m0 + mt * 16 + (lane & 15);
            int c = kb + ((lane >> 4) << 3);
            u32 off = (u32)(r * AP2 + c) * 2;
            ldsm4(ah[mt], sb + M_AH + off);
            ldsm4(al[mt], sb + M_AL + off);
        }
#pragma unroll
        for (int nt = 0; nt < 4; nt++) {
            int rn = n0 + nt * 8 + (lane & 7);
            int cn = kb + (((lane >> 3) & 1) << 3);
            u32 offb = (u32)(rn * AP2 + cn) * 2;
            u32 bh[2], bl[2];
            ldsm2(bh, sb + M_WH + offb);
            ldsm2(bl, sb + M_WL + offb);
#pragma unroll
            for (int mt = 0; mt < 2; mt++) {
                mma16816(acc2[mt][nt], ah[mt], bh);
                mma16816(acc2[mt][nt], ah[mt], bl);
                mma16816(acc2[mt][nt], al[mt], bh);
            }
        }
    }

    // epilogue2: weighted message -> coalesced store to g_msgbuf
#pragma unroll
    for (int mt = 0; mt < 2; mt++)
#pragma unroll
        for (int nt = 0; nt < 4; nt++) {
            int rA = m0 + mt * 16 + (lane >> 2);
            int rB = rA + 8;
            int c = n0 + nt * 8 + 2 * (lane & 3);
            float b0 = smb2[c], b1 = smb2[c + 1];
            float wA = swt[rA], wB = swt[rB];
            int eA = e0 + rA, eB = e0 + rB;
            if (eA < NE) {
                float2 v;
                v.x = (acc2[mt][nt][0] + b0) * wA;
                v.y = (acc2[mt][nt][1] + b1) * wA;
                *(float2*)&g_msgbuf[(u64)eA * 128 + c] = v;
            }
            if (eB < NE) {
                float2 v;
                v.x = (acc2[mt][nt][2] + b0) * wB;
                v.y = (acc2[mt][nt][3] + b1) * wB;
                *(float2*)&g_msgbuf[(u64)eB * 128 + c] = v;
            }
        }
}

// ---------------- node update: M=64 tiles, 2 CTAs/SM ----------------
#define UPP 136
#define U_AH 0
#define U_AL 17408
#define U_WH 34816
#define U_WL 69632
#define SMEM_UPD 104448

__global__ void __launch_bounds__(256, 2)
k_update(const float* __restrict__ ub1,
         const float* __restrict__ ub2,
         const float* __restrict__ lng,
         const float* __restrict__ lnb, int layer) {
    extern __shared__ char sm[];
    u16* sAh = (u16*)(sm + U_AH);
    u16* sAl = (u16*)(sm + U_AL);
    u16* sWh = (u16*)(sm + U_WH);
    u16* sWl = (u16*)(sm + U_WL);
    float* stage = (float*)(sm + U_WH);  // reused after GEMM2 (64x132 fp32 = 33.8KB)
    u32 sb = smem_u32(sm);
    int tid = threadIdx.x, lane = tid & 31, w = tid >> 5;
    int n0 = blockIdx.x * 64;

    // phase 0: CSR gather of weighted messages (agg in registers)
    int ln = tid >> 2, q = tid & 3;
    int nn = n0 + ln;
    float agg[32];
#pragma unroll
    for (int t = 0; t < 32; t++) agg[t] = 0.f;
    if (nn < NN) {
        int j0 = g_row[nn], j1 = g_cur[nn];
        for (int j = j0; j < j1; j++) {
            int e = g_eord[j];
            const float* mp = &g_msgbuf[(u64)e * 128 + q * 32];
#pragma unroll
            for (int t = 0; t < 8; t++) {
                float4 v = *(const float4*)&mp[t * 4];
                agg[t * 4]     += v.x;
                agg[t * 4 + 1] += v.y;
                agg[t * 4 + 2] += v.z;
                agg[t * 4 + 3] += v.w;
            }
        }
    }

    // A1 = h split
    for (int idx = tid; idx < 64 * 16; idx += 256) {
        int r = idx >> 4, c = (idx & 15) * 8;
        int n = n0 + r;
        if (n < NN) {
            *(uint4*)&sAh[r * UPP + c] = *(const uint4*)&g_hh[n * HID + c];
            *(uint4*)&sAl[r * UPP + c] = *(const uint4*)&g_hl[n * HID + c];
        } else {
            uint4 z = make_uint4(0, 0, 0, 0);
            *(uint4*)&sAh[r * UPP + c] = z;
            *(uint4*)&sAl[r * UPP + c] = z;
        }
    }
    // Wa (uw1 in-half 0)
    {
        const u16* wh = g_U1h + layer * 32768;
        const u16* wl = g_U1l + layer * 32768;
        for (int idx = tid; idx < 128 * 16; idx += 256) {
            int r = idx >> 4, c = (idx & 15) * 8;
            *(uint4*)&sWh[r * UPP + c] = *(const uint4*)&wh[r * 128 + c];
            *(uint4*)&sWl[r * UPP + c] = *(const uint4*)&wl[r * 128 + c];
        }
    }
    __syncthreads();

    int m0 = (w & 1) * 32, nw0 = (w >> 1) * 32;
    float acc[2][4][4];
#pragma unroll
    for (int i = 0; i < 2; i++)
#pragma unroll
        for (int j = 0; j < 4; j++)
#pragma unroll
            for (int k = 0; k < 4; k++) acc[i][j][k] = 0.f;

    for (int ks = 0; ks < 8; ks++) {
        int kb = ks * 16;
        u32 ah[2][4], al[2][4];
#pragma unroll
        for (int mt = 0; mt < 2; mt++) {
            int r = m0 + mt * 16 + (lane & 15);
            int c = kb + ((lane >> 4) << 3);
            u32 off = (u32)(r * UPP + c) * 2;
            ldsm4(ah[mt], sb + U_AH + off);
            ldsm4(al[mt], sb + U_AL + off);
        }
#pragma unroll
        for (int nt = 0; nt < 4; nt++) {
            int rn = nw0 + nt * 8 + (lane & 7);
            int cn = kb + (((lane >> 3) & 1) << 3);
            u32 offb = (u32)(rn * UPP + cn) * 2;
            u32 bh[2], bl[2];
            ldsm2(bh, sb + U_WH + offb);
            ldsm2(bl, sb + U_WL + offb);
#pragma unroll
            for (int mt = 0; mt < 2; mt++) {
                mma16816(acc[mt][nt], ah[mt], bh);
                mma16816(acc[mt][nt], ah[mt], bl);
                mma16816(acc[mt][nt], al[mt], bh);
            }
        }
    }
    __syncthreads();

    // A2 = agg split; Wb (uw1 in-half 1)
    {
#pragma unroll
        for (int t = 0; t < 16; t++) {
            u32 h, l;
            split2(agg[2 * t], agg[2 * t + 1], h, l);
            *(u32*)&sAh[ln * UPP + q * 32 + 2 * t] = h;
            *(u32*)&sAl[ln * UPP + q * 32 + 2 * t] = l;
        }
        const u16* wh = g_U1h + layer * 32768 + 16384;
        const u16* wl = g_U1l + layer * 32768 + 16384;
        for (int idx = tid; idx < 128 * 16; idx += 256) {
            int r = idx >> 4, c = (idx & 15) * 8;
            *(uint4*)&sWh[r * UPP + c] = *(const uint4*)&wh[r * 128 + c];
            *(uint4*)&sWl[r * UPP + c] = *(const uint4*)&wl[r * 128 + c];
        }
    }
    __syncthreads();

    for (int ks = 0; ks < 8; ks++) {
        int kb = ks * 16;
        u32 ah[2][4], al[2][4];
#pragma unroll
        for (int mt = 0; mt < 2; mt++) {
            int r = m0 + mt * 16 + (lane & 15);
            int c = kb + ((lane >> 4) << 3);
            u32 off = (u32)(r * UPP + c) * 2;
            ldsm4(ah[mt], sb + U_AH + off);
            ldsm4(al[mt], sb + U_AL + off);
        }
#pragma unroll
        for (int nt = 0; nt < 4; nt++) {
            int rn = nw0 + nt * 8 + (lane & 7);
            int cn = kb + (((lane >> 3) & 1) << 3);
            u32 offb = (u32)(rn * UPP + cn) * 2;
            u32 bh[2], bl[2];
            ldsm2(bh, sb + U_WH + offb);
            ldsm2(bl, sb + U_WL + offb);
#pragma unroll
            for (int mt = 0; mt < 2; mt++) {
                mma16816(acc[mt][nt], ah[mt], bh);
                mma16816(acc[mt][nt], ah[mt], bl);
                mma16816(acc[mt][nt], al[mt], bh);
            }
        }
    }
    __syncthreads();

    // relu(acc + ub1) -> re-split into A tiles
#pragma unroll
    for (int mt = 0; mt < 2; mt++)
#pragma unroll
        for (int nt = 0; nt < 4; nt++) {
            int rA = m0 + mt * 16 + (lane >> 2);
            int rB = rA + 8;
            int c = nw0 + nt * 8 + 2 * (lane & 3);
            float b0 = ub1[c], b1 = ub1[c + 1];
            u32 h, l;
            split2(fmaxf(acc[mt][nt][0] + b0, 0.f),
                   fmaxf(acc[mt][nt][1] + b1, 0.f), h, l);
            *(u32*)&sAh[rA * UPP + c] = h;
            *(u32*)&sAl[rA * UPP + c] = l;
            split2(fmaxf(acc[mt][nt][2] + b0, 0.f),
                   fmaxf(acc[mt][nt][3] + b1, 0.f), h, l);
            *(u32*)&sAh[rB * UPP + c] = h;
            *(u32*)&sAl[rB * UPP + c] = l;
        }
    // W2 = uw2 split
    {
        const u16* wh = g_U2h + layer * 128 * 128;
        const u16* wl = g_U2l + layer * 128 * 128;
        for (int idx = tid; idx < 128 * 16; idx += 256) {
            int r = idx >> 4, c = (idx & 15) * 8;
            *(uint4*)&sWh[r * UPP + c] = *(const uint4*)&wh[r * 128 + c];
            *(uint4*)&sWl[r * UPP + c] = *(const uint4*)&wl[r * 128 + c];
        }
    }
    __syncthreads();

    float acc2[2][4][4];
#pragma unroll
    for (int i = 0; i < 2; i++)
#pragma unroll
        for (int j = 0; j < 4; j++)
#pragma unroll
            for (int k = 0; k < 4; k++) acc2[i][j][k] = 0.f;

    for (int ks = 0; ks < 8; ks++) {
        int kb = ks * 16;
        u32 ah[2][4], al[2][4];
#pragma unroll
        for (int mt = 0; mt < 2; mt++) {
            int r = m0 + mt * 16 + (lane & 15);
            int c = kb + ((lane >> 4) << 3);
            u32 off = (u32)(r * UPP + c) * 2;
            ldsm4(ah[mt], sb + U_AH + off);
            ldsm4(al[mt], sb + U_AL + off);
        }
#pragma unroll
        for (int nt = 0; nt < 4; nt++) {
            int rn = nw0 + nt * 8 + (lane & 7);
            int cn = kb + (((lane >> 3) & 1) << 3);
            u32 offb = (u32)(rn * UPP + cn) * 2;
            u32 bh[2], bl[2];
            ldsm2(bh, sb + U_WH + offb);
            ldsm2(bl, sb + U_WL + offb);
#pragma unroll
            for (int mt = 0; mt < 2; mt++) {
                mma16816(acc2[mt][nt], ah[mt], bh);
                mma16816(acc2[mt][nt], ah[mt], bl);
                mma16816(acc2[mt][nt], al[mt], bh);
            }
        }
    }
    __syncthreads();  // W tiles dead -> stage

#pragma unroll
    for (int mt = 0; mt < 2; mt++)
#pragma unroll
        for (int nt = 0; nt < 4; nt++) {
            int rA = m0 + mt * 16 + (lane >> 2);
            int rB = rA + 8;
            int c = nw0 + nt * 8 + 2 * (lane & 3);
            stage[rA * 132 + c]     = acc2[mt][nt][0];
            stage[rA * 132 + c + 1] = acc2[mt][nt][1];
            stage[rB * 132 + c]     = acc2[mt][nt][2];
            stage[rB * 132 + c + 1] = acc2[mt][nt][3];
        }
    __syncthreads();

    // LN: 4 threads per row (ln, q)
    {
        int c0 = q * 32;
        float v[32];
        float s = 0.f, sq = 0.f;
        if (nn < NN) {
#pragma unroll
            for (int t4 = 0; t4 < 8; t4++) {
                float4 hres = *(const float4*)&g_h[nn * HID + c0 + t4 * 4];
                float hr[4] = {hres.x, hres.y, hres.z, hres.w};
#pragma unroll
                for (int j = 0; j < 4; j++) {
                    int t = t4 * 4 + j;
                    float val = stage[ln * 132 + c0 + t] + ub2[c0 + t] + hr[j];
                    val = fmaxf(val, 0.f);
                    v[t] = val;
                    s += val;
                    sq += val * val;
                }
            }
        } else {
#pragma unroll
            for (int t = 0; t < 32; t++) v[t] = 0.f;
        }
        s  += __shfl_xor_sync(0xffffffffu, s, 1);
        s  += __shfl_xor_sync(0xffffffffu, s, 2);
        sq += __shfl_xor_sync(0xffffffffu, sq, 1);
        sq += __shfl_xor_sync(0xffffffffu, sq, 2);
        float mu = s * (1.f / 128.f);
        float var = sq * (1.f / 128.f) - mu * mu;
        float rs = rsqrtf(var + 1e-5f);
        if (nn < NN) {
#pragma unroll
            for (int t4 = 0; t4 < 8; t4++) {
                float o[4];
#pragma unroll
                for (int j = 0; j < 4; j++) {
                    int t = t4 * 4 + j;
                    o[j] = (v[t] - mu) * rs * lng[c0 + t] + lnb[c0 + t];
                }
                *(float4*)&g_h[nn * HID + c0 + t4 * 4] =
                    make_float4(o[0], o[1], o[2], o[3]);
                u32 h0, l0, h1, l1;
                split2(o[0], o[1], h0, l0);
                split2(o[2], o[3], h1, l1);
                *(u32*)&g_hh[nn * HID + c0 + t4 * 4]     = h0;
                *(u32*)&g_hh[nn * HID + c0 + t4 * 4 + 2] = h1;
                *(u32*)&g_hl[nn * HID + c0 + t4 * 4]     = l0;
                *(u32*)&g_hl[nn * HID + c0 + t4 * 4 + 2] = l1;
            }
        }
    }
}

// ---------------- final readout ----------------
__global__ void k_final(const float* __restrict__ gc,
                        const float* __restrict__ qw1,
                        const float* __restrict__ qb1,
                        const float* __restrict__ qw2,
                        const float* __restrict__ qb2p,
                        float* __restrict__ out) {
    __shared__ float sA[32 * 33];
    __shared__ float sW[128 * 33];
    __shared__ float sctx[64];
    __shared__ float sout[32];
    int tid = threadIdx.x;
    int n0 = blockIdx.x * 32;
    if (tid < 64) sctx[tid] = gc[tid];
    if (tid < 32) sout[tid] = qb2p[0];
    __syncthreads();
    int tc = tid & 31, trg = tid >> 5;
    float acc[4][4] = {};
    for (int kb = 0; kb < 192; kb += 32) {
        for (int idx = tid; idx < 32 * 32; idx += NT) {
            int r = idx >> 5, kk = idx & 31;
            int n = n0 + r;
            int kg = kb + kk;
            float v = 0.f;
            if (n < NN) v = (kg < 128) ? g_h[n * HID + kg] : sctx[kg - 128];
            sA[r * 33 + kk] = v;
        }
        for (int idx = tid; idx < 128 * 32; idx += NT) {
            int o = idx >> 5, kk = idx & 31;
            sW[o * 33 + kk] = qw1[o * 192 + kb + kk];
        }
        __syncthreads();
#pragma unroll 8
        for (int k = 0; k < 32; k++) {
            float a[4], w[4];
#pragma unroll
            for (int i = 0; i < 4; i++) a[i] = sA[(trg * 4 + i) * 33 + k];
#pragma unroll
            for (int j = 0; j < 4; j++) w[j] = sW[(tc + 32 * j) * 33 + k];
#pragma unroll
            for (int i = 0; i < 4; i++)
#pragma unroll
                for (int j = 0; j < 4; j++) acc[i][j] += a[i] * w[j];
        }
        __syncthreads();
    }
    float p[4] = {0.f, 0.f, 0.f, 0.f};
#pragma unroll
    for (int j = 0; j < 4; j++) {
        int c = tc + 32 * j;
        float b = qb1[c], w2 = qw2[c];
#pragma unroll
        for (int i = 0; i < 4; i++) {
            float v = fmaxf(acc[i][j] + b, 0.f);
            p[i] += v * w2;
        }
    }
#pragma unroll
    for (int i = 0; i < 4; i++) atomicAdd(&sout[trg * 4 + i], p[i]);
    __syncthreads();
    if (tid < 32) {
        int n = n0 + tid;
        if (n < NN) out[n] = sout[tid];
    }
}

// ---------------- launch ----------------
extern "C" void kernel_launch(void* const* d_in, const int* in_sizes, int n_in,
                              void* d_out, int out_size) {
    const float* x    = (const float*)d_in[0];
    const void*  eidx = d_in[1];
    const float* ea   = (const float*)d_in[2];
    const float* gc   = (const float*)d_in[3];
    const float* npw  = (const float*)d_in[4];
    const float* npb  = (const float*)d_in[5];
    const float* mw1  = (const float*)d_in[6];
    const float* mb1  = (const float*)d_in[7];
    const float* mw2  = (const float*)d_in[8];
    const float* mb2  = (const float*)d_in[9];
    const float* aw1  = (const float*)d_in[10];
    const float* ab1  = (const float*)d_in[11];
    const float* aw2  = (const float*)d_in[12];
    const float* ab2  = (const float*)d_in[13];
    const float* uw1  = (const float*)d_in[14];
    const float* ub1  = (const float*)d_in[15];
    const float* uw2  = (const float*)d_in[16];
    const float* ub2  = (const float*)d_in[17];
    const float* lng  = (const float*)d_in[18];
    const float* lnb  = (const float*)d_in[19];
    const float* qw1  = (const float*)d_in[20];
    const float* qb1  = (const float*)d_in[21];
    const float* qw2  = (const float*)d_in[22];
    const float* qb2  = (const float*)d_in[23];
    float* out = (float*)d_out;

    cudaFuncSetAttribute(k_msg, cudaFuncAttributeMaxDynamicSharedMemorySize, SMEM_MSG2);
    cudaFuncSetAttribute(k_node_pre, cudaFuncAttributeMaxDynamicSharedMemorySize, SMEM_NP);
    cudaFuncSetAttribute(k_update, cudaFuncAttributeMaxDynamicSharedMemorySize, SMEM_UPD);

    int prep_tot = 3 * (256 * 128 + 192 * 16 + 128 * 128 + 256 * 128 + 128 * 128);
    k_prep<<<(prep_tot + 255) / 256, 256>>>(mw1, mw2, aw1, uw1, uw2);
    k_detect<<<1, NT>>>((const unsigned*)eidx);
    k_convert<<<(NE + NT - 1) / NT, NT>>>(eidx, ea);
    k_hist<<<(NE + 255) / 256, 256>>>();
    k_scan<<<1, 1024>>>();
    k_scatter<<<(NE + 255) / 256, 256>>>();
    k_nodeproj<<<(NN + 31) / 32, NT>>>(x, npw, npb);

    int ngrid = (NN + 63) / 64;
    int egrid = (NE + 63) / 64;
    for (int l = 0; l < 3; l++) {
        k_node_pre<<<ngrid, 256, SMEM_NP>>>(l);
        k_attn_lite<<<(NE + 63) / 64, 256>>>(ea, aw1 + l * 64 * 272, ab1 + l * 64,
                                             aw2 + l * 64, ab2 + l, l);
        k_exp<<<(NE + NT - 1) / NT, NT>>>(l);
        k_msg<<<egrid, 256, SMEM_MSG2>>>(mb1 + l * 128, mb2 + l * 128, l);
        k_update<<<ngrid, 256, SMEM_UPD>>>(ub1 + l * 128, ub2 + l * 128,
                                           lng + l * 128, lnb + l * 128, l);
    }
    k_final<<<(NN + 31) / 32, NT>>>(gc, qw1, qb1, qw2, qb2, out);
}

// round 10
// speedup vs baseline: 1.5390x; 1.0773x over previous
#include <cuda_runtime.h>
#include <cuda_bf16.h>

#define NN 50000
#define NE 600000
#define HID 128
#define NT 256

typedef unsigned long long u64;
typedef unsigned int u32;
typedef unsigned short u16;

// ---------------- scratch ----------------
__device__ float g_h[NN * HID];
__device__ float g_pre[NN * 256];      // [0:64)=u_s, [64:128)=u_d, [128:256)=vh
__device__ float g_msgbuf[(u64)NE * 128];
__device__ float g_sumexp[3 * NN];
__device__ float g_scores[NE];
__device__ float g_es[NE];
__device__ int   g_src[NE];
__device__ int   g_dst[NE];
__device__ unsigned g_maxenc[3];
__device__ int   g_is64;
// CSR by dst
__device__ int g_cnt[NN];
__device__ int g_row[NN];
__device__ int g_cur[NN];
__device__ int g_eord[NE];
// bf16 hi/lo splits
__device__ __align__(16) u16 g_hh[NN * HID];
__device__ __align__(16) u16 g_hl[NN * HID];
__device__ __align__(16) u16 g_eah[NE * 16];
__device__ __align__(16) u16 g_eal[NE * 16];
__device__ __align__(16) u16 g_NPh[3 * 256 * 128];
__device__ __align__(16) u16 g_NPl[3 * 256 * 128];
__device__ __align__(16) u16 g_EWh[3 * 192 * 16];
__device__ __align__(16) u16 g_EWl[3 * 192 * 16];
__device__ __align__(16) u16 g_W2h[3 * 128 * 128];
__device__ __align__(16) u16 g_W2l[3 * 128 * 128];
__device__ __align__(16) u16 g_U1h[3 * 256 * 128];
__device__ __align__(16) u16 g_U1l[3 * 256 * 128];
__device__ __align__(16) u16 g_U2h[3 * 128 * 128];
__device__ __align__(16) u16 g_U2l[3 * 128 * 128];

__device__ __forceinline__ unsigned fenc(float f) {
    unsigned u = __float_as_uint(f);
    return (u & 0x80000000u) ? ~u : (u | 0x80000000u);
}
__device__ __forceinline__ float fdec(unsigned u) {
    return (u & 0x80000000u) ? __uint_as_float(u & 0x7fffffffu)
                             : __uint_as_float(~u);
}

// ---------------- bf16 split helpers ----------------
__device__ __forceinline__ void split_bf16(float v, u16 &h, u16 &l) {
    __nv_bfloat16 bh = __float2bfloat16(v);
    __nv_bfloat16 bl = __float2bfloat16(v - __bfloat162float(bh));
    h = __bfloat16_as_ushort(bh);
    l = __bfloat16_as_ushort(bl);
}
__device__ __forceinline__ void split2(float a, float b, u32 &h, u32 &l) {
    u16 h0, l0, h1, l1;
    split_bf16(a, h0, l0);
    split_bf16(b, h1, l1);
    h = (u32)h0 | ((u32)h1 << 16);
    l = (u32)l0 | ((u32)l1 << 16);
}

// ---------------- HMMA helpers ----------------
__device__ __forceinline__ u32 smem_u32(const void* p) {
    u32 a;
    asm("{ .reg .u64 t; cvta.to.shared.u64 t, %1; cvt.u32.u64 %0, t; }"
        : "=r"(a) : "l"(p));
    return a;
}
__device__ __forceinline__ void ldsm4(u32* r, u32 addr) {
    asm volatile("ldmatrix.sync.aligned.m8n8.x4.shared.b16 {%0,%1,%2,%3}, [%4];"
        : "=r"(r[0]), "=r"(r[1]), "=r"(r[2]), "=r"(r[3]) : "r"(addr));
}
__device__ __forceinline__ void ldsm2(u32* r, u32 addr) {
    asm volatile("ldmatrix.sync.aligned.m8n8.x2.shared.b16 {%0,%1}, [%2];"
        : "=r"(r[0]), "=r"(r[1]) : "r"(addr));
}
__device__ __forceinline__ void mma16816(float* d, const u32* a, const u32* b) {
    asm volatile("mma.sync.aligned.m16n8k16.row.col.f32.bf16.bf16.f32 "
        "{%0,%1,%2,%3}, {%4,%5,%6,%7}, {%8,%9}, {%0,%1,%2,%3};"
        : "+f"(d[0]), "+f"(d[1]), "+f"(d[2]), "+f"(d[3])
        : "r"(a[0]), "r"(a[1]), "r"(a[2]), "r"(a[3]), "r"(b[0]), "r"(b[1]));
}

// ---------------- weight preconversion ----------------
__global__ void k_prep(const float* __restrict__ mw1, const float* __restrict__ mw2,
                       const float* __restrict__ aw1, const float* __restrict__ uw1,
                       const float* __restrict__ uw2) {
    int idx = blockIdx.x * blockDim.x + threadIdx.x;
    const int NP = 3 * 256 * 128, EW = 3 * 192 * 16, W2 = 3 * 128 * 128;
    const int U1 = 3 * 256 * 128, U2 = 3 * 128 * 128;
    u16 h, l;
    if (idx < NP) {
        int lyr = idx / (256 * 128);
        int rem = idx % (256 * 128);
        int n = rem / 128, k = rem % 128;
        float v;
        if (n < 64)        v = aw1[lyr * 64 * 272 + n * 272 + k];
        else if (n < 128)  v = aw1[lyr * 64 * 272 + (n - 64) * 272 + 128 + k];
        else               v = mw1[lyr * 128 * 144 + (n - 128) * 144 + k];
        split_bf16(v, h, l);
        g_NPh[idx] = h; g_NPl[idx] = l;
    } else if (idx < NP + EW) {
        int i = idx - NP;
        int lyr = i / (192 * 16);
        int rem = i % (192 * 16);
        int n = rem / 16, k = rem % 16;
        float v = (n < 64) ? aw1[lyr * 64 * 272 + n * 272 + 256 + k]
                           : mw1[lyr * 128 * 144 + (n - 64) * 144 + 128 + k];
        split_bf16(v, h, l);
        g_EWh[i] = h; g_EWl[i] = l;
    } else if (idx < NP + EW + W2) {
        int i = idx - NP - EW;
        split_bf16(mw2[i], h, l);
        g_W2h[i] = h; g_W2l[i] = l;
    } else if (idx < NP + EW + W2 + U1) {
        int i = idx - NP - EW - W2;
        int lyr = i / 32768;
        int rem = i % 32768;
        int half = rem / 16384;
        int r2 = rem % 16384;
        int n = r2 / 128, k = r2 % 128;
        split_bf16(uw1[lyr * 32768 + n * 256 + half * 128 + k], h, l);
        g_U1h[i] = h; g_U1l[i] = l;
    } else if (idx < NP + EW + W2 + U1 + U2) {
        int i = idx - NP - EW - W2 - U1;
        split_bf16(uw2[i], h, l);
        g_U2h[i] = h; g_U2l[i] = l;
    }
}

// ---------------- detect + convert + ea split + zero ----------------
__global__ void k_detect(const unsigned* __restrict__ raw) {
    __shared__ int nz;
    if (threadIdx.x == 0) nz = 0;
    __syncthreads();
    for (int i = threadIdx.x; i < 2048; i += NT)
        if (raw[2 * i + 1] != 0u) atomicOr(&nz, 1);
    __syncthreads();
    if (threadIdx.x == 0) g_is64 = (nz == 0) ? 1 : 0;
}

__global__ void k_convert(const void* __restrict__ eidx, const float* __restrict__ ea) {
    int i = blockIdx.x * blockDim.x + threadIdx.x;
    long long stride = (long long)gridDim.x * blockDim.x;
    if (i < NE) {
        if (g_is64) {
            const long long* p = (const long long*)eidx;
            g_src[i] = (int)p[i];
            g_dst[i] = (int)p[NE + i];
        } else {
            const int* p = (const int*)eidx;
            g_src[i] = p[i];
            g_dst[i] = p[NE + i];
        }
    }
    for (long long j = i; j < (long long)NE * 16; j += stride) {
        u16 h, l;
        split_bf16(ea[j], h, l);
        g_eah[j] = h; g_eal[j] = l;
    }
    for (long long j = i; j < 3 * NN; j += stride) g_sumexp[j] = 0.f;
    for (long long j = i; j < NN; j += stride) g_cnt[j] = 0;
    if (i == 0) {
        g_maxenc[0] = 0x007FFFFFu;
        g_maxenc[1] = 0x007FFFFFu;
        g_maxenc[2] = 0x007FFFFFu;
    }
}

// ---------------- counting sort by dst (CSR) ----------------
__global__ void k_hist() {
    int i = blockIdx.x * blockDim.x + threadIdx.x;
    if (i < NE) atomicAdd(&g_cnt[g_dst[i]], 1);
}

__global__ void k_scan() {
    __shared__ int warpsum[32];
    __shared__ int scarry;
    int tid = threadIdx.x, lane = tid & 31, wid = tid >> 5;
    if (tid == 0) scarry = 0;
    __syncthreads();
    for (int base = 0; base < NN; base += 1024) {
        int i = base + tid;
        int v = (i < NN) ? g_cnt[i] : 0;
        int s = v;
#pragma unroll
        for (int off = 1; off < 32; off <<= 1) {
            int t = __shfl_up_sync(0xffffffffu, s, off);
            if (lane >= off) s += t;
        }
        if (lane == 31) warpsum[wid] = s;
        __syncthreads();
        if (wid == 0) {
            int ws = warpsum[lane];
#pragma unroll
            for (int off = 1; off < 32; off <<= 1) {
                int t = __shfl_up_sync(0xffffffffu, ws, off);
                if (lane >= off) ws += t;
            }
            warpsum[lane] = ws;
        }
        __syncthreads();
        int incl = s + (wid > 0 ? warpsum[wid - 1] : 0) + scarry;
        if (i < NN) { g_row[i] = incl - v; g_cur[i] = incl - v; }
        __syncthreads();
        if (tid == 1023) scarry = incl;
        __syncthreads();
    }
}

__global__ void k_scatter() {
    int i = blockIdx.x * blockDim.x + threadIdx.x;
    if (i < NE) {
        int pos = atomicAdd(&g_cur[g_dst[i]], 1);
        g_eord[pos] = i;
    }
}

// ---------------- node projection (+ split store) ----------------
__global__ void k_nodeproj(const float* __restrict__ x,
                           const float* __restrict__ W,
                           const float* __restrict__ b) {
    __shared__ float sA[32 * 33];
    __shared__ float sW[128 * 33];
    int tid = threadIdx.x;
    int n0 = blockIdx.x * 32;
    for (int idx = tid; idx < 32 * 32; idx += NT) {
        int r = idx >> 5, k = idx & 31;
        int n = n0 + r;
        sA[r * 33 + k] = (n < NN) ? x[n * 32 + k] : 0.f;
    }
    for (int idx = tid; idx < 128 * 32; idx += NT) {
        int o = idx >> 5, k = idx & 31;
        sW[o * 33 + k] = W[o * 32 + k];
    }
    __syncthreads();
    int tc = tid & 31, trg = tid >> 5;
    float acc[4][4] = {};
#pragma unroll 8
    for (int k = 0; k < 32; k++) {
        float a[4], w[4];
#pragma unroll
        for (int i = 0; i < 4; i++) a[i] = sA[(trg * 4 + i) * 33 + k];
#pragma unroll
        for (int j = 0; j < 4; j++) w[j] = sW[(tc + 32 * j) * 33 + k];
#pragma unroll
        for (int i = 0; i < 4; i++)
#pragma unroll
            for (int j = 0; j < 4; j++) acc[i][j] += a[i] * w[j];
    }
#pragma unroll
    for (int i = 0; i < 4; i++) {
        int n = n0 + trg * 4 + i;
        if (n < NN)
#pragma unroll
            for (int j = 0; j < 4; j++) {
                int c = tc + 32 * j;
                float v = fmaxf(acc[i][j] + b[c], 0.f);
                g_h[n * HID + c] = v;
                u16 h, l;
                split_bf16(v, h, l);
                g_hh[n * HID + c] = h;
                g_hl[n * HID + c] = l;
            }
    }
}

// ---------------- node precompute GEMM: M=64 tiles, 2 CTAs/SM (layer 0 only) ----------------
#define NPP 136
#define NP_AH 0
#define NP_AL 17408
#define NP_WH 34816
#define NP_WL 69632
#define SMEM_NP 104448

__global__ void __launch_bounds__(256, 2)
k_node_pre(int layer) {
    extern __shared__ char sm[];
    u16* sAh = (u16*)(sm + NP_AH);
    u16* sAl = (u16*)(sm + NP_AL);
    u16* sWh = (u16*)(sm + NP_WH);
    u16* sWl = (u16*)(sm + NP_WL);
    u32 sb = smem_u32(sm);
    int tid = threadIdx.x, lane = tid & 31, w = tid >> 5;
    int n0 = blockIdx.x * 64;

    for (int idx = tid; idx < 64 * 16; idx += 256) {
        int r = idx >> 4, c = (idx & 15) * 8;
        int n = n0 + r;
        if (n < NN) {
            *(uint4*)&sAh[r * NPP + c] = *(const uint4*)&g_hh[n * HID + c];
            *(uint4*)&sAl[r * NPP + c] = *(const uint4*)&g_hl[n * HID + c];
        } else {
            uint4 z = make_uint4(0, 0, 0, 0);
            *(uint4*)&sAh[r * NPP + c] = z;
            *(uint4*)&sAl[r * NPP + c] = z;
        }
    }

    int m0 = (w & 1) * 32, n0w = (w >> 1) * 32;
    for (int half = 0; half < 2; half++) {
        const u16* wh = g_NPh + layer * 256 * 128 + half * 128 * 128;
        const u16* wl = g_NPl + layer * 256 * 128 + half * 128 * 128;
        for (int idx = tid; idx < 128 * 16; idx += 256) {
            int r = idx >> 4, c = (idx & 15) * 8;
            *(uint4*)&sWh[r * NPP + c] = *(const uint4*)&wh[r * 128 + c];
            *(uint4*)&sWl[r * NPP + c] = *(const uint4*)&wl[r * 128 + c];
        }
        __syncthreads();
        float acc[2][4][4];
#pragma unroll
        for (int i = 0; i < 2; i++)
#pragma unroll
            for (int j = 0; j < 4; j++)
#pragma unroll
                for (int k = 0; k < 4; k++) acc[i][j][k] = 0.f;
        for (int ks = 0; ks < 8; ks++) {
            int kb = ks * 16;
            u32 ah[2][4], al[2][4];
#pragma unroll
            for (int mt = 0; mt < 2; mt++) {
                int r = m0 + mt * 16 + (lane & 15);
                int c = kb + ((lane >> 4) << 3);
                u32 off = (u32)(r * NPP + c) * 2;
                ldsm4(ah[mt], sb + NP_AH + off);
                ldsm4(al[mt], sb + NP_AL + off);
            }
#pragma unroll
            for (int nt = 0; nt < 4; nt++) {
                int rn = n0w + nt * 8 + (lane & 7);
                int cn = kb + (((lane >> 3) & 1) << 3);
                u32 offb = (u32)(rn * NPP + cn) * 2;
                u32 bh[2], bl[2];
                ldsm2(bh, sb + NP_WH + offb);
                ldsm2(bl, sb + NP_WL + offb);
#pragma unroll
                for (int mt = 0; mt < 2; mt++) {
                    mma16816(acc[mt][nt], ah[mt], bh);
                    mma16816(acc[mt][nt], ah[mt], bl);
                    mma16816(acc[mt][nt], al[mt], bh);
                }
            }
        }
#pragma unroll
        for (int mt = 0; mt < 2; mt++)
#pragma unroll
            for (int nt = 0; nt < 4; nt++) {
                int rA = m0 + mt * 16 + (lane >> 2);
                int rB = rA + 8;
                int c = half * 128 + n0w + nt * 8 + 2 * (lane & 3);
                int nA = n0 + rA, nB = n0 + rB;
                if (nA < NN) {
                    g_pre[(u64)nA * 256 + c]     = acc[mt][nt][0];
                    g_pre[(u64)nA * 256 + c + 1] = acc[mt][nt][1];
                }
                if (nB < NN) {
                    g_pre[(u64)nB * 256 + c]     = acc[mt][nt][2];
                    g_pre[(u64)nB * 256 + c + 1] = acc[mt][nt][3];
                }
            }
        __syncthreads();
    }
}

// ---------------- attention scores (elementwise, decomposed) ----------------
__global__ void __launch_bounds__(256, 4)
k_attn_lite(const float* __restrict__ ea,
            const float* __restrict__ aw1l,
            const float* __restrict__ ab1,
            const float* __restrict__ aw2,
            const float* __restrict__ ab2p, int layer) {
    __shared__ float sea[64 * 17];
    __shared__ float sW[64 * 16];
    __shared__ float sb1[64], sv[64];
    __shared__ unsigned smax;
    int tid = threadIdx.x;
    int e0 = blockIdx.x * 64;
    if (tid == 0) smax = 0x007FFFFFu;
    {
        int r = tid >> 2, c = (tid & 3) * 4;
        float4 v = make_float4(0.f, 0.f, 0.f, 0.f);
        if (e0 + r < NE) v = *(const float4*)&ea[(u64)(e0 + r) * 16 + c];
        sea[r * 17 + c]     = v.x;
        sea[r * 17 + c + 1] = v.y;
        sea[r * 17 + c + 2] = v.z;
        sea[r * 17 + c + 3] = v.w;
    }
    {
        int r = tid >> 2, c = (tid & 3) * 4;
        float4 wv = *(const float4*)&aw1l[r * 272 + 256 + c];
        *(float4*)&sW[r * 16 + c] = wv;
    }
    if (tid < 64) { sb1[tid] = ab1[tid]; sv[tid] = aw2[tid]; }
    __syncthreads();

    int el = tid >> 2, p = tid & 3;
    int e = e0 + el;
    float score = 0.f;
    if (e < NE) {
        int s = g_src[e], d = g_dst[e];
        const float* ps = &g_pre[(u64)s * 256 + p * 16];
        const float* pd = &g_pre[(u64)d * 256 + 64 + p * 16];
        const float* er = &sea[el * 17];
#pragma unroll
        for (int c4 = 0; c4 < 4; c4++) {
            float4 a4 = *(const float4*)&ps[c4 * 4];
            float4 b4 = *(const float4*)&pd[c4 * 4];
            float av[4] = {a4.x, a4.y, a4.z, a4.w};
            float bv[4] = {b4.x, b4.y, b4.z, b4.w};
#pragma unroll
            for (int j = 0; j < 4; j++) {
                int c = p * 16 + c4 * 4 + j;
                float x = av[j] + bv[j] + sb1[c];
                const float* wr = &sW[c * 16];
#pragma unroll
                for (int k = 0; k < 16; k++) x += er[k] * wr[k];
                x = (x > 0.f) ? x : 0.2f * x;
                score += x * sv[c];
            }
        }
    }
    score += __shfl_xor_sync(0xffffffffu, score, 1);
    score += __shfl_xor_sync(0xffffffffu, score, 2);
    if (p == 0 && e < NE) {
        float sc = score + ab2p[0];
        g_scores[e] = sc;
        atomicMax(&smax, fenc(sc));
    }
    __syncthreads();
    if (tid == 0) atomicMax(&g_maxenc[layer], smax);
}

// ---------------- exp + scatter sum ----------------
__global__ void k_exp(int layer) {
    int i = blockIdx.x * blockDim.x + threadIdx.x;
    if (i >= NE) return;
    float m = fdec(g_maxenc[layer]);
    float es = expf(g_scores[i] - m);
    g_es[i] = es;
    atomicAdd(&g_sumexp[layer * NN + g_dst[i]], es);
}

// ---------------- message MLP: persistent weights, grid-stride tiles ----------------
#define AP2 136
#define M_AH 0
#define M_AL 17408
#define M_WH 34816
#define M_WL 69632
#define M_META 104448
#define SMEM_MSG2 (104448 + 1536)
#define NTILES ((NE + 63) / 64)

__global__ void __launch_bounds__(256, 2)
k_msg(const float* __restrict__ mb1,
      const float* __restrict__ mb2, int layer) {
    extern __shared__ char sm[];
    u16* sAh = (u16*)(sm + M_AH);
    u16* sAl = (u16*)(sm + M_AL);
    u16* sWh = (u16*)(sm + M_WH);
    u16* sWl = (u16*)(sm + M_WL);
    int*   ssrc = (int*)(sm + M_META);
    float* swt  = (float*)(sm + M_META + 256);
    float* smb1 = (float*)(sm + M_META + 512);
    float* smb2 = (float*)(sm + M_META + 1024);
    u32 sb = smem_u32(sm);

    int tid = threadIdx.x, lane = tid & 31, w = tid >> 5;
    int m0 = (w & 1) * 32, n0 = (w >> 1) * 32;

    // ---- one-time setup: stage Wea (compact stride 16) in A area, load W2, biases ----
    {
        const u16* wh = g_EWh + layer * 192 * 16 + 64 * 16;
        const u16* wl = g_EWl + layer * 192 * 16 + 64 * 16;
        for (int idx = tid; idx < 128 * 2; idx += 256) {
            int r = idx >> 1, c = (idx & 1) * 8;
            *(uint4*)&sAh[r * 16 + c] = *(const uint4*)&wh[r * 16 + c];
            *(uint4*)&sAl[r * 16 + c] = *(const uint4*)&wl[r * 16 + c];
        }
        const u16* w2h = g_W2h + layer * 128 * 128;
        const u16* w2l = g_W2l + layer * 128 * 128;
        for (int idx = tid; idx < 128 * 16; idx += 256) {
            int r = idx >> 4, c = (idx & 15) * 8;
            *(uint4*)&sWh[r * AP2 + c] = *(const uint4*)&w2h[r * 128 + c];
            *(uint4*)&sWl[r * AP2 + c] = *(const uint4*)&w2l[r * 128 + c];
        }
        if (tid < 128) { smb1[tid] = mb1[tid]; smb2[tid] = mb2[tid]; }
    }
    __syncthreads();
    // Wea fragments -> registers (held across all tiles)
    u32 weah[4][2], weal[4][2];
#pragma unroll
    for (int nt = 0; nt < 4; nt++) {
        int rn = n0 + nt * 8 + (lane & 7);
        int cn = ((lane >> 3) & 1) << 3;
        u32 off = (u32)(rn * 16 + cn) * 2;
        ldsm2(weah[nt], sb + M_AH + off);
        ldsm2(weal[nt], sb + M_AL + off);
    }
    __syncthreads();

    for (int t = blockIdx.x; t < NTILES; t += gridDim.x) {
        int e0 = t * 64;
        if (tid < 64) {
            int e = e0 + tid;
            if (e < NE) {
                ssrc[tid] = g_src[e];
                int d = g_dst[e];
                swt[tid] = g_es[e] / (g_sumexp[layer * NN + d] + 1e-6f);
            } else {
                ssrc[tid] = 0; swt[tid] = 0.f;
            }
        }
        // ea split -> A tile cols 0..15
        for (int idx = tid; idx < 64 * 2; idx += 256) {
            int r = idx >> 1, c = (idx & 1) * 8;
            int e = min(e0 + r, NE - 1);
            *(uint4*)&sAh[r * AP2 + c] = *(const uint4*)&g_eah[(u64)e * 16 + c];
            *(uint4*)&sAl[r * AP2 + c] = *(const uint4*)&g_eal[(u64)e * 16 + c];
        }
        __syncthreads();

        // GEMM_ea: K=16, Wea from registers
        float acc[2][4][4];
#pragma unroll
        for (int i = 0; i < 2; i++)
#pragma unroll
            for (int j = 0; j < 4; j++)
#pragma unroll
                for (int k = 0; k < 4; k++) acc[i][j][k] = 0.f;
        {
            u32 ah[2][4], al[2][4];
#pragma unroll
            for (int mt = 0; mt < 2; mt++) {
                int r = m0 + mt * 16 + (lane & 15);
                int c = (lane >> 4) << 3;
                u32 off = (u32)(r * AP2 + c) * 2;
                ldsm4(ah[mt], sb + M_AH + off);
                ldsm4(al[mt], sb + M_AL + off);
            }
#pragma unroll
            for (int nt = 0; nt < 4; nt++) {
#pragma unroll
                for (int mt = 0; mt < 2; mt++) {
                    mma16816(acc[mt][nt], ah[mt], weah[nt]);
                    mma16816(acc[mt][nt], ah[mt], weal[nt]);
                    mma16816(acc[mt][nt], al[mt], weah[nt]);
                }
            }
        }
        __syncthreads();

        // epilogue-ea: m = relu(eaW + vh + b1) -> split into A tiles (vh direct from L2)
#pragma unroll
        for (int mt = 0; mt < 2; mt++)
#pragma unroll
            for (int nt = 0; nt < 4; nt++) {
                int rA = m0 + mt * 16 + (lane >> 2);
                int rB = rA + 8;
                int c = n0 + nt * 8 + 2 * (lane & 3);
                float b0 = smb1[c], b1 = smb1[c + 1];
                float2 vA = *(const float2*)&g_pre[(u64)ssrc[rA] * 256 + 128 + c];
                float2 vB = *(const float2*)&g_pre[(u64)ssrc[rB] * 256 + 128 + c];
                u32 h, l;
                split2(fmaxf(acc[mt][nt][0] + vA.x + b0, 0.f),
                       fmaxf(acc[mt][nt][1] + vA.y + b1, 0.f), h, l);
                *(u32*)&sAh[rA * AP2 + c] = h;
                *(u32*)&sAl[rA * AP2 + c] = l;
                split2(fmaxf(acc[mt][nt][2] + vB.x + b0, 0.f),
                       fmaxf(acc[mt][nt][3] + vB.y + b1, 0.f), h, l);
                *(u32*)&sAh[rB * AP2 + c] = h;
                *(u32*)&sAl[rB * AP2 + c] = l;
            }
        __syncthreads();

        // GEMM2 K=128 (W2 resident)
        float acc2[2][4][4];
#pragma unroll
        for (int i = 0; i < 2; i++)
#pragma unroll
            for (int j = 0; j < 4; j++)
#pragma unroll
                for (int k = 0; k < 4; k++) acc2[i][j][k] = 0.f;

        for (int ks = 0; ks < 8; ks++) {
            int kb = ks * 16;
            u32 ah[2][4], al[2][4];
#pragma unroll
            for (int mt = 0; mt < 2; mt++) {
                int r = m0 + mt * 16 + (lane & 15);
                int c = kb + ((lane >> 4) << 3);
                u32 off = (u32)(r * AP2 + c) * 2;
                ldsm4(ah[mt], sb + M_AH + off);
                ldsm4(al[mt], sb + M_AL + off);
            }
#pragma unroll
            for (int nt = 0; nt < 4; nt++) {
                int rn = n0 + nt * 8 + (lane & 7);
                int cn = kb + (((lane >> 3) & 1) << 3);
                u32 offb = (u32)(rn * AP2 + cn) * 2;
                u32 bh[2], bl[2];
                ldsm2(bh, sb + M_WH + offb);
                ldsm2(bl, sb + M_WL + offb);
#pragma unroll
                for (int mt = 0; mt < 2; mt++) {
                    mma16816(acc2[mt][nt], ah[mt], bh);
                    mma16816(acc2[mt][nt], ah[mt], bl);
                    mma16816(acc2[mt][nt], al[mt], bh);
                }
            }
        }

        // epilogue2: weighted message -> coalesced store to g_msgbuf
#pragma unroll
        for (int mt = 0; mt < 2; mt++)
#pragma unroll
            for (int nt = 0; nt < 4; nt++) {
                int rA = m0 + mt * 16 + (lane >> 2);
                int rB = rA + 8;
                int c = n0 + nt * 8 + 2 * (lane & 3);
                float b0 = smb2[c], b1 = smb2[c + 1];
                float wA = swt[rA], wB = swt[rB];
                int eA = e0 + rA, eB = e0 + rB;
                if (eA < NE) {
                    float2 v;
                    v.x = (acc2[mt][nt][0] + b0) * wA;
                    v.y = (acc2[mt][nt][1] + b1) * wA;
                    *(float2*)&g_msgbuf[(u64)eA * 128 + c] = v;
                }
                if (eB < NE) {
                    float2 v;
                    v.x = (acc2[mt][nt][2] + b0) * wB;
                    v.y = (acc2[mt][nt][3] + b1) * wB;
                    *(float2*)&g_msgbuf[(u64)eB * 128 + c] = v;
                }
            }
        __syncthreads();
    }
}

// ---------------- node update: CSR gather + HMMA MLP + LN + fused next-layer pre ----------------
#define UPP 136
#define U_AH 0
#define U_AL 17408
#define U_WH 34816
#define U_WL 69632
#define SMEM_UPD 104448

__global__ void __launch_bounds__(256, 2)
k_update(const float* __restrict__ ub1,
         const float* __restrict__ ub2,
         const float* __restrict__ lng,
         const float* __restrict__ lnb, int layer, int do_pre) {
    extern __shared__ char sm[];
    u16* sAh = (u16*)(sm + U_AH);
    u16* sAl = (u16*)(sm + U_AL);
    u16* sWh = (u16*)(sm + U_WH);
    u16* sWl = (u16*)(sm + U_WL);
    float* stage = (float*)(sm + U_WH);
    u32 sb = smem_u32(sm);
    int tid = threadIdx.x, lane = tid & 31, w = tid >> 5;
    int n0 = blockIdx.x * 64;

    // phase 0: CSR gather of weighted messages (agg in registers)
    int ln = tid >> 2, q = tid & 3;
    int nn = n0 + ln;
    float agg[32];
#pragma unroll
    for (int t = 0; t < 32; t++) agg[t] = 0.f;
    if (nn < NN) {
        int j0 = g_row[nn], j1 = g_cur[nn];
        for (int j = j0; j < j1; j++) {
            int e = g_eord[j];
            const float* mp = &g_msgbuf[(u64)e * 128 + q * 32];
#pragma unroll
            for (int t = 0; t < 8; t++) {
                float4 v = *(const float4*)&mp[t * 4];
                agg[t * 4]     += v.x;
                agg[t * 4 + 1] += v.y;
                agg[t * 4 + 2] += v.z;
                agg[t * 4 + 3] += v.w;
            }
        }
    }

    // A1 = h split
    for (int idx = tid; idx < 64 * 16; idx += 256) {
        int r = idx >> 4, c = (idx & 15) * 8;
        int n = n0 + r;
        if (n < NN) {
            *(uint4*)&sAh[r * UPP + c] = *(const uint4*)&g_hh[n * HID + c];
            *(uint4*)&sAl[r * UPP + c] = *(const uint4*)&g_hl[n * HID + c];
        } else {
            uint4 z = make_uint4(0, 0, 0, 0);
            *(uint4*)&sAh[r * UPP + c] = z;
            *(uint4*)&sAl[r * UPP + c] = z;
        }
    }
    // Wa (uw1 in-half 0)
    {
        const u16* wh = g_U1h + layer * 32768;
        const u16* wl = g_U1l + layer * 32768;
        for (int idx = tid; idx < 128 * 16; idx += 256) {
            int r = idx >> 4, c = (idx & 15) * 8;
            *(uint4*)&sWh[r * UPP + c] = *(const uint4*)&wh[r * 128 + c];
            *(uint4*)&sWl[r * UPP + c] = *(const uint4*)&wl[r * 128 + c];
        }
    }
    __syncthreads();

    int m0 = (w & 1) * 32, nw0 = (w >> 1) * 32;
    float acc[2][4][4];
#pragma unroll
    for (int i = 0; i < 2; i++)
#pragma unroll
        for (int j = 0; j < 4; j++)
#pragma unroll
            for (int k = 0; k < 4; k++) acc[i][j][k] = 0.f;

    for (int ks = 0; ks < 8; ks++) {
        int kb = ks * 16;
        u32 ah[2][4], al[2][4];
#pragma unroll
        for (int mt = 0; mt < 2; mt++) {
            int r = m0 + mt * 16 + (lane & 15);
            int c = kb + ((lane >> 4) << 3);
            u32 off = (u32)(r * UPP + c) * 2;
            ldsm4(ah[mt], sb + U_AH + off);
            ldsm4(al[mt], sb + U_AL + off);
        }
#pragma unroll
        for (int nt = 0; nt < 4; nt++) {
            int rn = nw0 + nt * 8 + (lane & 7);
            int cn = kb + (((lane >> 3) & 1) << 3);
            u32 offb = (u32)(rn * UPP + cn) * 2;
            u32 bh[2], bl[2];
            ldsm2(bh, sb + U_WH + offb);
            ldsm2(bl, sb + U_WL + offb);
#pragma unroll
            for (int mt = 0; mt < 2; mt++) {
                mma16816(acc[mt][nt], ah[mt], bh);
                mma16816(acc[mt][nt], ah[mt], bl);
                mma16816(acc[mt][nt], al[mt], bh);
            }
        }
    }
    __syncthreads();

    // A2 = agg split; Wb (uw1 in-half 1)
    {
#pragma unroll
        for (int t = 0; t < 16; t++) {
            u32 h, l;
            split2(agg[2 * t], agg[2 * t + 1], h, l);
            *(u32*)&sAh[ln * UPP + q * 32 + 2 * t] = h;
            *(u32*)&sAl[ln * UPP + q * 32 + 2 * t] = l;
        }
        const u16* wh = g_U1h + layer * 32768 + 16384;
        const u16* wl = g_U1l + layer * 32768 + 16384;
        for (int idx = tid; idx < 128 * 16; idx += 256) {
            int r = idx >> 4, c = (idx & 15) * 8;
            *(uint4*)&sWh[r * UPP + c] = *(const uint4*)&wh[r * 128 + c];
            *(uint4*)&sWl[r * UPP + c] = *(const uint4*)&wl[r * 128 + c];
        }
    }
    __syncthreads();

    for (int ks = 0; ks < 8; ks++) {
        int kb = ks * 16;
        u32 ah[2][4], al[2][4];
#pragma unroll
        for (int mt = 0; mt < 2; mt++) {
            int r = m0 + mt * 16 + (lane & 15);
            int c = kb + ((lane >> 4) << 3);
            u32 off = (u32)(r * UPP + c) * 2;
            ldsm4(ah[mt], sb + U_AH + off);
            ldsm4(al[mt], sb + U_AL + off);
        }
#pragma unroll
        for (int nt = 0; nt < 4; nt++) {
            int rn = nw0 + nt * 8 + (lane & 7);
            int cn = kb + (((lane >> 3) & 1) << 3);
            u32 offb = (u32)(rn * UPP + cn) * 2;
            u32 bh[2], bl[2];
            ldsm2(bh, sb + U_WH + offb);
            ldsm2(bl, sb + U_WL + offb);
#pragma unroll
            for (int mt = 0; mt < 2; mt++) {
                mma16816(acc[mt][nt], ah[mt], bh);
                mma16816(acc[mt][nt], ah[mt], bl);
                mma16816(acc[mt][nt], al[mt], bh);
            }
        }
    }
    __syncthreads();

    // relu(acc + ub1) -> re-split into A tiles
#pragma unroll
    for (int mt = 0; mt < 2; mt++)
#pragma unroll
        for (int nt = 0; nt < 4; nt++) {
            int rA = m0 + mt * 16 + (lane >> 2);
            int rB = rA + 8;
            int c = nw0 + nt * 8 + 2 * (lane & 3);
            float b0 = ub1[c], b1 = ub1[c + 1];
            u32 h, l;
            split2(fmaxf(acc[mt][nt][0] + b0, 0.f),
                   fmaxf(acc[mt][nt][1] + b1, 0.f), h, l);
            *(u32*)&sAh[rA * UPP + c] = h;
            *(u32*)&sAl[rA * UPP + c] = l;
            split2(fmaxf(acc[mt][nt][2] + b0, 0.f),
                   fmaxf(acc[mt][nt][3] + b1, 0.f), h, l);
            *(u32*)&sAh[rB * UPP + c] = h;
            *(u32*)&sAl[rB * UPP + c] = l;
        }
    // W2 = uw2 split
    {
        const u16* wh = g_U2h + layer * 128 * 128;
        const u16* wl = g_U2l + layer * 128 * 128;
        for (int idx = tid; idx < 128 * 16; idx += 256) {
            int r = idx >> 4, c = (idx & 15) * 8;
            *(uint4*)&sWh[r * UPP + c] = *(const uint4*)&wh[r * 128 + c];
            *(uint4*)&sWl[r * UPP + c] = *(const uint4*)&wl[r * 128 + c];
        }
    }
    __syncthreads();

    float acc2[2][4][4];
#pragma unroll
    for (int i = 0; i < 2; i++)
#pragma unroll
        for (int j = 0; j < 4; j++)
#pragma unroll
            for (int k = 0; k < 4; k++) acc2[i][j][k] = 0.f;

    for (int ks = 0; ks < 8; ks++) {
        int kb = ks * 16;
        u32 ah[2][4], al[2][4];
#pragma unroll
        for (int mt = 0; mt < 2; mt++) {
            int r = m0 + mt * 16 + (lane & 15);
            int c = kb + ((lane >> 4) << 3);
            u32 off = (u32)(r * UPP + c) * 2;
            ldsm4(ah[mt], sb + U_AH + off);
            ldsm4(al[mt], sb + U_AL + off);
        }
#pragma unroll
        for (int nt = 0; nt < 4; nt++) {
            int rn = nw0 + nt * 8 + (lane & 7);
            int cn = kb + (((lane >> 3) & 1) << 3);
            u32 offb = (u32)(rn * UPP + cn) * 2;
            u32 bh[2], bl[2];
            ldsm2(bh, sb + U_WH + offb);
            ldsm2(bl, sb + U_WL + offb);
#pragma unroll
            for (int mt = 0; mt < 2; mt++) {
                mma16816(acc2[mt][nt], ah[mt], bh);
                mma16816(acc2[mt][nt], ah[mt], bl);
                mma16816(acc2[mt][nt], al[mt], bh);
            }
        }
    }
    __syncthreads();  // W tiles dead -> stage

#pragma unroll
    for (int mt = 0; mt < 2; mt++)
#pragma unroll
        for (int nt = 0; nt < 4; nt++) {
            int rA = m0 + mt * 16 + (lane >> 2);
            int rB = rA + 8;
            int c = nw0 + nt * 8 + 2 * (lane & 3);
            stage[rA * 132 + c]     = acc2[mt][nt][0];
            stage[rA * 132 + c + 1] = acc2[mt][nt][1];
            stage[rB * 132 + c]     = acc2[mt][nt][2];
            stage[rB * 132 + c + 1] = acc2[mt][nt][3];
        }
    __syncthreads();

    // LN: 4 threads per row (ln, q); also deposit split h into A tiles for fused pre
    {
        int c0 = q * 32;
        float v[32];
        float s = 0.f, sq = 0.f;
        if (nn < NN) {
#pragma unroll
            for (int t4 = 0; t4 < 8; t4++) {
                float4 hres = *(const float4*)&g_h[nn * HID + c0 + t4 * 4];
                float hr[4] = {hres.x, hres.y, hres.z, hres.w};
#pragma unroll
                for (int j = 0; j < 4; j++) {
                    int t = t4 * 4 + j;
                    float val = stage[ln * 132 + c0 + t] + ub2[c0 + t] + hr[j];
                    val = fmaxf(val, 0.f);
                    v[t] = val;
                    s += val;
                    sq += val * val;
                }
            }
        } else {
#pragma unroll
            for (int t = 0; t < 32; t++) v[t] = 0.f;
        }
        s  += __shfl_xor_sync(0xffffffffu, s, 1);
        s  += __shfl_xor_sync(0xffffffffu, s, 2);
        sq += __shfl_xor_sync(0xffffffffu, sq, 1);
        sq += __shfl_xor_sync(0xffffffffu, sq, 2);
        float mu = s * (1.f / 128.f);
        float var = sq * (1.f / 128.f) - mu * mu;
        float rs = rsqrtf(var + 1e-5f);
        float o[32];
#pragma unroll
        for (int t = 0; t < 32; t++)
            o[t] = (v[t] - mu) * rs * lng[c0 + t] + lnb[c0 + t];
        if (nn < NN) {
#pragma unroll
            for (int t4 = 0; t4 < 8; t4++) {
                *(float4*)&g_h[nn * HID + c0 + t4 * 4] =
                    make_float4(o[t4 * 4], o[t4 * 4 + 1], o[t4 * 4 + 2], o[t4 * 4 + 3]);
                u32 h0, l0, h1, l1;
                split2(o[t4 * 4], o[t4 * 4 + 1], h0, l0);
                split2(o[t4 * 4 + 2], o[t4 * 4 + 3], h1, l1);
                *(u32*)&g_hh[nn * HID + c0 + t4 * 4]     = h0;
                *(u32*)&g_hh[nn * HID + c0 + t4 * 4 + 2] = h1;
                *(u32*)&g_hl[nn * HID + c0 + t4 * 4]     = l0;
                *(u32*)&g_hl[nn * HID + c0 + t4 * 4 + 2] = l1;
            }
        }
        if (do_pre) {
#pragma unroll
            for (int t = 0; t < 16; t++) {
                u32 h, l;
                split2(o[2 * t], o[2 * t + 1], h, l);
                *(u32*)&sAh[ln * UPP + c0 + 2 * t] = h;
                *(u32*)&sAl[ln * UPP + c0 + 2 * t] = l;
            }
        }
    }

    // ---- fused next-layer node_pre: g_pre(layer+1) = h_new @ NPW(layer+1)^T ----
    if (do_pre) {
        __syncthreads();
        int npl = layer + 1;
        for (int half = 0; half < 2; half++) {
            const u16* wh = g_NPh + npl * 256 * 128 + half * 128 * 128;
            const u16* wl = g_NPl + npl * 256 * 128 + half * 128 * 128;
            for (int idx = tid; idx < 128 * 16; idx += 256) {
                int r = idx >> 4, c = (idx & 15) * 8;
                *(uint4*)&sWh[r * UPP + c] = *(const uint4*)&wh[r * 128 + c];
                *(uint4*)&sWl[r * UPP + c] = *(const uint4*)&wl[r * 128 + c];
            }
            __syncthreads();
            float accp[2][4][4];
#pragma unroll
            for (int i = 0; i < 2; i++)
#pragma unroll
                for (int j = 0; j < 4; j++)
#pragma unroll
                    for (int k = 0; k < 4; k++) accp[i][j][k] = 0.f;
            for (int ks = 0; ks < 8; ks++) {
                int kb = ks * 16;
                u32 ah[2][4], al[2][4];
#pragma unroll
                for (int mt = 0; mt < 2; mt++) {
                    int r = m0 + mt * 16 + (lane & 15);
                    int c = kb + ((lane >> 4) << 3);
                    u32 off = (u32)(r * UPP + c) * 2;
                    ldsm4(ah[mt], sb + U_AH + off);
                    ldsm4(al[mt], sb + U_AL + off);
                }
#pragma unroll
                for (int nt = 0; nt < 4; nt++) {
                    int rn = nw0 + nt * 8 + (lane & 7);
                    int cn = kb + (((lane >> 3) & 1) << 3);
                    u32 offb = (u32)(rn * UPP + cn) * 2;
                    u32 bh[2], bl[2];
                    ldsm2(bh, sb + U_WH + offb);
                    ldsm2(bl, sb + U_WL + offb);
#pragma unroll
                    for (int mt = 0; mt < 2; mt++) {
                        mma16816(accp[mt][nt], ah[mt], bh);
                        mma16816(accp[mt][nt], ah[mt], bl);
                        mma16816(accp[mt][nt], al[mt], bh);
                    }
                }
            }
#pragma unroll
            for (int mt = 0; mt < 2; mt++)
#pragma unroll
                for (int nt = 0; nt < 4; nt++) {
                    int rA = m0 + mt * 16 + (lane >> 2);
                    int rB = rA + 8;
                    int c = half * 128 + nw0 + nt * 8 + 2 * (lane & 3);
                    int nA = n0 + rA, nB = n0 + rB;
                    if (nA < NN) {
                        g_pre[(u64)nA * 256 + c]     = accp[mt][nt][0];
                        g_pre[(u64)nA * 256 + c + 1] = accp[mt][nt][1];
                    }
                    if (nB < NN) {
                        g_pre[(u64)nB * 256 + c]     = accp[mt][nt][2];
                        g_pre[(u64)nB * 256 + c + 1] = accp[mt][nt][3];
                    }
                }
            __syncthreads();
        }
    }
}

// ---------------- final readout ----------------
__global__ void k_final(const float* __restrict__ gc,
                        const float* __restrict__ qw1,
                        const float* __restrict__ qb1,
                        const float* __restrict__ qw2,
                        const float* __restrict__ qb2p,
                        float* __restrict__ out) {
    __shared__ float sA[32 * 33];
    __shared__ float sW[128 * 33];
    __shared__ float sctx[64];
    __shared__ float sout[32];
    int tid = threadIdx.x;
    int n0 = blockIdx.x * 32;
    if (tid < 64) sctx[tid] = gc[tid];
    if (tid < 32) sout[tid] = qb2p[0];
    __syncthreads();
    int tc = tid & 31, trg = tid >> 5;
    float acc[4][4] = {};
    for (int kb = 0; kb < 192; kb += 32) {
        for (int idx = tid; idx < 32 * 32; idx += NT) {
            int r = idx >> 5, kk = idx & 31;
            int n = n0 + r;
            int kg = kb + kk;
            float v = 0.f;
            if (n < NN) v = (kg < 128) ? g_h[n * HID + kg] : sctx[kg - 128];
            sA[r * 33 + kk] = v;
        }
        for (int idx = tid; idx < 128 * 32; idx += NT) {
            int o = idx >> 5, kk = idx & 31;
            sW[o * 33 + kk] = qw1[o * 192 + kb + kk];
        }
        __syncthreads();
#pragma unroll 8
        for (int k = 0; k < 32; k++) {
            float a[4], w[4];
#pragma unroll
            for (int i = 0; i < 4; i++) a[i] = sA[(trg * 4 + i) * 33 + k];
#pragma unroll
            for (int j = 0; j < 4; j++) w[j] = sW[(tc + 32 * j) * 33 + k];
#pragma unroll
            for (int i = 0; i < 4; i++)
#pragma unroll
                for (int j = 0; j < 4; j++) acc[i][j] += a[i] * w[j];
        }
        __syncthreads();
    }
    float p[4] = {0.f, 0.f, 0.f, 0.f};
#pragma unroll
    for (int j = 0; j < 4; j++) {
        int c = tc + 32 * j;
        float b = qb1[c], w2 = qw2[c];
#pragma unroll
        for (int i = 0; i < 4; i++) {
            float v = fmaxf(acc[i][j] + b, 0.f);
            p[i] += v * w2;
        }
    }
#pragma unroll
    for (int i = 0; i < 4; i++) atomicAdd(&sout[trg * 4 + i], p[i]);
    __syncthreads();
    if (tid < 32) {
        int n = n0 + tid;
        if (n < NN) out[n] = sout[tid];
    }
}

// ---------------- launch ----------------
extern "C" void kernel_launch(void* const* d_in, const int* in_sizes, int n_in,
                              void* d_out, int out_size) {
    const float* x    = (const float*)d_in[0];
    const void*  eidx = d_in[1];
    const float* ea   = (const float*)d_in[2];
    const float* gc   = (const float*)d_in[3];
    const float* npw  = (const float*)d_in[4];
    const float* npb  = (const float*)d_in[5];
    const float* mw1  = (const float*)d_in[6];
    const float* mb1  = (const float*)d_in[7];
    const float* mw2  = (const float*)d_in[8];
    const float* mb2  = (const float*)d_in[9];
    const float* aw1  = (const float*)d_in[10];
    const float* ab1  = (const float*)d_in[11];
    const float* aw2  = (const float*)d_in[12];
    const float* ab2  = (const float*)d_in[13];
    const float* uw1  = (const float*)d_in[14];
    const float* ub1  = (const float*)d_in[15];
    const float* uw2  = (const float*)d_in[16];
    const float* ub2  = (const float*)d_in[17];
    const float* lng  = (const float*)d_in[18];
    const float* lnb  = (const float*)d_in[19];
    const float* qw1  = (const float*)d_in[20];
    const float* qb1  = (const float*)d_in[21];
    const float* qw2  = (const float*)d_in[22];
    const float* qb2  = (const float*)d_in[23];
    float* out = (float*)d_out;

    cudaFuncSetAttribute(k_msg, cudaFuncAttributeMaxDynamicSharedMemorySize, SMEM_MSG2);
    cudaFuncSetAttribute(k_node_pre, cudaFuncAttributeMaxDynamicSharedMemorySize, SMEM_NP);
    cudaFuncSetAttribute(k_update, cudaFuncAttributeMaxDynamicSharedMemorySize, SMEM_UPD);

    int prep_tot = 3 * (256 * 128 + 192 * 16 + 128 * 128 + 256 * 128 + 128 * 128);
    k_prep<<<(prep_tot + 255) / 256, 256>>>(mw1, mw2, aw1, uw1, uw2);
    k_detect<<<1, NT>>>((const unsigned*)eidx);
    k_convert<<<(NE + NT - 1) / NT, NT>>>(eidx, ea);
    k_hist<<<(NE + 255) / 256, 256>>>();
    k_scan<<<1, 1024>>>();
    k_scatter<<<(NE + 255) / 256, 256>>>();
    k_nodeproj<<<(NN + 31) / 32, NT>>>(x, npw, npb);

    int ngrid = (NN + 63) / 64;
    k_node_pre<<<ngrid, 256, SMEM_NP>>>(0);
    for (int l = 0; l < 3; l++) {
        k_attn_lite<<<(NE + 63) / 64, 256>>>(ea, aw1 + l * 64 * 272, ab1 + l * 64,
                                             aw2 + l * 64, ab2 + l, l);
        k_exp<<<(NE + NT - 1) / NT, NT>>>(l);
        k_msg<<<296, 256, SMEM_MSG2>>>(mb1 + l * 128, mb2 + l * 128, l);
        k_update<<<ngrid, 256, SMEM_UPD>>>(ub1 + l * 128, ub2 + l * 128,
                                           lng + l * 128, lnb + l * 128, l,
                                           (l < 2) ? 1 : 0);
    }
    k_final<<<(NN + 31) / 32, NT>>>(gc, qw1, qb1, qw2, qb2, out);
}